// round 4
// baseline (speedup 1.0000x reference)
#include <cuda_runtime.h>
#include <cuda_bf16.h>
#include <math.h>
#include <stdint.h>

// Problem constants  (L, D, H, FF, I, MAXREL = 6, 512, 8, 2048, 50, 128)
#define BATCH 16
#define SEQ   512
#define DM    512
#define NH    8
#define HD    64
#define FFD   2048
#define NLAYER 6
#define MAXREL 128
#define NREL  257          // 2*MAXREL+1
#define MROWS (BATCH*SEQ)  // 8192

// Scratch (no allocation allowed)
__device__ float g_h[MROWS*DM];
__device__ float g_q[MROWS*DM];
__device__ float g_k[MROWS*DM];
__device__ float g_v[MROWS*DM];
__device__ float g_ctx[MROWS*DM];
__device__ float g_tmp[MROWS*FFD];

// ---------------------------------------------------------------------------
// Embedding: h = x @ in_w + in_b + sinusoidal_pe
// ---------------------------------------------------------------------------
__global__ void embed_kernel(const float* __restrict__ x,
                             const float* __restrict__ in_w,
                             const float* __restrict__ in_b,
                             float* __restrict__ h)
{
    int idx = blockIdx.x * 256 + threadIdx.x;
    if (idx >= MROWS * DM) return;
    int r = idx >> 9;
    int c = idx & 511;
    const float* xr = x + (size_t)r * 50;
    float acc = in_b[c];
    #pragma unroll 10
    for (int i = 0; i < 50; i++)
        acc = fmaf(xr[i], in_w[i * DM + c], acc);
    int s = r & (SEQ - 1);
    int two_i = c & ~1;
    float earg = (float)two_i * (-9.210340371976184f / 512.0f);
    float div32 = expf(earg);
    float argf = (float)s * div32;
    double pe = (c & 1) ? cos((double)argf) : sin((double)argf);
    h[idx] = acc + (float)pe;
}

// ---------------------------------------------------------------------------
// Tiled SGEMM: C[M,N] = A[M,K] @ B[K,N] (+bias)(+relu)
// BM=BN=64, BK=16, 256 threads, 4x4 microtile.
// ---------------------------------------------------------------------------
template <bool BIAS, bool RELU>
__global__ __launch_bounds__(256)
void sgemm_kernel(const float* __restrict__ A, const float* __restrict__ Bm,
                  const float* __restrict__ bias, float* __restrict__ C,
                  int Md, int Nd, int Kd)
{
    __shared__ float As[16][64];
    __shared__ float Bs[16][64];

    int tid = threadIdx.x;
    int tx = tid & 15;
    int ty = tid >> 4;
    int row0 = blockIdx.y * 64;
    int col0 = blockIdx.x * 64;

    int arow = tid >> 2;
    int acol = (tid & 3) << 2;
    int brow = tid >> 4;
    int bcol = (tid & 15) << 2;

    float acc[4][4] = {};

    for (int k0 = 0; k0 < Kd; k0 += 16) {
        float4 av = *(const float4*)(A + (size_t)(row0 + arow) * Kd + k0 + acol);
        As[acol + 0][arow] = av.x;
        As[acol + 1][arow] = av.y;
        As[acol + 2][arow] = av.z;
        As[acol + 3][arow] = av.w;
        float4 bv = *(const float4*)(Bm + (size_t)(k0 + brow) * Nd + col0 + bcol);
        *(float4*)&Bs[brow][bcol] = bv;
        __syncthreads();

        #pragma unroll
        for (int kk = 0; kk < 16; kk++) {
            float4 a = *(const float4*)&As[kk][ty * 4];
            float4 b = *(const float4*)&Bs[kk][tx * 4];
            acc[0][0] = fmaf(a.x, b.x, acc[0][0]);
            acc[0][1] = fmaf(a.x, b.y, acc[0][1]);
            acc[0][2] = fmaf(a.x, b.z, acc[0][2]);
            acc[0][3] = fmaf(a.x, b.w, acc[0][3]);
            acc[1][0] = fmaf(a.y, b.x, acc[1][0]);
            acc[1][1] = fmaf(a.y, b.y, acc[1][1]);
            acc[1][2] = fmaf(a.y, b.z, acc[1][2]);
            acc[1][3] = fmaf(a.y, b.w, acc[1][3]);
            acc[2][0] = fmaf(a.z, b.x, acc[2][0]);
            acc[2][1] = fmaf(a.z, b.y, acc[2][1]);
            acc[2][2] = fmaf(a.z, b.z, acc[2][2]);
            acc[2][3] = fmaf(a.z, b.w, acc[2][3]);
            acc[3][0] = fmaf(a.w, b.x, acc[3][0]);
            acc[3][1] = fmaf(a.w, b.y, acc[3][1]);
            acc[3][2] = fmaf(a.w, b.z, acc[3][2]);
            acc[3][3] = fmaf(a.w, b.w, acc[3][3]);
        }
        __syncthreads();
    }

    float4 bv = make_float4(0.f, 0.f, 0.f, 0.f);
    if (BIAS) bv = *(const float4*)(bias + col0 + tx * 4);
    #pragma unroll
    for (int i = 0; i < 4; i++) {
        int row = row0 + ty * 4 + i;
        float4 o;
        o.x = acc[i][0]; o.y = acc[i][1]; o.z = acc[i][2]; o.w = acc[i][3];
        if (BIAS) { o.x += bv.x; o.y += bv.y; o.z += bv.z; o.w += bv.w; }
        if (RELU) {
            o.x = fmaxf(o.x, 0.f); o.y = fmaxf(o.y, 0.f);
            o.z = fmaxf(o.z, 0.f); o.w = fmaxf(o.w, 0.f);
        }
        *(float4*)(C + (size_t)row * Nd + col0 + tx * 4) = o;
    }
}

// ---------------------------------------------------------------------------
// Fused attention per (b,h,q): scores = q.k/8 + q.rel[clip(k-q,±128)+128]
// ---------------------------------------------------------------------------
__global__ __launch_bounds__(256)
void attn_kernel(const float* __restrict__ q, const float* __restrict__ k,
                 const float* __restrict__ v, const float* __restrict__ rel,
                 float* __restrict__ ctx)
{
    __shared__ __align__(16) float q_s[HD];
    __shared__ float qrel_s[NREL];
    __shared__ float sc[SEQ];
    __shared__ float red[256];
    __shared__ float cpart[4 * HD];

    int tid = threadIdx.x;
    int qi = blockIdx.x;
    int h  = blockIdx.y;
    int b  = blockIdx.z;
    int bs = b * SEQ;

    const float* qrow = q + ((size_t)(bs + qi) * DM + h * HD);
    if (tid < HD) q_s[tid] = qrow[tid];
    __syncthreads();

    // q . rel_emb[j], j in [0,257)
    for (int j = tid; j < NREL; j += 256) {
        const float4* rr = (const float4*)(rel + (size_t)j * HD);
        float a = 0.f;
        #pragma unroll
        for (int d4 = 0; d4 < HD / 4; d4++) {
            float4 rv = rr[d4];
            a = fmaf(q_s[d4*4+0], rv.x, a);
            a = fmaf(q_s[d4*4+1], rv.y, a);
            a = fmaf(q_s[d4*4+2], rv.z, a);
            a = fmaf(q_s[d4*4+3], rv.w, a);
        }
        qrel_s[j] = a;
    }
    __syncthreads();

    // scores
    for (int key = tid; key < SEQ; key += 256) {
        const float4* kp = (const float4*)(k + ((size_t)(bs + key) * DM + h * HD));
        float acc = 0.f;
        #pragma unroll
        for (int d4 = 0; d4 < HD / 4; d4++) {
            float4 kk = kp[d4];
            acc = fmaf(q_s[d4*4+0], kk.x, acc);
            acc = fmaf(q_s[d4*4+1], kk.y, acc);
            acc = fmaf(q_s[d4*4+2], kk.z, acc);
            acc = fmaf(q_s[d4*4+3], kk.w, acc);
        }
        int di = key - qi;
        di = min(max(di, -MAXREL), MAXREL) + MAXREL;
        sc[key] = acc * 0.125f + qrel_s[di];
    }
    __syncthreads();

    // max reduce
    red[tid] = fmaxf(sc[tid], sc[tid + 256]);
    __syncthreads();
    for (int s = 128; s > 0; s >>= 1) {
        if (tid < s) red[tid] = fmaxf(red[tid], red[tid + s]);
        __syncthreads();
    }
    float mx = red[0];
    __syncthreads();

    float e0 = __expf(sc[tid] - mx);
    float e1 = __expf(sc[tid + 256] - mx);
    sc[tid] = e0;
    sc[tid + 256] = e1;
    red[tid] = e0 + e1;
    __syncthreads();
    for (int s = 128; s > 0; s >>= 1) {
        if (tid < s) red[tid] += red[tid + s];
        __syncthreads();
    }
    float inv = 1.0f / red[0];
    __syncthreads();

    // ctx: 4 partitions of 128 keys x 64 dims
    int d = tid & 63;
    int part = tid >> 6;
    const float* vb = v + (size_t)(bs + part * 128) * DM + h * HD + d;
    float acc = 0.f;
    #pragma unroll 8
    for (int kk = 0; kk < 128; kk++)
        acc = fmaf(sc[part * 128 + kk], vb[(size_t)kk * DM], acc);
    cpart[part * HD + d] = acc;
    __syncthreads();
    if (part == 0) {
        float tot = cpart[d] + cpart[HD + d] + cpart[2*HD + d] + cpart[3*HD + d];
        ctx[(size_t)(bs + qi) * DM + h * HD + d] = tot * inv;
    }
}

// ---------------------------------------------------------------------------
// Fused residual add + LayerNorm
// ---------------------------------------------------------------------------
__device__ __forceinline__ float block_sum128(float v, float* ws)
{
    #pragma unroll
    for (int o = 16; o > 0; o >>= 1) v += __shfl_xor_sync(0xffffffffu, v, o);
    int lane = threadIdx.x & 31, w = threadIdx.x >> 5;
    if (lane == 0) ws[w] = v;
    __syncthreads();
    v = ws[0] + ws[1] + ws[2] + ws[3];
    __syncthreads();
    return v;
}

__global__ __launch_bounds__(128)
void add_ln_kernel(const float* __restrict__ x, const float* __restrict__ add,
                   const float* __restrict__ g, const float* __restrict__ bta,
                   float* __restrict__ out)
{
    __shared__ float ws[4];
    int row = blockIdx.x;
    int tid = threadIdx.x;
    float4 v = ((const float4*)(x + (size_t)row * DM))[tid];
    if (add != nullptr) {
        float4 a = ((const float4*)(add + (size_t)row * DM))[tid];
        v.x += a.x; v.y += a.y; v.z += a.z; v.w += a.w;
    }
    float s = block_sum128(v.x + v.y + v.z + v.w, ws);
    float mean = s * (1.0f / DM);
    float dx = v.x - mean, dy = v.y - mean, dz = v.z - mean, dw = v.w - mean;
    float sq = block_sum128(dx*dx + dy*dy + dz*dz + dw*dw, ws);
    float rstd = rsqrtf(sq * (1.0f / DM) + 1e-5f);
    float4 gg = ((const float4*)g)[tid];
    float4 bb = ((const float4*)bta)[tid];
    float4 o;
    o.x = dx * rstd * gg.x + bb.x;
    o.y = dy * rstd * gg.y + bb.y;
    o.z = dz * rstd * gg.z + bb.z;
    o.w = dw * rstd * gg.w + bb.w;
    ((float4*)(out + (size_t)row * DM))[tid] = o;
}

// ---------------------------------------------------------------------------
// Head stage 2: out[r] = dot(tmp[r,0:256], p2_w) + p2_b (one warp per row)
// ---------------------------------------------------------------------------
__global__ __launch_bounds__(256)
void head2_kernel(const float* __restrict__ tmp, const float* __restrict__ p2_w,
                  const float* __restrict__ p2_b, float* __restrict__ out)
{
    int wid = threadIdx.x >> 5;
    int lane = threadIdx.x & 31;
    int row = blockIdx.x * 8 + wid;
    const float* tr = tmp + (size_t)row * 256;
    float acc = 0.f;
    #pragma unroll
    for (int j = lane; j < 256; j += 32) acc = fmaf(tr[j], p2_w[j], acc);
    #pragma unroll
    for (int o = 16; o > 0; o >>= 1) acc += __shfl_xor_sync(0xffffffffu, acc, o);
    if (lane == 0) out[row] = acc + p2_b[0];
}

// ---------------------------------------------------------------------------
// Launcher
// ---------------------------------------------------------------------------
extern "C" void kernel_launch(void* const* d_in, const int* in_sizes, int n_in,
                              void* d_out, int out_size)
{
    const float* x     = (const float*)d_in[0];
    const float* in_w  = (const float*)d_in[1];
    const float* in_b  = (const float*)d_in[2];
    const float* Wq    = (const float*)d_in[3];
    const float* Wk    = (const float*)d_in[4];
    const float* Wv    = (const float*)d_in[5];
    const float* Wo    = (const float*)d_in[6];
    const float* bo    = (const float*)d_in[7];
    const float* relE  = (const float*)d_in[8];
    const float* w1    = (const float*)d_in[9];
    const float* b1    = (const float*)d_in[10];
    const float* w2    = (const float*)d_in[11];
    const float* b2    = (const float*)d_in[12];
    const float* ln1_g = (const float*)d_in[13];
    const float* ln1_b = (const float*)d_in[14];
    const float* ln2_g = (const float*)d_in[15];
    const float* ln2_b = (const float*)d_in[16];
    const float* on_g  = (const float*)d_in[17];
    const float* on_b  = (const float*)d_in[18];
    const float* p1_w  = (const float*)d_in[19];
    const float* p1_b  = (const float*)d_in[20];
    const float* p2_w  = (const float*)d_in[21];
    const float* p2_b  = (const float*)d_in[22];
    float* out = (float*)d_out;

    float *h, *q, *k, *v, *ctx, *tmp;
    cudaGetSymbolAddress((void**)&h,   g_h);
    cudaGetSymbolAddress((void**)&q,   g_q);
    cudaGetSymbolAddress((void**)&k,   g_k);
    cudaGetSymbolAddress((void**)&v,   g_v);
    cudaGetSymbolAddress((void**)&ctx, g_ctx);
    cudaGetSymbolAddress((void**)&tmp, g_tmp);

    embed_kernel<<<(MROWS * DM) / 256, 256>>>(x, in_w, in_b, h);

    dim3 gD(DM / 64, MROWS / 64);
    dim3 gF(FFD / 64, MROWS / 64);
    dim3 gP(256 / 64, MROWS / 64);
    dim3 gA(SEQ, NH, BATCH);

    for (int l = 0; l < NLAYER; l++) {
        const float* wq  = Wq + (size_t)l * DM * DM;
        const float* wk  = Wk + (size_t)l * DM * DM;
        const float* wv  = Wv + (size_t)l * DM * DM;
        const float* wo  = Wo + (size_t)l * DM * DM;
        const float* bol = bo + (size_t)l * DM;
        const float* rl  = relE + (size_t)l * NREL * HD;   // 257*64 stride
        const float* w1l = w1 + (size_t)l * DM * FFD;
        const float* b1l = b1 + (size_t)l * FFD;
        const float* w2l = w2 + (size_t)l * FFD * DM;
        const float* b2l = b2 + (size_t)l * DM;

        sgemm_kernel<false, false><<<gD, 256>>>(h, wq, nullptr, q, MROWS, DM, DM);
        sgemm_kernel<false, false><<<gD, 256>>>(h, wk, nullptr, k, MROWS, DM, DM);
        sgemm_kernel<false, false><<<gD, 256>>>(h, wv, nullptr, v, MROWS, DM, DM);

        attn_kernel<<<gA, 256>>>(q, k, v, rl, ctx);

        sgemm_kernel<true, false><<<gD, 256>>>(ctx, wo, bol, q, MROWS, DM, DM);
        add_ln_kernel<<<MROWS, 128>>>(h, q, ln1_g + (size_t)l * DM, ln1_b + (size_t)l * DM, h);

        sgemm_kernel<true, true><<<gF, 256>>>(h, w1l, b1l, tmp, MROWS, FFD, DM);
        sgemm_kernel<true, false><<<gD, 256>>>(tmp, w2l, b2l, q, MROWS, DM, FFD);
        add_ln_kernel<<<MROWS, 128>>>(h, q, ln2_g + (size_t)l * DM, ln2_b + (size_t)l * DM, h);
    }

    add_ln_kernel<<<MROWS, 128>>>(h, nullptr, on_g, on_b, q);
    sgemm_kernel<true, true><<<gP, 256>>>(q, p1_w, p1_b, tmp, MROWS, 256, DM);
    head2_kernel<<<MROWS / 8, 256>>>(tmp, p2_w, p2_b, out);
}

// round 5
// speedup vs baseline: 1.1321x; 1.1321x over previous
#include <cuda_runtime.h>
#include <cuda_bf16.h>
#include <math.h>
#include <stdint.h>

// Problem constants  (L, D, H, FF, I, MAXREL = 6, 512, 8, 2048, 50, 128)
#define BATCH 16
#define SEQ   512
#define DM    512
#define NH    8
#define HD    64
#define FFD   2048
#define NLAYER 6
#define MAXREL 128
#define NREL  257
#define MROWS (BATCH*SEQ)  // 8192
#define QT    32           // query tile for attention

// Scratch (no allocation allowed)
__device__ float g_h[MROWS*DM];
__device__ float g_q[MROWS*DM];
__device__ float g_k[MROWS*DM];
__device__ float g_v[MROWS*DM];
__device__ float g_ctx[MROWS*DM];
__device__ float g_tmp[MROWS*FFD];

// ---------------------------------------------------------------------------
// Embedding: h = x @ in_w + in_b + sinusoidal_pe
// ---------------------------------------------------------------------------
__global__ void embed_kernel(const float* __restrict__ x,
                             const float* __restrict__ in_w,
                             const float* __restrict__ in_b,
                             float* __restrict__ h)
{
    int idx = blockIdx.x * 256 + threadIdx.x;
    if (idx >= MROWS * DM) return;
    int r = idx >> 9;
    int c = idx & 511;
    const float* xr = x + (size_t)r * 50;
    float acc = in_b[c];
    #pragma unroll 10
    for (int i = 0; i < 50; i++)
        acc = fmaf(xr[i], in_w[i * DM + c], acc);
    int s = r & (SEQ - 1);
    int two_i = c & ~1;
    float earg = (float)two_i * (-9.210340371976184f / 512.0f);
    float div32 = expf(earg);
    float argf = (float)s * div32;
    double pe = (c & 1) ? cos((double)argf) : sin((double)argf);
    h[idx] = acc + (float)pe;
}

// ---------------------------------------------------------------------------
// SGEMM 128x128 tile, BK=16, 256 threads, 8x8 microtile.
// C[M,N] = A[M,K] @ B[K,N] (+bias)(+relu).  M%128==0, N%128==0, K%16==0.
// ---------------------------------------------------------------------------
template <bool BIAS, bool RELU>
__global__ __launch_bounds__(256)
void sgemm128(const float* __restrict__ A, const float* __restrict__ Bm,
              const float* __restrict__ bias, float* __restrict__ C,
              int M, int N, int K)
{
    __shared__ float As[16][128];   // transposed: As[k][m]
    __shared__ float Bs[16][128];   // Bs[k][n]

    int tid = threadIdx.x;
    int row0 = blockIdx.y * 128;
    int col0 = blockIdx.x * 128;
    int tx = tid & 15;              // -> col group (8 cols)
    int ty = tid >> 4;              // -> row group (8 rows)

    float acc[8][8] = {};

    for (int k0 = 0; k0 < K; k0 += 16) {
        // load A tile: 128 rows x 16 cols (2 float4 / thread)
        #pragma unroll
        for (int i = 0; i < 2; i++) {
            int f = tid + i * 256;
            int ar = f >> 2;
            int ac = (f & 3) << 2;
            float4 av = *(const float4*)(A + (size_t)(row0 + ar) * K + k0 + ac);
            As[ac + 0][ar] = av.x;
            As[ac + 1][ar] = av.y;
            As[ac + 2][ar] = av.z;
            As[ac + 3][ar] = av.w;
        }
        // load B tile: 16 rows x 128 cols (2 float4 / thread)
        #pragma unroll
        for (int i = 0; i < 2; i++) {
            int f = tid + i * 256;
            int br = f >> 5;
            int bc = (f & 31) << 2;
            *(float4*)&Bs[br][bc] = *(const float4*)(Bm + (size_t)(k0 + br) * N + col0 + bc);
        }
        __syncthreads();

        #pragma unroll
        for (int kk = 0; kk < 16; kk++) {
            float4 a0 = *(const float4*)&As[kk][ty * 8];
            float4 a1 = *(const float4*)&As[kk][ty * 8 + 4];
            float4 b0 = *(const float4*)&Bs[kk][tx * 8];
            float4 b1 = *(const float4*)&Bs[kk][tx * 8 + 4];
            float av[8] = {a0.x, a0.y, a0.z, a0.w, a1.x, a1.y, a1.z, a1.w};
            float bv[8] = {b0.x, b0.y, b0.z, b0.w, b1.x, b1.y, b1.z, b1.w};
            #pragma unroll
            for (int i = 0; i < 8; i++)
                #pragma unroll
                for (int j = 0; j < 8; j++)
                    acc[i][j] = fmaf(av[i], bv[j], acc[i][j]);
        }
        __syncthreads();
    }

    float bvv[8] = {};
    if (BIAS) {
        float4 c0 = *(const float4*)(bias + col0 + tx * 8);
        float4 c1 = *(const float4*)(bias + col0 + tx * 8 + 4);
        bvv[0]=c0.x; bvv[1]=c0.y; bvv[2]=c0.z; bvv[3]=c0.w;
        bvv[4]=c1.x; bvv[5]=c1.y; bvv[6]=c1.z; bvv[7]=c1.w;
    }
    #pragma unroll
    for (int i = 0; i < 8; i++) {
        int row = row0 + ty * 8 + i;
        float o[8];
        #pragma unroll
        for (int j = 0; j < 8; j++) {
            o[j] = acc[i][j];
            if (BIAS) o[j] += bvv[j];
            if (RELU) o[j] = fmaxf(o[j], 0.f);
        }
        *(float4*)(C + (size_t)row * N + col0 + tx * 8)     = make_float4(o[0],o[1],o[2],o[3]);
        *(float4*)(C + (size_t)row * N + col0 + tx * 8 + 4) = make_float4(o[4],o[5],o[6],o[7]);
    }
}

// ---------------------------------------------------------------------------
// Flash-style attention: block = (q-tile of 32, head, batch), 256 threads.
// smem (dynamic, ~120KB): Qs[32][64] | KV[64][64] | QR[32][257] | S[32][512]
// ---------------------------------------------------------------------------
__global__ __launch_bounds__(256)
void attn_flash(const float* __restrict__ qb, const float* __restrict__ kb,
                const float* __restrict__ vb, const float* __restrict__ rel,
                float* __restrict__ ctx)
{
    extern __shared__ float sm[];
    float* Qs = sm;                    // QT*HD    = 2048
    float* KV = Qs + QT * HD;          // 64*HD    = 4096
    float* QR = KV + 64 * HD;          // QT*NREL  = 8224
    float* Sm = QR + QT * NREL;        // QT*SEQ   = 16384

    int tid = threadIdx.x;
    int qt = blockIdx.x;
    int h  = blockIdx.y;
    int b  = blockIdx.z;
    int bs = b * SEQ;
    int q0 = qt * QT;

    // load Q tile (2 float4 / thread)
    #pragma unroll
    for (int i = 0; i < 2; i++) {
        int f = tid + i * 256;
        int qr = f >> 4;
        int qc = (f & 15) << 2;
        *(float4*)&Qs[qr * HD + qc] =
            *(const float4*)(qb + (size_t)(bs + q0 + qr) * DM + h * HD + qc);
    }
    __syncthreads();

    // QR[q][j] = Qs[q] . rel[j]
    for (int idx = tid; idx < QT * NREL; idx += 256) {
        int qq = idx / NREL;
        int j  = idx - qq * NREL;
        const float4* rr = (const float4*)(rel + (size_t)j * HD);
        const float4* qv = (const float4*)&Qs[qq * HD];
        float a = 0.f;
        #pragma unroll
        for (int d4 = 0; d4 < HD / 4; d4++) {
            float4 rv = rr[d4];
            float4 qf = qv[d4];
            a = fmaf(qf.x, rv.x, a);
            a = fmaf(qf.y, rv.y, a);
            a = fmaf(qf.z, rv.z, a);
            a = fmaf(qf.w, rv.w, a);
        }
        QR[qq * NREL + j] = a;
    }

    // scores: loop over 8 key-tiles of 64
    int q  = tid >> 3;      // 0..31
    int cg = tid & 7;       // col group of 8
    for (int kt = 0; kt < 8; kt++) {
        // load K tile (4 float4 / thread)
        #pragma unroll
        for (int i = 0; i < 4; i++) {
            int f = tid + i * 256;
            int kr = f >> 4;
            int kc = (f & 15) << 2;
            *(float4*)&KV[kr * HD + kc] =
                *(const float4*)(kb + (size_t)(bs + kt * 64 + kr) * DM + h * HD + kc);
        }
        __syncthreads();

        float a8[8] = {};
        const float4* qv = (const float4*)&Qs[q * HD];
        #pragma unroll
        for (int d4 = 0; d4 < HD / 4; d4++) {
            float4 qf = qv[d4];
            #pragma unroll
            for (int j = 0; j < 8; j++) {
                float4 kf = *(const float4*)&KV[(cg * 8 + j) * HD + d4 * 4];
                a8[j] = fmaf(qf.x, kf.x, a8[j]);
                a8[j] = fmaf(qf.y, kf.y, a8[j]);
                a8[j] = fmaf(qf.z, kf.z, a8[j]);
                a8[j] = fmaf(qf.w, kf.w, a8[j]);
            }
        }
        #pragma unroll
        for (int j = 0; j < 8; j++) {
            int key = kt * 64 + cg * 8 + j;
            int di = key - (q0 + q);
            di = min(max(di, -MAXREL), MAXREL) + MAXREL;
            Sm[q * SEQ + key] = a8[j] * 0.125f + QR[q * NREL + di];
        }
        __syncthreads();
    }

    // softmax per row: row = tid>>3 (same q), 8 lanes per row
    int sub = tid & 7;
    float mx = -1e30f;
    for (int c = sub; c < SEQ; c += 8) mx = fmaxf(mx, Sm[q * SEQ + c]);
    #pragma unroll
    for (int o = 1; o < 8; o <<= 1) mx = fmaxf(mx, __shfl_xor_sync(0xffffffffu, mx, o));
    float sum = 0.f;
    for (int c = sub; c < SEQ; c += 8) {
        float e = __expf(Sm[q * SEQ + c] - mx);
        Sm[q * SEQ + c] = e;
        sum += e;
    }
    #pragma unroll
    for (int o = 1; o < 8; o <<= 1) sum += __shfl_xor_sync(0xffffffffu, sum, o);
    float inv = 1.0f / sum;
    __syncthreads();

    // PV: thread (q, dg) -> dims dg*8..dg*8+7
    int dg = tid & 7;
    float c8[8] = {};
    for (int kt = 0; kt < 8; kt++) {
        // load V tile
        #pragma unroll
        for (int i = 0; i < 4; i++) {
            int f = tid + i * 256;
            int vr = f >> 4;
            int vc = (f & 15) << 2;
            *(float4*)&KV[vr * HD + vc] =
                *(const float4*)(vb + (size_t)(bs + kt * 64 + vr) * DM + h * HD + vc);
        }
        __syncthreads();
        #pragma unroll 4
        for (int c = 0; c < 64; c++) {
            float p = Sm[q * SEQ + kt * 64 + c];
            float4 v0 = *(const float4*)&KV[c * HD + dg * 8];
            float4 v1 = *(const float4*)&KV[c * HD + dg * 8 + 4];
            c8[0] = fmaf(p, v0.x, c8[0]);
            c8[1] = fmaf(p, v0.y, c8[1]);
            c8[2] = fmaf(p, v0.z, c8[2]);
            c8[3] = fmaf(p, v0.w, c8[3]);
            c8[4] = fmaf(p, v1.x, c8[4]);
            c8[5] = fmaf(p, v1.y, c8[5]);
            c8[6] = fmaf(p, v1.z, c8[6]);
            c8[7] = fmaf(p, v1.w, c8[7]);
        }
        __syncthreads();
    }
    float* cp = ctx + (size_t)(bs + q0 + q) * DM + h * HD + dg * 8;
    *(float4*)cp       = make_float4(c8[0]*inv, c8[1]*inv, c8[2]*inv, c8[3]*inv);
    *(float4*)(cp + 4) = make_float4(c8[4]*inv, c8[5]*inv, c8[6]*inv, c8[7]*inv);
}

#define ATTN_SMEM ((QT*HD + 64*HD + QT*NREL + QT*SEQ) * (int)sizeof(float))

// ---------------------------------------------------------------------------
// Fused residual add + LayerNorm
// ---------------------------------------------------------------------------
__device__ __forceinline__ float block_sum128(float v, float* ws)
{
    #pragma unroll
    for (int o = 16; o > 0; o >>= 1) v += __shfl_xor_sync(0xffffffffu, v, o);
    int lane = threadIdx.x & 31, w = threadIdx.x >> 5;
    if (lane == 0) ws[w] = v;
    __syncthreads();
    v = ws[0] + ws[1] + ws[2] + ws[3];
    __syncthreads();
    return v;
}

__global__ __launch_bounds__(128)
void add_ln_kernel(const float* __restrict__ x, const float* __restrict__ add,
                   const float* __restrict__ g, const float* __restrict__ bta,
                   float* __restrict__ out)
{
    __shared__ float ws[4];
    int row = blockIdx.x;
    int tid = threadIdx.x;
    float4 v = ((const float4*)(x + (size_t)row * DM))[tid];
    if (add != nullptr) {
        float4 a = ((const float4*)(add + (size_t)row * DM))[tid];
        v.x += a.x; v.y += a.y; v.z += a.z; v.w += a.w;
    }
    float s = block_sum128(v.x + v.y + v.z + v.w, ws);
    float mean = s * (1.0f / DM);
    float dx = v.x - mean, dy = v.y - mean, dz = v.z - mean, dw = v.w - mean;
    float sq = block_sum128(dx*dx + dy*dy + dz*dz + dw*dw, ws);
    float rstd = rsqrtf(sq * (1.0f / DM) + 1e-5f);
    float4 gg = ((const float4*)g)[tid];
    float4 bb = ((const float4*)bta)[tid];
    float4 o;
    o.x = dx * rstd * gg.x + bb.x;
    o.y = dy * rstd * gg.y + bb.y;
    o.z = dz * rstd * gg.z + bb.z;
    o.w = dw * rstd * gg.w + bb.w;
    ((float4*)(out + (size_t)row * DM))[tid] = o;
}

// ---------------------------------------------------------------------------
// Head stage 2
// ---------------------------------------------------------------------------
__global__ __launch_bounds__(256)
void head2_kernel(const float* __restrict__ tmp, const float* __restrict__ p2_w,
                  const float* __restrict__ p2_b, float* __restrict__ out)
{
    int wid = threadIdx.x >> 5;
    int lane = threadIdx.x & 31;
    int row = blockIdx.x * 8 + wid;
    const float* tr = tmp + (size_t)row * 256;
    float acc = 0.f;
    #pragma unroll
    for (int j = lane; j < 256; j += 32) acc = fmaf(tr[j], p2_w[j], acc);
    #pragma unroll
    for (int o = 16; o > 0; o >>= 1) acc += __shfl_xor_sync(0xffffffffu, acc, o);
    if (lane == 0) out[row] = acc + p2_b[0];
}

// ---------------------------------------------------------------------------
// Launcher
// ---------------------------------------------------------------------------
extern "C" void kernel_launch(void* const* d_in, const int* in_sizes, int n_in,
                              void* d_out, int out_size)
{
    const float* x     = (const float*)d_in[0];
    const float* in_w  = (const float*)d_in[1];
    const float* in_b  = (const float*)d_in[2];
    const float* Wq    = (const float*)d_in[3];
    const float* Wk    = (const float*)d_in[4];
    const float* Wv    = (const float*)d_in[5];
    const float* Wo    = (const float*)d_in[6];
    const float* bo    = (const float*)d_in[7];
    const float* relE  = (const float*)d_in[8];
    const float* w1    = (const float*)d_in[9];
    const float* b1    = (const float*)d_in[10];
    const float* w2    = (const float*)d_in[11];
    const float* b2    = (const float*)d_in[12];
    const float* ln1_g = (const float*)d_in[13];
    const float* ln1_b = (const float*)d_in[14];
    const float* ln2_g = (const float*)d_in[15];
    const float* ln2_b = (const float*)d_in[16];
    const float* on_g  = (const float*)d_in[17];
    const float* on_b  = (const float*)d_in[18];
    const float* p1_w  = (const float*)d_in[19];
    const float* p1_b  = (const float*)d_in[20];
    const float* p2_w  = (const float*)d_in[21];
    const float* p2_b  = (const float*)d_in[22];
    float* out = (float*)d_out;

    float *h, *q, *k, *v, *ctx, *tmp;
    cudaGetSymbolAddress((void**)&h,   g_h);
    cudaGetSymbolAddress((void**)&q,   g_q);
    cudaGetSymbolAddress((void**)&k,   g_k);
    cudaGetSymbolAddress((void**)&v,   g_v);
    cudaGetSymbolAddress((void**)&ctx, g_ctx);
    cudaGetSymbolAddress((void**)&tmp, g_tmp);

    static bool attr_set = false;
    if (!attr_set) {
        cudaFuncSetAttribute(attn_flash, cudaFuncAttributeMaxDynamicSharedMemorySize,
                             ATTN_SMEM);
        attr_set = true;
    }

    embed_kernel<<<(MROWS * DM) / 256, 256>>>(x, in_w, in_b, h);

    dim3 gD(DM / 128, MROWS / 128);     // 4 x 64
    dim3 gF(FFD / 128, MROWS / 128);    // 16 x 64
    dim3 gP(256 / 128, MROWS / 128);    // 2 x 64
    dim3 gA(SEQ / QT, NH, BATCH);       // 16 x 8 x 16

    for (int l = 0; l < NLAYER; l++) {
        const float* wq  = Wq + (size_t)l * DM * DM;
        const float* wk  = Wk + (size_t)l * DM * DM;
        const float* wv  = Wv + (size_t)l * DM * DM;
        const float* wo  = Wo + (size_t)l * DM * DM;
        const float* bol = bo + (size_t)l * DM;
        const float* rl  = relE + (size_t)l * NREL * HD;
        const float* w1l = w1 + (size_t)l * DM * FFD;
        const float* b1l = b1 + (size_t)l * FFD;
        const float* w2l = w2 + (size_t)l * FFD * DM;
        const float* b2l = b2 + (size_t)l * DM;

        sgemm128<false, false><<<gD, 256>>>(h, wq, nullptr, q, MROWS, DM, DM);
        sgemm128<false, false><<<gD, 256>>>(h, wk, nullptr, k, MROWS, DM, DM);
        sgemm128<false, false><<<gD, 256>>>(h, wv, nullptr, v, MROWS, DM, DM);

        attn_flash<<<gA, 256, ATTN_SMEM>>>(q, k, v, rl, ctx);

        sgemm128<true, false><<<gD, 256>>>(ctx, wo, bol, q, MROWS, DM, DM);
        add_ln_kernel<<<MROWS, 128>>>(h, q, ln1_g + (size_t)l * DM, ln1_b + (size_t)l * DM, h);

        sgemm128<true, true><<<gF, 256>>>(h, w1l, b1l, tmp, MROWS, FFD, DM);
        sgemm128<true, false><<<gD, 256>>>(tmp, w2l, b2l, q, MROWS, DM, FFD);
        add_ln_kernel<<<MROWS, 128>>>(h, q, ln2_g + (size_t)l * DM, ln2_b + (size_t)l * DM, h);
    }

    add_ln_kernel<<<MROWS, 128>>>(h, nullptr, on_g, on_b, q);
    sgemm128<true, true><<<gP, 256>>>(q, p1_w, p1_b, tmp, MROWS, 256, DM);
    head2_kernel<<<MROWS / 8, 256>>>(tmp, p2_w, p2_b, out);
}

// round 7
// speedup vs baseline: 1.9020x; 1.6800x over previous
#include <cuda_runtime.h>
#include <cuda_bf16.h>
#include <math.h>
#include <stdint.h>

// Problem constants  (L, D, H, FF, I, MAXREL = 6, 512, 8, 2048, 50, 128)
#define BATCH 16
#define SEQ   512
#define DM    512
#define NH    8
#define HD    64
#define FFD   2048
#define NLAYER 6
#define MAXREL 128
#define NREL  257
#define MROWS (BATCH*SEQ)  // 8192

// Scratch (no allocation allowed)
__device__ float g_h[MROWS*DM];
__device__ float g_q[MROWS*DM];
__device__ float g_k[MROWS*DM];
__device__ float g_v[MROWS*DM];
__device__ float g_ctx[MROWS*DM];
__device__ float g_tmp[MROWS*FFD];
__device__ float g_qr[(size_t)NH*MROWS*NREL];          // 67 MB
__device__ float g_sc[(size_t)BATCH*NH*SEQ*SEQ];       // 134 MB

// ---------------------------------------------------------------------------
// Embedding
// ---------------------------------------------------------------------------
__global__ void embed_kernel(const float* __restrict__ x,
                             const float* __restrict__ in_w,
                             const float* __restrict__ in_b,
                             float* __restrict__ h)
{
    int idx = blockIdx.x * 256 + threadIdx.x;
    if (idx >= MROWS * DM) return;
    int r = idx >> 9;
    int c = idx & 511;
    const float* xr = x + (size_t)r * 50;
    float acc = in_b[c];
    #pragma unroll 10
    for (int i = 0; i < 50; i++)
        acc = fmaf(xr[i], in_w[i * DM + c], acc);
    int s = r & (SEQ - 1);
    int two_i = c & ~1;
    float earg = (float)two_i * (-9.210340371976184f / 512.0f);
    float div32 = expf(earg);
    float argf = (float)s * div32;
    double pe = (c & 1) ? cos((double)argf) : sin((double)argf);
    h[idx] = acc + (float)pe;
}

// ---------------------------------------------------------------------------
// SGEMM 128x128 tile, BK=16, 256 threads, 8x8 microtile.
// ---------------------------------------------------------------------------
template <bool BIAS, bool RELU>
__global__ __launch_bounds__(256)
void sgemm128(const float* __restrict__ A, const float* __restrict__ Bm,
              const float* __restrict__ bias, float* __restrict__ C,
              int M, int N, int K)
{
    __shared__ float As[16][128];
    __shared__ float Bs[16][128];

    int tid = threadIdx.x;
    int row0 = blockIdx.y * 128;
    int col0 = blockIdx.x * 128;
    int tx = tid & 15;
    int ty = tid >> 4;

    float acc[8][8] = {};

    for (int k0 = 0; k0 < K; k0 += 16) {
        #pragma unroll
        for (int i = 0; i < 2; i++) {
            int f = tid + i * 256;
            int ar = f >> 2;
            int ac = (f & 3) << 2;
            float4 av = *(const float4*)(A + (size_t)(row0 + ar) * K + k0 + ac);
            As[ac + 0][ar] = av.x;
            As[ac + 1][ar] = av.y;
            As[ac + 2][ar] = av.z;
            As[ac + 3][ar] = av.w;
        }
        #pragma unroll
        for (int i = 0; i < 2; i++) {
            int f = tid + i * 256;
            int br = f >> 5;
            int bc = (f & 31) << 2;
            *(float4*)&Bs[br][bc] = *(const float4*)(Bm + (size_t)(k0 + br) * N + col0 + bc);
        }
        __syncthreads();

        #pragma unroll
        for (int kk = 0; kk < 16; kk++) {
            float4 a0 = *(const float4*)&As[kk][ty * 8];
            float4 a1 = *(const float4*)&As[kk][ty * 8 + 4];
            float4 b0 = *(const float4*)&Bs[kk][tx * 8];
            float4 b1 = *(const float4*)&Bs[kk][tx * 8 + 4];
            float av[8] = {a0.x, a0.y, a0.z, a0.w, a1.x, a1.y, a1.z, a1.w};
            float bv[8] = {b0.x, b0.y, b0.z, b0.w, b1.x, b1.y, b1.z, b1.w};
            #pragma unroll
            for (int i = 0; i < 8; i++)
                #pragma unroll
                for (int j = 0; j < 8; j++)
                    acc[i][j] = fmaf(av[i], bv[j], acc[i][j]);
        }
        __syncthreads();
    }

    float bvv[8] = {};
    if (BIAS) {
        float4 c0 = *(const float4*)(bias + col0 + tx * 8);
        float4 c1 = *(const float4*)(bias + col0 + tx * 8 + 4);
        bvv[0]=c0.x; bvv[1]=c0.y; bvv[2]=c0.z; bvv[3]=c0.w;
        bvv[4]=c1.x; bvv[5]=c1.y; bvv[6]=c1.z; bvv[7]=c1.w;
    }
    #pragma unroll
    for (int i = 0; i < 8; i++) {
        int row = row0 + ty * 8 + i;
        float o[8];
        #pragma unroll
        for (int j = 0; j < 8; j++) {
            o[j] = acc[i][j];
            if (BIAS) o[j] += bvv[j];
            if (RELU) o[j] = fmaxf(o[j], 0.f);
        }
        *(float4*)(C + (size_t)row * N + col0 + tx * 8)     = make_float4(o[0],o[1],o[2],o[3]);
        *(float4*)(C + (size_t)row * N + col0 + tx * 8 + 4) = make_float4(o[4],o[5],o[6],o[7]);
    }
}

// ---------------------------------------------------------------------------
// qrel: QR[h][row][j] = sum_d q[row, h*64+d] * rel[j*64+d]
// grid (MROWS/64, NH), 256 threads.
// smem layout: rel padded [257][65], then Q tile at a 16-float-aligned offset.
// ---------------------------------------------------------------------------
#define REL_FLOATS  ((NREL * 65 + 15) & ~15)   // 16-float aligned
#define QREL_SMEM   ((REL_FLOATS + 64 * 64) * (int)sizeof(float))
__global__ __launch_bounds__(256)
void qrel_kernel(const float* __restrict__ qb, const float* __restrict__ rel,
                 float* __restrict__ qr)
{
    extern __shared__ float sm[];
    float* rel_s = sm;                 // [257][65]
    float* Qs    = sm + REL_FLOATS;    // [64][64], 16B-aligned

    int tid = threadIdx.x;
    int row0 = blockIdx.x * 64;
    int h = blockIdx.y;

    for (int idx = tid; idx < NREL * 16; idx += 256) {
        int j = idx >> 4;
        int d0 = (idx & 15) << 2;
        float4 rv = *(const float4*)(rel + (size_t)j * HD + d0);
        rel_s[j * 65 + d0 + 0] = rv.x;
        rel_s[j * 65 + d0 + 1] = rv.y;
        rel_s[j * 65 + d0 + 2] = rv.z;
        rel_s[j * 65 + d0 + 3] = rv.w;
    }
    for (int idx = tid; idx < 64 * 16; idx += 256) {
        int r = idx >> 4;
        int d0 = (idx & 15) << 2;
        *(float4*)&Qs[r * HD + d0] =
            *(const float4*)(qb + (size_t)(row0 + r) * DM + h * HD + d0);
    }
    __syncthreads();

    for (int j = tid; j < NREL; j += 256) {
        for (int r0 = 0; r0 < 64; r0 += 8) {
            float acc8[8] = {};
            for (int d = 0; d < HD; d++) {
                float rv = rel_s[j * 65 + d];
                #pragma unroll
                for (int t = 0; t < 8; t++)
                    acc8[t] = fmaf(Qs[(r0 + t) * HD + d], rv, acc8[t]);
            }
            #pragma unroll
            for (int t = 0; t < 8; t++)
                qr[((size_t)h * MROWS + row0 + r0 + t) * NREL + j] = acc8[t];
        }
    }
}

// ---------------------------------------------------------------------------
// attn_score: S[bh][q][k] = (Q_h . K_h)/8 + QR[h][row][clip(k-q)+128]
// 128x128 tile, K=64 single pass. grid (4, 4, B*NH). dyn smem 64KB.
// ---------------------------------------------------------------------------
#define SCORE_SMEM (2 * 64 * 128 * (int)sizeof(float))
__global__ __launch_bounds__(256)
void attn_score(const float* __restrict__ qb, const float* __restrict__ kb,
                const float* __restrict__ qr, float* __restrict__ sc)
{
    extern __shared__ float sm[];
    float* As = sm;            // [64][128]  As[d][i]
    float* Bs = sm + 64*128;   // [64][128]  Bs[d][j]

    int tid = threadIdx.x;
    int k0 = blockIdx.x * 128;
    int q0 = blockIdx.y * 128;
    int bh = blockIdx.z;
    int b = bh >> 3;
    int h = bh & 7;
    int bs = b * SEQ;

    #pragma unroll
    for (int i = 0; i < 8; i++) {
        int idx = tid + i * 256;
        int r  = idx & 127;
        int d0 = (idx >> 7) << 2;
        float4 av = *(const float4*)(qb + (size_t)(bs + q0 + r) * DM + h * HD + d0);
        As[(d0 + 0) * 128 + r] = av.x;
        As[(d0 + 1) * 128 + r] = av.y;
        As[(d0 + 2) * 128 + r] = av.z;
        As[(d0 + 3) * 128 + r] = av.w;
        float4 bv = *(const float4*)(kb + (size_t)(bs + k0 + r) * DM + h * HD + d0);
        Bs[(d0 + 0) * 128 + r] = bv.x;
        Bs[(d0 + 1) * 128 + r] = bv.y;
        Bs[(d0 + 2) * 128 + r] = bv.z;
        Bs[(d0 + 3) * 128 + r] = bv.w;
    }
    __syncthreads();

    int tx = tid & 15;
    int ty = tid >> 4;
    float acc[8][8] = {};
    #pragma unroll 8
    for (int kk = 0; kk < 64; kk++) {
        float4 a0 = *(const float4*)&As[kk * 128 + ty * 8];
        float4 a1 = *(const float4*)&As[kk * 128 + ty * 8 + 4];
        float4 b0 = *(const float4*)&Bs[kk * 128 + tx * 8];
        float4 b1 = *(const float4*)&Bs[kk * 128 + tx * 8 + 4];
        float av[8] = {a0.x, a0.y, a0.z, a0.w, a1.x, a1.y, a1.z, a1.w};
        float bv[8] = {b0.x, b0.y, b0.z, b0.w, b1.x, b1.y, b1.z, b1.w};
        #pragma unroll
        for (int i = 0; i < 8; i++)
            #pragma unroll
            for (int j = 0; j < 8; j++)
                acc[i][j] = fmaf(av[i], bv[j], acc[i][j]);
    }

    #pragma unroll
    for (int i = 0; i < 8; i++) {
        int qg = q0 + ty * 8 + i;
        const float* qrow = qr + ((size_t)h * MROWS + bs + qg) * NREL;
        float o[8];
        #pragma unroll
        for (int j = 0; j < 8; j++) {
            int kg = k0 + tx * 8 + j;
            int di = kg - qg;
            di = min(max(di, -MAXREL), MAXREL) + MAXREL;
            o[j] = acc[i][j] * 0.125f + qrow[di];
        }
        float* op = sc + ((size_t)bh * SEQ + qg) * SEQ + k0 + tx * 8;
        *(float4*)op       = make_float4(o[0], o[1], o[2], o[3]);
        *(float4*)(op + 4) = make_float4(o[4], o[5], o[6], o[7]);
    }
}

// ---------------------------------------------------------------------------
// softmax over each row of 512, in place. grid = B*NH*SEQ blocks of 128.
// ---------------------------------------------------------------------------
__global__ __launch_bounds__(128)
void softmax_rows(float* __restrict__ sc)
{
    __shared__ float ws[4];
    int tid = threadIdx.x;
    int lane = tid & 31, w = tid >> 5;
    float* row = sc + (size_t)blockIdx.x * SEQ;
    float4 v = ((float4*)row)[tid];

    float m = fmaxf(fmaxf(v.x, v.y), fmaxf(v.z, v.w));
    #pragma unroll
    for (int o = 16; o > 0; o >>= 1) m = fmaxf(m, __shfl_xor_sync(0xffffffffu, m, o));
    if (lane == 0) ws[w] = m;
    __syncthreads();
    m = fmaxf(fmaxf(ws[0], ws[1]), fmaxf(ws[2], ws[3]));
    __syncthreads();

    v.x = __expf(v.x - m); v.y = __expf(v.y - m);
    v.z = __expf(v.z - m); v.w = __expf(v.w - m);
    float s = v.x + v.y + v.z + v.w;
    #pragma unroll
    for (int o = 16; o > 0; o >>= 1) s += __shfl_xor_sync(0xffffffffu, s, o);
    if (lane == 0) ws[w] = s;
    __syncthreads();
    s = ws[0] + ws[1] + ws[2] + ws[3];
    float inv = 1.0f / s;
    v.x *= inv; v.y *= inv; v.z *= inv; v.w *= inv;
    ((float4*)row)[tid] = v;
}

// ---------------------------------------------------------------------------
// attn_pv: ctx_h = P[512,512] @ V_h[512,64].
// block: 128 rows x 64 dims; K-chunks of 64. grid (4, B*NH). smem 48KB static.
// ---------------------------------------------------------------------------
__global__ __launch_bounds__(256)
void attn_pv(const float* __restrict__ p, const float* __restrict__ vb,
             float* __restrict__ ctx)
{
    __shared__ float Ps[64 * 128];   // Ps[kk][i]
    __shared__ float Vs[64 * 64];    // Vs[kk][d]

    int tid = threadIdx.x;
    int q0 = blockIdx.x * 128;
    int bh = blockIdx.y;
    int b = bh >> 3;
    int h = bh & 7;
    int bs = b * SEQ;

    int tx = tid & 15;
    int ty = tid >> 4;
    float acc[8][4] = {};

    for (int kc = 0; kc < SEQ; kc += 64) {
        #pragma unroll
        for (int i = 0; i < 8; i++) {
            int idx = tid + i * 256;
            int r  = idx & 127;
            int kk0 = (idx >> 7) << 2;
            float4 pv = *(const float4*)(p + ((size_t)bh * SEQ + q0 + r) * SEQ + kc + kk0);
            Ps[(kk0 + 0) * 128 + r] = pv.x;
            Ps[(kk0 + 1) * 128 + r] = pv.y;
            Ps[(kk0 + 2) * 128 + r] = pv.z;
            Ps[(kk0 + 3) * 128 + r] = pv.w;
        }
        #pragma unroll
        for (int i = 0; i < 4; i++) {
            int idx = tid + i * 256;
            int kk = idx >> 4;
            int d0 = (idx & 15) << 2;
            *(float4*)&Vs[kk * 64 + d0] =
                *(const float4*)(vb + (size_t)(bs + kc + kk) * DM + h * HD + d0);
        }
        __syncthreads();

        #pragma unroll 8
        for (int kk = 0; kk < 64; kk++) {
            float4 a0 = *(const float4*)&Ps[kk * 128 + ty * 8];
            float4 a1 = *(const float4*)&Ps[kk * 128 + ty * 8 + 4];
            float4 bv = *(const float4*)&Vs[kk * 64 + tx * 4];
            float av[8] = {a0.x, a0.y, a0.z, a0.w, a1.x, a1.y, a1.z, a1.w};
            #pragma unroll
            for (int i = 0; i < 8; i++) {
                acc[i][0] = fmaf(av[i], bv.x, acc[i][0]);
                acc[i][1] = fmaf(av[i], bv.y, acc[i][1]);
                acc[i][2] = fmaf(av[i], bv.z, acc[i][2]);
                acc[i][3] = fmaf(av[i], bv.w, acc[i][3]);
            }
        }
        __syncthreads();
    }

    #pragma unroll
    for (int i = 0; i < 8; i++) {
        *(float4*)(ctx + (size_t)(bs + q0 + ty * 8 + i) * DM + h * HD + tx * 4) =
            make_float4(acc[i][0], acc[i][1], acc[i][2], acc[i][3]);
    }
}

// ---------------------------------------------------------------------------
// Fused residual add + LayerNorm
// ---------------------------------------------------------------------------
__device__ __forceinline__ float block_sum128(float v, float* ws)
{
    #pragma unroll
    for (int o = 16; o > 0; o >>= 1) v += __shfl_xor_sync(0xffffffffu, v, o);
    int lane = threadIdx.x & 31, w = threadIdx.x >> 5;
    if (lane == 0) ws[w] = v;
    __syncthreads();
    v = ws[0] + ws[1] + ws[2] + ws[3];
    __syncthreads();
    return v;
}

__global__ __launch_bounds__(128)
void add_ln_kernel(const float* __restrict__ x, const float* __restrict__ add,
                   const float* __restrict__ g, const float* __restrict__ bta,
                   float* __restrict__ out)
{
    __shared__ float ws[4];
    int row = blockIdx.x;
    int tid = threadIdx.x;
    float4 v = ((const float4*)(x + (size_t)row * DM))[tid];
    if (add != nullptr) {
        float4 a = ((const float4*)(add + (size_t)row * DM))[tid];
        v.x += a.x; v.y += a.y; v.z += a.z; v.w += a.w;
    }
    float s = block_sum128(v.x + v.y + v.z + v.w, ws);
    float mean = s * (1.0f / DM);
    float dx = v.x - mean, dy = v.y - mean, dz = v.z - mean, dw = v.w - mean;
    float sq = block_sum128(dx*dx + dy*dy + dz*dz + dw*dw, ws);
    float rstd = rsqrtf(sq * (1.0f / DM) + 1e-5f);
    float4 gg = ((const float4*)g)[tid];
    float4 bb = ((const float4*)bta)[tid];
    float4 o;
    o.x = dx * rstd * gg.x + bb.x;
    o.y = dy * rstd * gg.y + bb.y;
    o.z = dz * rstd * gg.z + bb.z;
    o.w = dw * rstd * gg.w + bb.w;
    ((float4*)(out + (size_t)row * DM))[tid] = o;
}

// ---------------------------------------------------------------------------
// Head stage 2
// ---------------------------------------------------------------------------
__global__ __launch_bounds__(256)
void head2_kernel(const float* __restrict__ tmp, const float* __restrict__ p2_w,
                  const float* __restrict__ p2_b, float* __restrict__ out)
{
    int wid = threadIdx.x >> 5;
    int lane = threadIdx.x & 31;
    int row = blockIdx.x * 8 + wid;
    const float* tr = tmp + (size_t)row * 256;
    float acc = 0.f;
    #pragma unroll
    for (int j = lane; j < 256; j += 32) acc = fmaf(tr[j], p2_w[j], acc);
    #pragma unroll
    for (int o = 16; o > 0; o >>= 1) acc += __shfl_xor_sync(0xffffffffu, acc, o);
    if (lane == 0) out[row] = acc + p2_b[0];
}

// ---------------------------------------------------------------------------
// Launcher
// ---------------------------------------------------------------------------
extern "C" void kernel_launch(void* const* d_in, const int* in_sizes, int n_in,
                              void* d_out, int out_size)
{
    const float* x     = (const float*)d_in[0];
    const float* in_w  = (const float*)d_in[1];
    const float* in_b  = (const float*)d_in[2];
    const float* Wq    = (const float*)d_in[3];
    const float* Wk    = (const float*)d_in[4];
    const float* Wv    = (const float*)d_in[5];
    const float* Wo    = (const float*)d_in[6];
    const float* bo    = (const float*)d_in[7];
    const float* relE  = (const float*)d_in[8];
    const float* w1    = (const float*)d_in[9];
    const float* b1    = (const float*)d_in[10];
    const float* w2    = (const float*)d_in[11];
    const float* b2    = (const float*)d_in[12];
    const float* ln1_g = (const float*)d_in[13];
    const float* ln1_b = (const float*)d_in[14];
    const float* ln2_g = (const float*)d_in[15];
    const float* ln2_b = (const float*)d_in[16];
    const float* on_g  = (const float*)d_in[17];
    const float* on_b  = (const float*)d_in[18];
    const float* p1_w  = (const float*)d_in[19];
    const float* p1_b  = (const float*)d_in[20];
    const float* p2_w  = (const float*)d_in[21];
    const float* p2_b  = (const float*)d_in[22];
    float* out = (float*)d_out;

    float *h, *q, *k, *v, *ctx, *tmp, *qr, *sc;
    cudaGetSymbolAddress((void**)&h,   g_h);
    cudaGetSymbolAddress((void**)&q,   g_q);
    cudaGetSymbolAddress((void**)&k,   g_k);
    cudaGetSymbolAddress((void**)&v,   g_v);
    cudaGetSymbolAddress((void**)&ctx, g_ctx);
    cudaGetSymbolAddress((void**)&tmp, g_tmp);
    cudaGetSymbolAddress((void**)&qr,  g_qr);
    cudaGetSymbolAddress((void**)&sc,  g_sc);

    static bool attr_set = false;
    if (!attr_set) {
        cudaFuncSetAttribute(qrel_kernel, cudaFuncAttributeMaxDynamicSharedMemorySize, QREL_SMEM);
        cudaFuncSetAttribute(attn_score, cudaFuncAttributeMaxDynamicSharedMemorySize, SCORE_SMEM);
        attr_set = true;
    }

    embed_kernel<<<(MROWS * DM) / 256, 256>>>(x, in_w, in_b, h);

    dim3 gD(DM / 128, MROWS / 128);
    dim3 gF(FFD / 128, MROWS / 128);
    dim3 gP(256 / 128, MROWS / 128);
    dim3 gQR(MROWS / 64, NH);
    dim3 gS(SEQ / 128, SEQ / 128, BATCH * NH);
    dim3 gPV(SEQ / 128, BATCH * NH);

    for (int l = 0; l < NLAYER; l++) {
        const float* wq  = Wq + (size_t)l * DM * DM;
        const float* wk  = Wk + (size_t)l * DM * DM;
        const float* wv  = Wv + (size_t)l * DM * DM;
        const float* wo  = Wo + (size_t)l * DM * DM;
        const float* bol = bo + (size_t)l * DM;
        const float* rl  = relE + (size_t)l * NREL * HD;
        const float* w1l = w1 + (size_t)l * DM * FFD;
        const float* b1l = b1 + (size_t)l * FFD;
        const float* w2l = w2 + (size_t)l * FFD * DM;
        const float* b2l = b2 + (size_t)l * DM;

        sgemm128<false, false><<<gD, 256>>>(h, wq, nullptr, q, MROWS, DM, DM);
        sgemm128<false, false><<<gD, 256>>>(h, wk, nullptr, k, MROWS, DM, DM);
        sgemm128<false, false><<<gD, 256>>>(h, wv, nullptr, v, MROWS, DM, DM);

        qrel_kernel<<<gQR, 256, QREL_SMEM>>>(q, rl, qr);
        attn_score<<<gS, 256, SCORE_SMEM>>>(q, k, qr, sc);
        softmax_rows<<<BATCH * NH * SEQ, 128>>>(sc);
        attn_pv<<<gPV, 256>>>(sc, v, ctx);

        sgemm128<true, false><<<gD, 256>>>(ctx, wo, bol, q, MROWS, DM, DM);
        add_ln_kernel<<<MROWS, 128>>>(h, q, ln1_g + (size_t)l * DM, ln1_b + (size_t)l * DM, h);

        sgemm128<true, true><<<gF, 256>>>(h, w1l, b1l, tmp, MROWS, FFD, DM);
        sgemm128<true, false><<<gD, 256>>>(tmp, w2l, b2l, q, MROWS, DM, FFD);
        add_ln_kernel<<<MROWS, 128>>>(h, q, ln2_g + (size_t)l * DM, ln2_b + (size_t)l * DM, h);
    }

    add_ln_kernel<<<MROWS, 128>>>(h, nullptr, on_g, on_b, q);
    sgemm128<true, true><<<gP, 256>>>(q, p1_w, p1_b, tmp, MROWS, 256, DM);
    head2_kernel<<<MROWS / 8, 256>>>(tmp, p2_w, p2_b, out);
}

// round 9
// speedup vs baseline: 4.7519x; 2.4984x over previous
#include <cuda_runtime.h>
#include <cuda_bf16.h>
#include <math.h>
#include <stdint.h>

// Problem constants  (L, D, H, FF, I, MAXREL = 6, 512, 8, 2048, 50, 128)
#define BATCH 16
#define SEQ   512
#define DM    512
#define NH    8
#define HD    64
#define FFD   2048
#define NLAYER 6
#define MAXREL 128
#define NREL  257
#define MROWS (BATCH*SEQ)  // 8192

// Scratch (no allocation allowed)
__device__ float g_h[MROWS*DM];
__device__ float g_q[MROWS*DM];
__device__ float g_k[MROWS*DM];
__device__ float g_v[MROWS*DM];
__device__ float g_ctx[MROWS*DM];
__device__ float g_tmp[MROWS*FFD];
__device__ float g_qr[(size_t)NH*MROWS*NREL];
__device__ float g_sc[(size_t)BATCH*NH*SEQ*SEQ];

// TF32 round-to-nearest (matches cuBLAS tf32 input quantization)
__device__ __forceinline__ float tf32r(float x)
{
    uint32_t u;
    asm("cvt.rna.tf32.f32 %0, %1;" : "=r"(u) : "f"(x));
    return __uint_as_float(u);
}

// m16n8k8 tf32 mma (row.col), fp32 accumulate
__device__ __forceinline__ void mma_tf32(float* c, const uint32_t* a, const uint32_t* b)
{
    asm volatile(
        "mma.sync.aligned.m16n8k8.row.col.f32.tf32.tf32.f32 "
        "{%0,%1,%2,%3}, {%4,%5,%6,%7}, {%8,%9}, {%0,%1,%2,%3};"
        : "+f"(c[0]), "+f"(c[1]), "+f"(c[2]), "+f"(c[3])
        : "r"(a[0]), "r"(a[1]), "r"(a[2]), "r"(a[3]), "r"(b[0]), "r"(b[1]));
}

// ===========================================================================
// tgemm: TF32 tensor-core GEMM via mma.sync.
// C[M,N] = A[M,K] @ B[K,N] (+bias)(+relu). 128x128 tile, BK=16, 256 threads.
// Warp grid: 2 (M) x 4 (N); warp tile 64x32 = 4x4 m16n8 tiles.
// ===========================================================================
template <bool BIAS, bool RELU>
__global__ __launch_bounds__(256, 2)
void tgemm(const float* __restrict__ A, const float* __restrict__ B,
           const float* __restrict__ bias, float* __restrict__ C,
           int N, int K)
{
    __shared__ float As[16][132];   // [k][m], padded
    __shared__ float Bs[16][132];   // [k][n], padded

    int tid = threadIdx.x;
    int warp = tid >> 5;
    int lane = tid & 31;
    int row0 = blockIdx.y * 128;
    int col0 = blockIdx.x * 128;

    int wm = (warp & 1) * 64;       // warp M offset
    int wn = (warp >> 1) * 32;      // warp N offset
    int groupID = lane >> 2;        // 0..7
    int tig = lane & 3;             // 0..3

    float acc[4][4][4] = {};        // [mtile][ntile][creg]

    for (int k0 = 0; k0 < K; k0 += 16) {
        // load A tile 128x16 -> As[k][m] (tf32-rounded)
        #pragma unroll
        for (int i = 0; i < 2; i++) {
            int f = tid + i * 256;
            int ar = f >> 2;
            int ac = (f & 3) << 2;
            float4 av = *(const float4*)(A + (size_t)(row0 + ar) * K + k0 + ac);
            As[ac + 0][ar] = tf32r(av.x);
            As[ac + 1][ar] = tf32r(av.y);
            As[ac + 2][ar] = tf32r(av.z);
            As[ac + 3][ar] = tf32r(av.w);
        }
        // load B tile 16x128 -> Bs[k][n] (tf32-rounded)
        #pragma unroll
        for (int i = 0; i < 2; i++) {
            int f = tid + i * 256;
            int br = f >> 5;
            int bc = (f & 31) << 2;
            float4 bv = *(const float4*)(B + (size_t)(k0 + br) * N + col0 + bc);
            Bs[br][bc + 0] = tf32r(bv.x);
            Bs[br][bc + 1] = tf32r(bv.y);
            Bs[br][bc + 2] = tf32r(bv.z);
            Bs[br][bc + 3] = tf32r(bv.w);
        }
        __syncthreads();

        #pragma unroll
        for (int ks = 0; ks < 16; ks += 8) {
            uint32_t af[4][4];
            uint32_t bf[4][2];
            #pragma unroll
            for (int mt = 0; mt < 4; mt++) {
                int m = wm + mt * 16 + groupID;
                af[mt][0] = __float_as_uint(As[ks + tig    ][m]);
                af[mt][1] = __float_as_uint(As[ks + tig    ][m + 8]);
                af[mt][2] = __float_as_uint(As[ks + tig + 4][m]);
                af[mt][3] = __float_as_uint(As[ks + tig + 4][m + 8]);
            }
            #pragma unroll
            for (int nt = 0; nt < 4; nt++) {
                int n = wn + nt * 8 + groupID;
                bf[nt][0] = __float_as_uint(Bs[ks + tig    ][n]);
                bf[nt][1] = __float_as_uint(Bs[ks + tig + 4][n]);
            }
            #pragma unroll
            for (int mt = 0; mt < 4; mt++)
                #pragma unroll
                for (int nt = 0; nt < 4; nt++)
                    mma_tf32(acc[mt][nt], af[mt], bf[nt]);
        }
        __syncthreads();
    }

    // epilogue: c0 (gid, tig*2), c1 (gid, tig*2+1), c2 (gid+8, tig*2), c3 (+1)
    #pragma unroll
    for (int mt = 0; mt < 4; mt++) {
        int ra = row0 + wm + mt * 16 + groupID;
        int rb = ra + 8;
        #pragma unroll
        for (int nt = 0; nt < 4; nt++) {
            int col = col0 + wn + nt * 8 + tig * 2;
            float o0 = acc[mt][nt][0], o1 = acc[mt][nt][1];
            float o2 = acc[mt][nt][2], o3 = acc[mt][nt][3];
            if (BIAS) {
                float b0 = bias[col], b1 = bias[col + 1];
                o0 += b0; o1 += b1; o2 += b0; o3 += b1;
            }
            if (RELU) {
                o0 = fmaxf(o0, 0.f); o1 = fmaxf(o1, 0.f);
                o2 = fmaxf(o2, 0.f); o3 = fmaxf(o3, 0.f);
            }
            *(float2*)(C + (size_t)ra * N + col) = make_float2(o0, o1);
            *(float2*)(C + (size_t)rb * N + col) = make_float2(o2, o3);
        }
    }
}

// ===========================================================================
// Embedding
// ===========================================================================
__global__ void embed_kernel(const float* __restrict__ x,
                             const float* __restrict__ in_w,
                             const float* __restrict__ in_b,
                             float* __restrict__ h)
{
    int idx = blockIdx.x * 256 + threadIdx.x;
    if (idx >= MROWS * DM) return;
    int r = idx >> 9;
    int c = idx & 511;
    const float* xr = x + (size_t)r * 50;
    float acc = in_b[c];
    #pragma unroll 10
    for (int i = 0; i < 50; i++)
        acc = fmaf(xr[i], in_w[i * DM + c], acc);
    int s = r & (SEQ - 1);
    int two_i = c & ~1;
    float earg = (float)two_i * (-9.210340371976184f / 512.0f);
    float div32 = expf(earg);
    float argf = (float)s * div32;
    double pe = (c & 1) ? cos((double)argf) : sin((double)argf);
    h[idx] = acc + (float)pe;
}

// ===========================================================================
// SGEMM 128x128 (fp32) — head p1 gemm
// ===========================================================================
template <bool BIAS, bool RELU>
__global__ __launch_bounds__(256)
void sgemm128(const float* __restrict__ A, const float* __restrict__ Bm,
              const float* __restrict__ bias, float* __restrict__ C,
              int M, int N, int K)
{
    __shared__ float As[16][128];
    __shared__ float Bs[16][128];

    int tid = threadIdx.x;
    int row0 = blockIdx.y * 128;
    int col0 = blockIdx.x * 128;
    int tx = tid & 15;
    int ty = tid >> 4;

    float acc[8][8] = {};

    for (int k0 = 0; k0 < K; k0 += 16) {
        #pragma unroll
        for (int i = 0; i < 2; i++) {
            int f = tid + i * 256;
            int ar = f >> 2;
            int ac = (f & 3) << 2;
            float4 av = *(const float4*)(A + (size_t)(row0 + ar) * K + k0 + ac);
            As[ac + 0][ar] = av.x;
            As[ac + 1][ar] = av.y;
            As[ac + 2][ar] = av.z;
            As[ac + 3][ar] = av.w;
        }
        #pragma unroll
        for (int i = 0; i < 2; i++) {
            int f = tid + i * 256;
            int br = f >> 5;
            int bc = (f & 31) << 2;
            *(float4*)&Bs[br][bc] = *(const float4*)(Bm + (size_t)(k0 + br) * N + col0 + bc);
        }
        __syncthreads();

        #pragma unroll
        for (int kk = 0; kk < 16; kk++) {
            float4 a0 = *(const float4*)&As[kk][ty * 8];
            float4 a1 = *(const float4*)&As[kk][ty * 8 + 4];
            float4 b0 = *(const float4*)&Bs[kk][tx * 8];
            float4 b1 = *(const float4*)&Bs[kk][tx * 8 + 4];
            float av[8] = {a0.x, a0.y, a0.z, a0.w, a1.x, a1.y, a1.z, a1.w};
            float bv[8] = {b0.x, b0.y, b0.z, b0.w, b1.x, b1.y, b1.z, b1.w};
            #pragma unroll
            for (int i = 0; i < 8; i++)
                #pragma unroll
                for (int j = 0; j < 8; j++)
                    acc[i][j] = fmaf(av[i], bv[j], acc[i][j]);
        }
        __syncthreads();
    }

    float bvv[8] = {};
    if (BIAS) {
        float4 c0 = *(const float4*)(bias + col0 + tx * 8);
        float4 c1 = *(const float4*)(bias + col0 + tx * 8 + 4);
        bvv[0]=c0.x; bvv[1]=c0.y; bvv[2]=c0.z; bvv[3]=c0.w;
        bvv[4]=c1.x; bvv[5]=c1.y; bvv[6]=c1.z; bvv[7]=c1.w;
    }
    #pragma unroll
    for (int i = 0; i < 8; i++) {
        int row = row0 + ty * 8 + i;
        float o[8];
        #pragma unroll
        for (int j = 0; j < 8; j++) {
            o[j] = acc[i][j];
            if (BIAS) o[j] += bvv[j];
            if (RELU) o[j] = fmaxf(o[j], 0.f);
        }
        *(float4*)(C + (size_t)row * N + col0 + tx * 8)     = make_float4(o[0],o[1],o[2],o[3]);
        *(float4*)(C + (size_t)row * N + col0 + tx * 8 + 4) = make_float4(o[4],o[5],o[6],o[7]);
    }
}

// ===========================================================================
// qrel: QR[h][row][j] = q[row, h*64:] . rel[j]
// ===========================================================================
#define REL_FLOATS  ((NREL * 65 + 15) & ~15)
#define QREL_SMEM   ((REL_FLOATS + 64 * 64) * (int)sizeof(float))
__global__ __launch_bounds__(256)
void qrel_kernel(const float* __restrict__ qb, const float* __restrict__ rel,
                 float* __restrict__ qr)
{
    extern __shared__ float sm[];
    float* rel_s = sm;
    float* Qs    = sm + REL_FLOATS;

    int tid = threadIdx.x;
    int row0 = blockIdx.x * 64;
    int h = blockIdx.y;

    for (int idx = tid; idx < NREL * 16; idx += 256) {
        int j = idx >> 4;
        int d0 = (idx & 15) << 2;
        float4 rv = *(const float4*)(rel + (size_t)j * HD + d0);
        rel_s[j * 65 + d0 + 0] = rv.x;
        rel_s[j * 65 + d0 + 1] = rv.y;
        rel_s[j * 65 + d0 + 2] = rv.z;
        rel_s[j * 65 + d0 + 3] = rv.w;
    }
    for (int idx = tid; idx < 64 * 16; idx += 256) {
        int r = idx >> 4;
        int d0 = (idx & 15) << 2;
        *(float4*)&Qs[r * HD + d0] =
            *(const float4*)(qb + (size_t)(row0 + r) * DM + h * HD + d0);
    }
    __syncthreads();

    for (int j = tid; j < NREL; j += 256) {
        for (int r0 = 0; r0 < 64; r0 += 8) {
            float acc8[8] = {};
            for (int d = 0; d < HD; d++) {
                float rv = rel_s[j * 65 + d];
                #pragma unroll
                for (int t = 0; t < 8; t++)
                    acc8[t] = fmaf(Qs[(r0 + t) * HD + d], rv, acc8[t]);
            }
            #pragma unroll
            for (int t = 0; t < 8; t++)
                qr[((size_t)h * MROWS + row0 + r0 + t) * NREL + j] = acc8[t];
        }
    }
}

// ===========================================================================
// attn_score: 128x128 tile, K=64 single pass
// ===========================================================================
#define SCORE_SMEM (2 * 64 * 128 * (int)sizeof(float))
__global__ __launch_bounds__(256)
void attn_score(const float* __restrict__ qb, const float* __restrict__ kb,
                const float* __restrict__ qr, float* __restrict__ sc)
{
    extern __shared__ float sm[];
    float* As = sm;
    float* Bs = sm + 64*128;

    int tid = threadIdx.x;
    int k0 = blockIdx.x * 128;
    int q0 = blockIdx.y * 128;
    int bh = blockIdx.z;
    int b = bh >> 3;
    int h = bh & 7;
    int bs = b * SEQ;

    #pragma unroll
    for (int i = 0; i < 8; i++) {
        int idx = tid + i * 256;
        int r  = idx & 127;
        int d0 = (idx >> 7) << 2;
        float4 av = *(const float4*)(qb + (size_t)(bs + q0 + r) * DM + h * HD + d0);
        As[(d0 + 0) * 128 + r] = av.x;
        As[(d0 + 1) * 128 + r] = av.y;
        As[(d0 + 2) * 128 + r] = av.z;
        As[(d0 + 3) * 128 + r] = av.w;
        float4 bv = *(const float4*)(kb + (size_t)(bs + k0 + r) * DM + h * HD + d0);
        Bs[(d0 + 0) * 128 + r] = bv.x;
        Bs[(d0 + 1) * 128 + r] = bv.y;
        Bs[(d0 + 2) * 128 + r] = bv.z;
        Bs[(d0 + 3) * 128 + r] = bv.w;
    }
    __syncthreads();

    int tx = tid & 15;
    int ty = tid >> 4;
    float acc[8][8] = {};
    #pragma unroll 8
    for (int kk = 0; kk < 64; kk++) {
        float4 a0 = *(const float4*)&As[kk * 128 + ty * 8];
        float4 a1 = *(const float4*)&As[kk * 128 + ty * 8 + 4];
        float4 b0 = *(const float4*)&Bs[kk * 128 + tx * 8];
        float4 b1 = *(const float4*)&Bs[kk * 128 + tx * 8 + 4];
        float av[8] = {a0.x, a0.y, a0.z, a0.w, a1.x, a1.y, a1.z, a1.w};
        float bv[8] = {b0.x, b0.y, b0.z, b0.w, b1.x, b1.y, b1.z, b1.w};
        #pragma unroll
        for (int i = 0; i < 8; i++)
            #pragma unroll
            for (int j = 0; j < 8; j++)
                acc[i][j] = fmaf(av[i], bv[j], acc[i][j]);
    }

    #pragma unroll
    for (int i = 0; i < 8; i++) {
        int qg = q0 + ty * 8 + i;
        const float* qrow = qr + ((size_t)h * MROWS + bs + qg) * NREL;
        float o[8];
        #pragma unroll
        for (int j = 0; j < 8; j++) {
            int kg = k0 + tx * 8 + j;
            int di = kg - qg;
            di = min(max(di, -MAXREL), MAXREL) + MAXREL;
            o[j] = acc[i][j] * 0.125f + qrow[di];
        }
        float* op = sc + ((size_t)bh * SEQ + qg) * SEQ + k0 + tx * 8;
        *(float4*)op       = make_float4(o[0], o[1], o[2], o[3]);
        *(float4*)(op + 4) = make_float4(o[4], o[5], o[6], o[7]);
    }
}

// ===========================================================================
// softmax rows
// ===========================================================================
__global__ __launch_bounds__(128)
void softmax_rows(float* __restrict__ sc)
{
    __shared__ float ws[4];
    int tid = threadIdx.x;
    int lane = tid & 31, w = tid >> 5;
    float* row = sc + (size_t)blockIdx.x * SEQ;
    float4 v = ((float4*)row)[tid];

    float m = fmaxf(fmaxf(v.x, v.y), fmaxf(v.z, v.w));
    #pragma unroll
    for (int o = 16; o > 0; o >>= 1) m = fmaxf(m, __shfl_xor_sync(0xffffffffu, m, o));
    if (lane == 0) ws[w] = m;
    __syncthreads();
    m = fmaxf(fmaxf(ws[0], ws[1]), fmaxf(ws[2], ws[3]));
    __syncthreads();

    v.x = __expf(v.x - m); v.y = __expf(v.y - m);
    v.z = __expf(v.z - m); v.w = __expf(v.w - m);
    float s = v.x + v.y + v.z + v.w;
    #pragma unroll
    for (int o = 16; o > 0; o >>= 1) s += __shfl_xor_sync(0xffffffffu, s, o);
    if (lane == 0) ws[w] = s;
    __syncthreads();
    s = ws[0] + ws[1] + ws[2] + ws[3];
    float inv = 1.0f / s;
    v.x *= inv; v.y *= inv; v.z *= inv; v.w *= inv;
    ((float4*)row)[tid] = v;
}

// ===========================================================================
// attn_pv
// ===========================================================================
__global__ __launch_bounds__(256)
void attn_pv(const float* __restrict__ p, const float* __restrict__ vb,
             float* __restrict__ ctx)
{
    __shared__ float Ps[64 * 128];
    __shared__ float Vs[64 * 64];

    int tid = threadIdx.x;
    int q0 = blockIdx.x * 128;
    int bh = blockIdx.y;
    int b = bh >> 3;
    int h = bh & 7;
    int bs = b * SEQ;

    int tx = tid & 15;
    int ty = tid >> 4;
    float acc[8][4] = {};

    for (int kc = 0; kc < SEQ; kc += 64) {
        #pragma unroll
        for (int i = 0; i < 8; i++) {
            int idx = tid + i * 256;
            int r  = idx & 127;
            int kk0 = (idx >> 7) << 2;
            float4 pv = *(const float4*)(p + ((size_t)bh * SEQ + q0 + r) * SEQ + kc + kk0);
            Ps[(kk0 + 0) * 128 + r] = pv.x;
            Ps[(kk0 + 1) * 128 + r] = pv.y;
            Ps[(kk0 + 2) * 128 + r] = pv.z;
            Ps[(kk0 + 3) * 128 + r] = pv.w;
        }
        #pragma unroll
        for (int i = 0; i < 4; i++) {
            int idx = tid + i * 256;
            int kk = idx >> 4;
            int d0 = (idx & 15) << 2;
            *(float4*)&Vs[kk * 64 + d0] =
                *(const float4*)(vb + (size_t)(bs + kc + kk) * DM + h * HD + d0);
        }
        __syncthreads();

        #pragma unroll 8
        for (int kk = 0; kk < 64; kk++) {
            float4 a0 = *(const float4*)&Ps[kk * 128 + ty * 8];
            float4 a1 = *(const float4*)&Ps[kk * 128 + ty * 8 + 4];
            float4 bv = *(const float4*)&Vs[kk * 64 + tx * 4];
            float av[8] = {a0.x, a0.y, a0.z, a0.w, a1.x, a1.y, a1.z, a1.w};
            #pragma unroll
            for (int i = 0; i < 8; i++) {
                acc[i][0] = fmaf(av[i], bv.x, acc[i][0]);
                acc[i][1] = fmaf(av[i], bv.y, acc[i][1]);
                acc[i][2] = fmaf(av[i], bv.z, acc[i][2]);
                acc[i][3] = fmaf(av[i], bv.w, acc[i][3]);
            }
        }
        __syncthreads();
    }

    #pragma unroll
    for (int i = 0; i < 8; i++) {
        *(float4*)(ctx + (size_t)(bs + q0 + ty * 8 + i) * DM + h * HD + tx * 4) =
            make_float4(acc[i][0], acc[i][1], acc[i][2], acc[i][3]);
    }
}

// ===========================================================================
// residual add + LayerNorm
// ===========================================================================
__device__ __forceinline__ float block_sum128(float v, float* ws)
{
    #pragma unroll
    for (int o = 16; o > 0; o >>= 1) v += __shfl_xor_sync(0xffffffffu, v, o);
    int lane = threadIdx.x & 31, w = threadIdx.x >> 5;
    if (lane == 0) ws[w] = v;
    __syncthreads();
    v = ws[0] + ws[1] + ws[2] + ws[3];
    __syncthreads();
    return v;
}

__global__ __launch_bounds__(128)
void add_ln_kernel(const float* __restrict__ x, const float* __restrict__ add,
                   const float* __restrict__ g, const float* __restrict__ bta,
                   float* __restrict__ out)
{
    __shared__ float ws[4];
    int row = blockIdx.x;
    int tid = threadIdx.x;
    float4 v = ((const float4*)(x + (size_t)row * DM))[tid];
    if (add != nullptr) {
        float4 a = ((const float4*)(add + (size_t)row * DM))[tid];
        v.x += a.x; v.y += a.y; v.z += a.z; v.w += a.w;
    }
    float s = block_sum128(v.x + v.y + v.z + v.w, ws);
    float mean = s * (1.0f / DM);
    float dx = v.x - mean, dy = v.y - mean, dz = v.z - mean, dw = v.w - mean;
    float sq = block_sum128(dx*dx + dy*dy + dz*dz + dw*dw, ws);
    float rstd = rsqrtf(sq * (1.0f / DM) + 1e-5f);
    float4 gg = ((const float4*)g)[tid];
    float4 bb = ((const float4*)bta)[tid];
    float4 o;
    o.x = dx * rstd * gg.x + bb.x;
    o.y = dy * rstd * gg.y + bb.y;
    o.z = dz * rstd * gg.z + bb.z;
    o.w = dw * rstd * gg.w + bb.w;
    ((float4*)(out + (size_t)row * DM))[tid] = o;
}

// ===========================================================================
// head stage 2
// ===========================================================================
__global__ __launch_bounds__(256)
void head2_kernel(const float* __restrict__ tmp, const float* __restrict__ p2_w,
                  const float* __restrict__ p2_b, float* __restrict__ out)
{
    int wid = threadIdx.x >> 5;
    int lane = threadIdx.x & 31;
    int row = blockIdx.x * 8 + wid;
    const float* tr = tmp + (size_t)row * 256;
    float acc = 0.f;
    #pragma unroll
    for (int j = lane; j < 256; j += 32) acc = fmaf(tr[j], p2_w[j], acc);
    #pragma unroll
    for (int o = 16; o > 0; o >>= 1) acc += __shfl_xor_sync(0xffffffffu, acc, o);
    if (lane == 0) out[row] = acc + p2_b[0];
}

// ===========================================================================
// Launcher
// ===========================================================================
extern "C" void kernel_launch(void* const* d_in, const int* in_sizes, int n_in,
                              void* d_out, int out_size)
{
    const float* x     = (const float*)d_in[0];
    const float* in_w  = (const float*)d_in[1];
    const float* in_b  = (const float*)d_in[2];
    const float* Wq    = (const float*)d_in[3];
    const float* Wk    = (const float*)d_in[4];
    const float* Wv    = (const float*)d_in[5];
    const float* Wo    = (const float*)d_in[6];
    const float* bo    = (const float*)d_in[7];
    const float* relE  = (const float*)d_in[8];
    const float* w1    = (const float*)d_in[9];
    const float* b1    = (const float*)d_in[10];
    const float* w2    = (const float*)d_in[11];
    const float* b2    = (const float*)d_in[12];
    const float* ln1_g = (const float*)d_in[13];
    const float* ln1_b = (const float*)d_in[14];
    const float* ln2_g = (const float*)d_in[15];
    const float* ln2_b = (const float*)d_in[16];
    const float* on_g  = (const float*)d_in[17];
    const float* on_b  = (const float*)d_in[18];
    const float* p1_w  = (const float*)d_in[19];
    const float* p1_b  = (const float*)d_in[20];
    const float* p2_w  = (const float*)d_in[21];
    const float* p2_b  = (const float*)d_in[22];
    float* out = (float*)d_out;

    float *h, *q, *k, *v, *ctx, *tmp, *qr, *sc;
    cudaGetSymbolAddress((void**)&h,   g_h);
    cudaGetSymbolAddress((void**)&q,   g_q);
    cudaGetSymbolAddress((void**)&k,   g_k);
    cudaGetSymbolAddress((void**)&v,   g_v);
    cudaGetSymbolAddress((void**)&ctx, g_ctx);
    cudaGetSymbolAddress((void**)&tmp, g_tmp);
    cudaGetSymbolAddress((void**)&qr,  g_qr);
    cudaGetSymbolAddress((void**)&sc,  g_sc);

    static bool attr_set = false;
    if (!attr_set) {
        cudaFuncSetAttribute(qrel_kernel, cudaFuncAttributeMaxDynamicSharedMemorySize, QREL_SMEM);
        cudaFuncSetAttribute(attn_score, cudaFuncAttributeMaxDynamicSharedMemorySize, SCORE_SMEM);
        attr_set = true;
    }

    embed_kernel<<<(MROWS * DM) / 256, 256>>>(x, in_w, in_b, h);

    dim3 gD(DM / 128, MROWS / 128);     // 4 x 64
    dim3 gF(FFD / 128, MROWS / 128);    // 16 x 64
    dim3 gP(256 / 128, MROWS / 128);
    dim3 gQR(MROWS / 64, NH);
    dim3 gS(SEQ / 128, SEQ / 128, BATCH * NH);
    dim3 gPV(SEQ / 128, BATCH * NH);

    for (int l = 0; l < NLAYER; l++) {
        const float* wq  = Wq + (size_t)l * DM * DM;
        const float* wk  = Wk + (size_t)l * DM * DM;
        const float* wv  = Wv + (size_t)l * DM * DM;
        const float* wo  = Wo + (size_t)l * DM * DM;
        const float* bol = bo + (size_t)l * DM;
        const float* rl  = relE + (size_t)l * NREL * HD;
        const float* w1l = w1 + (size_t)l * DM * FFD;
        const float* b1l = b1 + (size_t)l * FFD;
        const float* w2l = w2 + (size_t)l * FFD * DM;
        const float* b2l = b2 + (size_t)l * DM;

        tgemm<false, false><<<gD, 256>>>(h, wq, nullptr, q, DM, DM);
        tgemm<false, false><<<gD, 256>>>(h, wk, nullptr, k, DM, DM);
        tgemm<false, false><<<gD, 256>>>(h, wv, nullptr, v, DM, DM);

        qrel_kernel<<<gQR, 256, QREL_SMEM>>>(q, rl, qr);
        attn_score<<<gS, 256, SCORE_SMEM>>>(q, k, qr, sc);
        softmax_rows<<<BATCH * NH * SEQ, 128>>>(sc);
        attn_pv<<<gPV, 256>>>(sc, v, ctx);

        tgemm<true, false><<<gD, 256>>>(ctx, wo, bol, q, DM, DM);
        add_ln_kernel<<<MROWS, 128>>>(h, q, ln1_g + (size_t)l * DM, ln1_b + (size_t)l * DM, h);

        tgemm<true, true><<<gF, 256>>>(h, w1l, b1l, tmp, FFD, DM);
        tgemm<true, false><<<gD, 256>>>(tmp, w2l, b2l, q, DM, FFD);
        add_ln_kernel<<<MROWS, 128>>>(h, q, ln2_g + (size_t)l * DM, ln2_b + (size_t)l * DM, h);
    }

    add_ln_kernel<<<MROWS, 128>>>(h, nullptr, on_g, on_b, q);
    sgemm128<true, true><<<gP, 256>>>(q, p1_w, p1_b, tmp, MROWS, 256, DM);
    head2_kernel<<<MROWS / 8, 256>>>(tmp, p2_w, p2_b, out);
}

// round 10
// speedup vs baseline: 5.7549x; 1.2111x over previous
#include <cuda_runtime.h>
#include <cuda_bf16.h>
#include <math.h>
#include <stdint.h>

// Problem constants  (L, D, H, FF, I, MAXREL = 6, 512, 8, 2048, 50, 128)
#define BATCH 16
#define SEQ   512
#define DM    512
#define NH    8
#define HD    64
#define FFD   2048
#define NLAYER 6
#define MAXREL 128
#define NREL  257
#define MROWS (BATCH*SEQ)  // 8192

// Scratch (no allocation allowed)
__device__ float g_h[MROWS*DM];
__device__ float g_q[MROWS*DM];
__device__ float g_k[MROWS*DM];
__device__ float g_v[MROWS*DM];
__device__ float g_ctx[MROWS*DM];
__device__ float g_tmp[MROWS*FFD];
__device__ float g_qr[(size_t)NH*MROWS*NREL];
__device__ float g_sc[(size_t)BATCH*NH*SEQ*SEQ];

// TF32 round-to-nearest -> bits
__device__ __forceinline__ uint32_t tf32u(float x)
{
    uint32_t u;
    asm("cvt.rna.tf32.f32 %0, %1;" : "=r"(u) : "f"(x));
    return u;
}
__device__ __forceinline__ float tf32r(float x)
{
    return __uint_as_float(tf32u(x));
}

// m16n8k8 tf32 mma (row.col), fp32 accumulate
__device__ __forceinline__ void mma_tf32(float* c, const uint32_t* a, const uint32_t* b)
{
    asm volatile(
        "mma.sync.aligned.m16n8k8.row.col.f32.tf32.tf32.f32 "
        "{%0,%1,%2,%3}, {%4,%5,%6,%7}, {%8,%9}, {%0,%1,%2,%3};"
        : "+f"(c[0]), "+f"(c[1]), "+f"(c[2]), "+f"(c[3])
        : "r"(a[0]), "r"(a[1]), "r"(a[2]), "r"(a[3]), "r"(b[0]), "r"(b[1]));
}

__device__ __forceinline__ uint32_t smem_u32(const void* p) {
    uint32_t a;
    asm("{ .reg .u64 t; cvta.to.shared.u64 t, %1; cvt.u32.u64 %0, t; }" : "=r"(a) : "l"(p));
    return a;
}
#define CP_ASYNC16(dst, src) \
    asm volatile("cp.async.cg.shared.global [%0], [%1], 16;" :: "r"(dst), "l"(src))
#define CP_COMMIT() asm volatile("cp.async.commit_group;" ::: "memory")
#define CP_WAIT1()  asm volatile("cp.async.wait_group 1;" ::: "memory")

// ===========================================================================
// tgemm: TF32 mma.sync GEMM, cp.async double-buffered.
// C[M,N] = A[M,K] @ B[K,N] (+bias)(+relu). 128x128 tile, BK=16, 256 threads.
// A smem: [m][k] pad 20 floats; B smem: [k][n] pad 136 floats. 2 stages.
// ===========================================================================
#define APAD 20
#define BPAD 136
#define A_STAGE (128 * APAD)     // floats
#define B_STAGE (16 * BPAD)

template <bool BIAS, bool RELU>
__global__ __launch_bounds__(256, 2)
void tgemm(const float* __restrict__ A, const float* __restrict__ B,
           const float* __restrict__ bias, float* __restrict__ C,
           int N, int K)
{
    __shared__ float As[2][A_STAGE];
    __shared__ float Bs[2][B_STAGE];

    int tid = threadIdx.x;
    int warp = tid >> 5;
    int lane = tid & 31;
    int row0 = blockIdx.y * 128;
    int col0 = blockIdx.x * 128;

    int wm = (warp & 1) * 64;
    int wn = (warp >> 1) * 32;
    int gid = lane >> 2;            // 0..7
    int tig = lane & 3;             // 0..3

    uint32_t asb[2] = { smem_u32(As[0]), smem_u32(As[1]) };
    uint32_t bsb[2] = { smem_u32(Bs[0]), smem_u32(Bs[1]) };

    // per-thread copy assignments (2 chunks A, 2 chunks B each)
    // A: 512 chunks; chunk ch -> row=ch>>2, fc=(ch&3)*4
    // B: 512 chunks; chunk ch -> kk=ch>>5, nc=(ch&31)*4
    auto prefetch = [&](int c, int s) {
        int k0 = c << 4;
        #pragma unroll
        for (int i = 0; i < 2; i++) {
            int ch = tid + i * 256;
            int ar = ch >> 2;
            int fc = (ch & 3) << 2;
            CP_ASYNC16(asb[s] + (ar * APAD + fc) * 4,
                       A + (size_t)(row0 + ar) * K + k0 + fc);
            int kk = ch >> 5;
            int nc = (ch & 31) << 2;
            CP_ASYNC16(bsb[s] + (kk * BPAD + nc) * 4,
                       B + (size_t)(k0 + kk) * N + col0 + nc);
        }
    };

    float acc[4][4][4] = {};
    const int NC = K >> 4;

    prefetch(0, 0);
    CP_COMMIT();

    for (int c = 0; c < NC; c++) {
        if (c + 1 < NC) prefetch(c + 1, (c + 1) & 1);
        CP_COMMIT();
        CP_WAIT1();
        __syncthreads();

        const float* as = As[c & 1];
        const float* bs = Bs[c & 1];
        #pragma unroll
        for (int ks = 0; ks < 16; ks += 8) {
            uint32_t af[4][4];
            uint32_t bf[4][2];
            #pragma unroll
            for (int mt = 0; mt < 4; mt++) {
                int m = wm + mt * 16 + gid;
                af[mt][0] = tf32u(as[m * APAD + ks + tig]);
                af[mt][1] = tf32u(as[(m + 8) * APAD + ks + tig]);
                af[mt][2] = tf32u(as[m * APAD + ks + tig + 4]);
                af[mt][3] = tf32u(as[(m + 8) * APAD + ks + tig + 4]);
            }
            #pragma unroll
            for (int nt = 0; nt < 4; nt++) {
                int n = wn + nt * 8 + gid;
                bf[nt][0] = tf32u(bs[(ks + tig) * BPAD + n]);
                bf[nt][1] = tf32u(bs[(ks + tig + 4) * BPAD + n]);
            }
            #pragma unroll
            for (int mt = 0; mt < 4; mt++)
                #pragma unroll
                for (int nt = 0; nt < 4; nt++)
                    mma_tf32(acc[mt][nt], af[mt], bf[nt]);
        }
        __syncthreads();
    }

    // epilogue
    #pragma unroll
    for (int mt = 0; mt < 4; mt++) {
        int ra = row0 + wm + mt * 16 + gid;
        int rb = ra + 8;
        #pragma unroll
        for (int nt = 0; nt < 4; nt++) {
            int col = col0 + wn + nt * 8 + tig * 2;
            float o0 = acc[mt][nt][0], o1 = acc[mt][nt][1];
            float o2 = acc[mt][nt][2], o3 = acc[mt][nt][3];
            if (BIAS) {
                float b0 = bias[col], b1 = bias[col + 1];
                o0 += b0; o1 += b1; o2 += b0; o3 += b1;
            }
            if (RELU) {
                o0 = fmaxf(o0, 0.f); o1 = fmaxf(o1, 0.f);
                o2 = fmaxf(o2, 0.f); o3 = fmaxf(o3, 0.f);
            }
            *(float2*)(C + (size_t)ra * N + col) = make_float2(o0, o1);
            *(float2*)(C + (size_t)rb * N + col) = make_float2(o2, o3);
        }
    }
}

// ===========================================================================
// Embedding
// ===========================================================================
__global__ void embed_kernel(const float* __restrict__ x,
                             const float* __restrict__ in_w,
                             const float* __restrict__ in_b,
                             float* __restrict__ h)
{
    int idx = blockIdx.x * 256 + threadIdx.x;
    if (idx >= MROWS * DM) return;
    int r = idx >> 9;
    int c = idx & 511;
    const float* xr = x + (size_t)r * 50;
    float acc = in_b[c];
    #pragma unroll 10
    for (int i = 0; i < 50; i++)
        acc = fmaf(xr[i], in_w[i * DM + c], acc);
    int s = r & (SEQ - 1);
    int two_i = c & ~1;
    float earg = (float)two_i * (-9.210340371976184f / 512.0f);
    float div32 = expf(earg);
    float argf = (float)s * div32;
    double pe = (c & 1) ? cos((double)argf) : sin((double)argf);
    h[idx] = acc + (float)pe;
}

// ===========================================================================
// SGEMM 128x128 (fp32) — head p1 gemm
// ===========================================================================
template <bool BIAS, bool RELU>
__global__ __launch_bounds__(256)
void sgemm128(const float* __restrict__ A, const float* __restrict__ Bm,
              const float* __restrict__ bias, float* __restrict__ C,
              int M, int N, int K)
{
    __shared__ float As2[16][128];
    __shared__ float Bs2[16][128];

    int tid = threadIdx.x;
    int row0 = blockIdx.y * 128;
    int col0 = blockIdx.x * 128;
    int tx = tid & 15;
    int ty = tid >> 4;

    float acc[8][8] = {};

    for (int k0 = 0; k0 < K; k0 += 16) {
        #pragma unroll
        for (int i = 0; i < 2; i++) {
            int f = tid + i * 256;
            int ar = f >> 2;
            int ac = (f & 3) << 2;
            float4 av = *(const float4*)(A + (size_t)(row0 + ar) * K + k0 + ac);
            As2[ac + 0][ar] = av.x;
            As2[ac + 1][ar] = av.y;
            As2[ac + 2][ar] = av.z;
            As2[ac + 3][ar] = av.w;
        }
        #pragma unroll
        for (int i = 0; i < 2; i++) {
            int f = tid + i * 256;
            int br = f >> 5;
            int bc = (f & 31) << 2;
            *(float4*)&Bs2[br][bc] = *(const float4*)(Bm + (size_t)(k0 + br) * N + col0 + bc);
        }
        __syncthreads();

        #pragma unroll
        for (int kk = 0; kk < 16; kk++) {
            float4 a0 = *(const float4*)&As2[kk][ty * 8];
            float4 a1 = *(const float4*)&As2[kk][ty * 8 + 4];
            float4 b0 = *(const float4*)&Bs2[kk][tx * 8];
            float4 b1 = *(const float4*)&Bs2[kk][tx * 8 + 4];
            float av[8] = {a0.x, a0.y, a0.z, a0.w, a1.x, a1.y, a1.z, a1.w};
            float bv[8] = {b0.x, b0.y, b0.z, b0.w, b1.x, b1.y, b1.z, b1.w};
            #pragma unroll
            for (int i = 0; i < 8; i++)
                #pragma unroll
                for (int j = 0; j < 8; j++)
                    acc[i][j] = fmaf(av[i], bv[j], acc[i][j]);
        }
        __syncthreads();
    }

    float bvv[8] = {};
    if (BIAS) {
        float4 c0 = *(const float4*)(bias + col0 + tx * 8);
        float4 c1 = *(const float4*)(bias + col0 + tx * 8 + 4);
        bvv[0]=c0.x; bvv[1]=c0.y; bvv[2]=c0.z; bvv[3]=c0.w;
        bvv[4]=c1.x; bvv[5]=c1.y; bvv[6]=c1.z; bvv[7]=c1.w;
    }
    #pragma unroll
    for (int i = 0; i < 8; i++) {
        int row = row0 + ty * 8 + i;
        float o[8];
        #pragma unroll
        for (int j = 0; j < 8; j++) {
            o[j] = acc[i][j];
            if (BIAS) o[j] += bvv[j];
            if (RELU) o[j] = fmaxf(o[j], 0.f);
        }
        *(float4*)(C + (size_t)row * N + col0 + tx * 8)     = make_float4(o[0],o[1],o[2],o[3]);
        *(float4*)(C + (size_t)row * N + col0 + tx * 8 + 4) = make_float4(o[4],o[5],o[6],o[7]);
    }
}

// ===========================================================================
// qrel
// ===========================================================================
#define REL_FLOATS  ((NREL * 65 + 15) & ~15)
#define QREL_SMEM   ((REL_FLOATS + 64 * 64) * (int)sizeof(float))
__global__ __launch_bounds__(256)
void qrel_kernel(const float* __restrict__ qb, const float* __restrict__ rel,
                 float* __restrict__ qr)
{
    extern __shared__ float sm[];
    float* rel_s = sm;
    float* Qs    = sm + REL_FLOATS;

    int tid = threadIdx.x;
    int row0 = blockIdx.x * 64;
    int h = blockIdx.y;

    for (int idx = tid; idx < NREL * 16; idx += 256) {
        int j = idx >> 4;
        int d0 = (idx & 15) << 2;
        float4 rv = *(const float4*)(rel + (size_t)j * HD + d0);
        rel_s[j * 65 + d0 + 0] = rv.x;
        rel_s[j * 65 + d0 + 1] = rv.y;
        rel_s[j * 65 + d0 + 2] = rv.z;
        rel_s[j * 65 + d0 + 3] = rv.w;
    }
    for (int idx = tid; idx < 64 * 16; idx += 256) {
        int r = idx >> 4;
        int d0 = (idx & 15) << 2;
        *(float4*)&Qs[r * HD + d0] =
            *(const float4*)(qb + (size_t)(row0 + r) * DM + h * HD + d0);
    }
    __syncthreads();

    for (int j = tid; j < NREL; j += 256) {
        for (int r0 = 0; r0 < 64; r0 += 8) {
            float acc8[8] = {};
            for (int d = 0; d < HD; d++) {
                float rv = rel_s[j * 65 + d];
                #pragma unroll
                for (int t = 0; t < 8; t++)
                    acc8[t] = fmaf(Qs[(r0 + t) * HD + d], rv, acc8[t]);
            }
            #pragma unroll
            for (int t = 0; t < 8; t++)
                qr[((size_t)h * MROWS + row0 + r0 + t) * NREL + j] = acc8[t];
        }
    }
}

// ===========================================================================
// attn_score
// ===========================================================================
#define SCORE_SMEM (2 * 64 * 128 * (int)sizeof(float))
__global__ __launch_bounds__(256)
void attn_score(const float* __restrict__ qb, const float* __restrict__ kb,
                const float* __restrict__ qr, float* __restrict__ sc)
{
    extern __shared__ float sm[];
    float* As = sm;
    float* Bs = sm + 64*128;

    int tid = threadIdx.x;
    int k0 = blockIdx.x * 128;
    int q0 = blockIdx.y * 128;
    int bh = blockIdx.z;
    int b = bh >> 3;
    int h = bh & 7;
    int bs = b * SEQ;

    #pragma unroll
    for (int i = 0; i < 8; i++) {
        int idx = tid + i * 256;
        int r  = idx & 127;
        int d0 = (idx >> 7) << 2;
        float4 av = *(const float4*)(qb + (size_t)(bs + q0 + r) * DM + h * HD + d0);
        As[(d0 + 0) * 128 + r] = av.x;
        As[(d0 + 1) * 128 + r] = av.y;
        As[(d0 + 2) * 128 + r] = av.z;
        As[(d0 + 3) * 128 + r] = av.w;
        float4 bv = *(const float4*)(kb + (size_t)(bs + k0 + r) * DM + h * HD + d0);
        Bs[(d0 + 0) * 128 + r] = bv.x;
        Bs[(d0 + 1) * 128 + r] = bv.y;
        Bs[(d0 + 2) * 128 + r] = bv.z;
        Bs[(d0 + 3) * 128 + r] = bv.w;
    }
    __syncthreads();

    int tx = tid & 15;
    int ty = tid >> 4;
    float acc[8][8] = {};
    #pragma unroll 8
    for (int kk = 0; kk < 64; kk++) {
        float4 a0 = *(const float4*)&As[kk * 128 + ty * 8];
        float4 a1 = *(const float4*)&As[kk * 128 + ty * 8 + 4];
        float4 b0 = *(const float4*)&Bs[kk * 128 + tx * 8];
        float4 b1 = *(const float4*)&Bs[kk * 128 + tx * 8 + 4];
        float av[8] = {a0.x, a0.y, a0.z, a0.w, a1.x, a1.y, a1.z, a1.w};
        float bv[8] = {b0.x, b0.y, b0.z, b0.w, b1.x, b1.y, b1.z, b1.w};
        #pragma unroll
        for (int i = 0; i < 8; i++)
            #pragma unroll
            for (int j = 0; j < 8; j++)
                acc[i][j] = fmaf(av[i], bv[j], acc[i][j]);
    }

    #pragma unroll
    for (int i = 0; i < 8; i++) {
        int qg = q0 + ty * 8 + i;
        const float* qrow = qr + ((size_t)h * MROWS + bs + qg) * NREL;
        float o[8];
        #pragma unroll
        for (int j = 0; j < 8; j++) {
            int kg = k0 + tx * 8 + j;
            int di = kg - qg;
            di = min(max(di, -MAXREL), MAXREL) + MAXREL;
            o[j] = acc[i][j] * 0.125f + qrow[di];
        }
        float* op = sc + ((size_t)bh * SEQ + qg) * SEQ + k0 + tx * 8;
        *(float4*)op       = make_float4(o[0], o[1], o[2], o[3]);
        *(float4*)(op + 4) = make_float4(o[4], o[5], o[6], o[7]);
    }
}

// ===========================================================================
// softmax rows
// ===========================================================================
__global__ __launch_bounds__(128)
void softmax_rows(float* __restrict__ sc)
{
    __shared__ float ws[4];
    int tid = threadIdx.x;
    int lane = tid & 31, w = tid >> 5;
    float* row = sc + (size_t)blockIdx.x * SEQ;
    float4 v = ((float4*)row)[tid];

    float m = fmaxf(fmaxf(v.x, v.y), fmaxf(v.z, v.w));
    #pragma unroll
    for (int o = 16; o > 0; o >>= 1) m = fmaxf(m, __shfl_xor_sync(0xffffffffu, m, o));
    if (lane == 0) ws[w] = m;
    __syncthreads();
    m = fmaxf(fmaxf(ws[0], ws[1]), fmaxf(ws[2], ws[3]));
    __syncthreads();

    v.x = __expf(v.x - m); v.y = __expf(v.y - m);
    v.z = __expf(v.z - m); v.w = __expf(v.w - m);
    float s = v.x + v.y + v.z + v.w;
    #pragma unroll
    for (int o = 16; o > 0; o >>= 1) s += __shfl_xor_sync(0xffffffffu, s, o);
    if (lane == 0) ws[w] = s;
    __syncthreads();
    s = ws[0] + ws[1] + ws[2] + ws[3];
    float inv = 1.0f / s;
    v.x *= inv; v.y *= inv; v.z *= inv; v.w *= inv;
    ((float4*)row)[tid] = v;
}

// ===========================================================================
// attn_pv
// ===========================================================================
__global__ __launch_bounds__(256)
void attn_pv(const float* __restrict__ p, const float* __restrict__ vb,
             float* __restrict__ ctx)
{
    __shared__ float Ps[64 * 128];
    __shared__ float Vs[64 * 64];

    int tid = threadIdx.x;
    int q0 = blockIdx.x * 128;
    int bh = blockIdx.y;
    int b = bh >> 3;
    int h = bh & 7;
    int bs = b * SEQ;

    int tx = tid & 15;
    int ty = tid >> 4;
    float acc[8][4] = {};

    for (int kc = 0; kc < SEQ; kc += 64) {
        #pragma unroll
        for (int i = 0; i < 8; i++) {
            int idx = tid + i * 256;
            int r  = idx & 127;
            int kk0 = (idx >> 7) << 2;
            float4 pv = *(const float4*)(p + ((size_t)bh * SEQ + q0 + r) * SEQ + kc + kk0);
            Ps[(kk0 + 0) * 128 + r] = pv.x;
            Ps[(kk0 + 1) * 128 + r] = pv.y;
            Ps[(kk0 + 2) * 128 + r] = pv.z;
            Ps[(kk0 + 3) * 128 + r] = pv.w;
        }
        #pragma unroll
        for (int i = 0; i < 4; i++) {
            int idx = tid + i * 256;
            int kk = idx >> 4;
            int d0 = (idx & 15) << 2;
            *(float4*)&Vs[kk * 64 + d0] =
                *(const float4*)(vb + (size_t)(bs + kc + kk) * DM + h * HD + d0);
        }
        __syncthreads();

        #pragma unroll 8
        for (int kk = 0; kk < 64; kk++) {
            float4 a0 = *(const float4*)&Ps[kk * 128 + ty * 8];
            float4 a1 = *(const float4*)&Ps[kk * 128 + ty * 8 + 4];
            float4 bv = *(const float4*)&Vs[kk * 64 + tx * 4];
            float av[8] = {a0.x, a0.y, a0.z, a0.w, a1.x, a1.y, a1.z, a1.w};
            #pragma unroll
            for (int i = 0; i < 8; i++) {
                acc[i][0] = fmaf(av[i], bv.x, acc[i][0]);
                acc[i][1] = fmaf(av[i], bv.y, acc[i][1]);
                acc[i][2] = fmaf(av[i], bv.z, acc[i][2]);
                acc[i][3] = fmaf(av[i], bv.w, acc[i][3]);
            }
        }
        __syncthreads();
    }

    #pragma unroll
    for (int i = 0; i < 8; i++) {
        *(float4*)(ctx + (size_t)(bs + q0 + ty * 8 + i) * DM + h * HD + tx * 4) =
            make_float4(acc[i][0], acc[i][1], acc[i][2], acc[i][3]);
    }
}

// ===========================================================================
// residual add + LayerNorm
// ===========================================================================
__device__ __forceinline__ float block_sum128(float v, float* ws)
{
    #pragma unroll
    for (int o = 16; o > 0; o >>= 1) v += __shfl_xor_sync(0xffffffffu, v, o);
    int lane = threadIdx.x & 31, w = threadIdx.x >> 5;
    if (lane == 0) ws[w] = v;
    __syncthreads();
    v = ws[0] + ws[1] + ws[2] + ws[3];
    __syncthreads();
    return v;
}

__global__ __launch_bounds__(128)
void add_ln_kernel(const float* __restrict__ x, const float* __restrict__ add,
                   const float* __restrict__ g, const float* __restrict__ bta,
                   float* __restrict__ out)
{
    __shared__ float ws[4];
    int row = blockIdx.x;
    int tid = threadIdx.x;
    float4 v = ((const float4*)(x + (size_t)row * DM))[tid];
    if (add != nullptr) {
        float4 a = ((const float4*)(add + (size_t)row * DM))[tid];
        v.x += a.x; v.y += a.y; v.z += a.z; v.w += a.w;
    }
    float s = block_sum128(v.x + v.y + v.z + v.w, ws);
    float mean = s * (1.0f / DM);
    float dx = v.x - mean, dy = v.y - mean, dz = v.z - mean, dw = v.w - mean;
    float sq = block_sum128(dx*dx + dy*dy + dz*dz + dw*dw, ws);
    float rstd = rsqrtf(sq * (1.0f / DM) + 1e-5f);
    float4 gg = ((const float4*)g)[tid];
    float4 bb = ((const float4*)bta)[tid];
    float4 o;
    o.x = dx * rstd * gg.x + bb.x;
    o.y = dy * rstd * gg.y + bb.y;
    o.z = dz * rstd * gg.z + bb.z;
    o.w = dw * rstd * gg.w + bb.w;
    ((float4*)(out + (size_t)row * DM))[tid] = o;
}

// ===========================================================================
// head stage 2
// ===========================================================================
__global__ __launch_bounds__(256)
void head2_kernel(const float* __restrict__ tmp, const float* __restrict__ p2_w,
                  const float* __restrict__ p2_b, float* __restrict__ out)
{
    int wid = threadIdx.x >> 5;
    int lane = threadIdx.x & 31;
    int row = blockIdx.x * 8 + wid;
    const float* tr = tmp + (size_t)row * 256;
    float acc = 0.f;
    #pragma unroll
    for (int j = lane; j < 256; j += 32) acc = fmaf(tr[j], p2_w[j], acc);
    #pragma unroll
    for (int o = 16; o > 0; o >>= 1) acc += __shfl_xor_sync(0xffffffffu, acc, o);
    if (lane == 0) out[row] = acc + p2_b[0];
}

// ===========================================================================
// Launcher
// ===========================================================================
extern "C" void kernel_launch(void* const* d_in, const int* in_sizes, int n_in,
                              void* d_out, int out_size)
{
    const float* x     = (const float*)d_in[0];
    const float* in_w  = (const float*)d_in[1];
    const float* in_b  = (const float*)d_in[2];
    const float* Wq    = (const float*)d_in[3];
    const float* Wk    = (const float*)d_in[4];
    const float* Wv    = (const float*)d_in[5];
    const float* Wo    = (const float*)d_in[6];
    const float* bo    = (const float*)d_in[7];
    const float* relE  = (const float*)d_in[8];
    const float* w1    = (const float*)d_in[9];
    const float* b1    = (const float*)d_in[10];
    const float* w2    = (const float*)d_in[11];
    const float* b2    = (const float*)d_in[12];
    const float* ln1_g = (const float*)d_in[13];
    const float* ln1_b = (const float*)d_in[14];
    const float* ln2_g = (const float*)d_in[15];
    const float* ln2_b = (const float*)d_in[16];
    const float* on_g  = (const float*)d_in[17];
    const float* on_b  = (const float*)d_in[18];
    const float* p1_w  = (const float*)d_in[19];
    const float* p1_b  = (const float*)d_in[20];
    const float* p2_w  = (const float*)d_in[21];
    const float* p2_b  = (const float*)d_in[22];
    float* out = (float*)d_out;

    float *h, *q, *k, *v, *ctx, *tmp, *qr, *sc;
    cudaGetSymbolAddress((void**)&h,   g_h);
    cudaGetSymbolAddress((void**)&q,   g_q);
    cudaGetSymbolAddress((void**)&k,   g_k);
    cudaGetSymbolAddress((void**)&v,   g_v);
    cudaGetSymbolAddress((void**)&ctx, g_ctx);
    cudaGetSymbolAddress((void**)&tmp, g_tmp);
    cudaGetSymbolAddress((void**)&qr,  g_qr);
    cudaGetSymbolAddress((void**)&sc,  g_sc);

    static bool attr_set = false;
    if (!attr_set) {
        cudaFuncSetAttribute(qrel_kernel, cudaFuncAttributeMaxDynamicSharedMemorySize, QREL_SMEM);
        cudaFuncSetAttribute(attn_score, cudaFuncAttributeMaxDynamicSharedMemorySize, SCORE_SMEM);
        attr_set = true;
    }

    embed_kernel<<<(MROWS * DM) / 256, 256>>>(x, in_w, in_b, h);

    dim3 gD(DM / 128, MROWS / 128);
    dim3 gF(FFD / 128, MROWS / 128);
    dim3 gP(256 / 128, MROWS / 128);
    dim3 gQR(MROWS / 64, NH);
    dim3 gS(SEQ / 128, SEQ / 128, BATCH * NH);
    dim3 gPV(SEQ / 128, BATCH * NH);

    for (int l = 0; l < NLAYER; l++) {
        const float* wq  = Wq + (size_t)l * DM * DM;
        const float* wk  = Wk + (size_t)l * DM * DM;
        const float* wv  = Wv + (size_t)l * DM * DM;
        const float* wo  = Wo + (size_t)l * DM * DM;
        const float* bol = bo + (size_t)l * DM;
        const float* rl  = relE + (size_t)l * NREL * HD;
        const float* w1l = w1 + (size_t)l * DM * FFD;
        const float* b1l = b1 + (size_t)l * FFD;
        const float* w2l = w2 + (size_t)l * FFD * DM;
        const float* b2l = b2 + (size_t)l * DM;

        tgemm<false, false><<<gD, 256>>>(h, wq, nullptr, q, DM, DM);
        tgemm<false, false><<<gD, 256>>>(h, wk, nullptr, k, DM, DM);
        tgemm<false, false><<<gD, 256>>>(h, wv, nullptr, v, DM, DM);

        qrel_kernel<<<gQR, 256, QREL_SMEM>>>(q, rl, qr);
        attn_score<<<gS, 256, SCORE_SMEM>>>(q, k, qr, sc);
        softmax_rows<<<BATCH * NH * SEQ, 128>>>(sc);
        attn_pv<<<gPV, 256>>>(sc, v, ctx);

        tgemm<true, false><<<gD, 256>>>(ctx, wo, bol, q, DM, DM);
        add_ln_kernel<<<MROWS, 128>>>(h, q, ln1_g + (size_t)l * DM, ln1_b + (size_t)l * DM, h);

        tgemm<true, true><<<gF, 256>>>(h, w1l, b1l, tmp, FFD, DM);
        tgemm<true, false><<<gD, 256>>>(tmp, w2l, b2l, q, DM, FFD);
        add_ln_kernel<<<MROWS, 128>>>(h, q, ln2_g + (size_t)l * DM, ln2_b + (size_t)l * DM, h);
    }

    add_ln_kernel<<<MROWS, 128>>>(h, nullptr, on_g, on_b, q);
    sgemm128<true, true><<<gP, 256>>>(q, p1_w, p1_b, tmp, MROWS, 256, DM);
    head2_kernel<<<MROWS / 8, 256>>>(tmp, p2_w, p2_b, out);
}

// round 11
// speedup vs baseline: 6.7149x; 1.1668x over previous
#include <cuda_runtime.h>
#include <cuda_bf16.h>
#include <math.h>
#include <stdint.h>

// Problem constants  (L, D, H, FF, I, MAXREL = 6, 512, 8, 2048, 50, 128)
#define BATCH 16
#define SEQ   512
#define DM    512
#define NH    8
#define HD    64
#define FFD   2048
#define NLAYER 6
#define MAXREL 128
#define NREL  257
#define MROWS (BATCH*SEQ)  // 8192

// Scratch (no allocation allowed)
__device__ float g_h[MROWS*DM];
__device__ float g_q[MROWS*DM];
__device__ float g_k[MROWS*DM];
__device__ float g_v[MROWS*DM];
__device__ float g_ctx[MROWS*DM];
__device__ float g_tmp[MROWS*FFD];
__device__ float g_qr[(size_t)NH*MROWS*NREL];
__device__ float g_sc[(size_t)BATCH*NH*SEQ*SEQ];

// TF32 round-to-nearest -> bits
__device__ __forceinline__ uint32_t tf32u(float x)
{
    uint32_t u;
    asm("cvt.rna.tf32.f32 %0, %1;" : "=r"(u) : "f"(x));
    return u;
}

// m16n8k8 tf32 mma (row.col), fp32 accumulate
__device__ __forceinline__ void mma_tf32(float* c, const uint32_t* a, const uint32_t* b)
{
    asm volatile(
        "mma.sync.aligned.m16n8k8.row.col.f32.tf32.tf32.f32 "
        "{%0,%1,%2,%3}, {%4,%5,%6,%7}, {%8,%9}, {%0,%1,%2,%3};"
        : "+f"(c[0]), "+f"(c[1]), "+f"(c[2]), "+f"(c[3])
        : "r"(a[0]), "r"(a[1]), "r"(a[2]), "r"(a[3]), "r"(b[0]), "r"(b[1]));
}

__device__ __forceinline__ uint32_t smem_u32(const void* p) {
    uint32_t a;
    asm("{ .reg .u64 t; cvta.to.shared.u64 t, %1; cvt.u32.u64 %0, t; }" : "=r"(a) : "l"(p));
    return a;
}
#define CP_ASYNC16(dst, src) \
    asm volatile("cp.async.cg.shared.global [%0], [%1], 16;" :: "r"(dst), "l"(src))
#define CP_COMMIT() asm volatile("cp.async.commit_group;" ::: "memory")
#define CP_WAIT1()  asm volatile("cp.async.wait_group 1;" ::: "memory")

// ===========================================================================
// tgemm: TF32 mma.sync GEMM, cp.async double-buffered (unchanged from R10)
// ===========================================================================
#define APAD 20
#define BPAD 136
#define A_STAGE (128 * APAD)
#define B_STAGE (16 * BPAD)

template <bool BIAS, bool RELU>
__global__ __launch_bounds__(256, 2)
void tgemm(const float* __restrict__ A, const float* __restrict__ B,
           const float* __restrict__ bias, float* __restrict__ C,
           int N, int K)
{
    __shared__ float As[2][A_STAGE];
    __shared__ float Bs[2][B_STAGE];

    int tid = threadIdx.x;
    int warp = tid >> 5;
    int lane = tid & 31;
    int row0 = blockIdx.y * 128;
    int col0 = blockIdx.x * 128;

    int wm = (warp & 1) * 64;
    int wn = (warp >> 1) * 32;
    int gid = lane >> 2;
    int tig = lane & 3;

    uint32_t asb[2] = { smem_u32(As[0]), smem_u32(As[1]) };
    uint32_t bsb[2] = { smem_u32(Bs[0]), smem_u32(Bs[1]) };

    auto prefetch = [&](int c, int s) {
        int k0 = c << 4;
        #pragma unroll
        for (int i = 0; i < 2; i++) {
            int ch = tid + i * 256;
            int ar = ch >> 2;
            int fc = (ch & 3) << 2;
            CP_ASYNC16(asb[s] + (ar * APAD + fc) * 4,
                       A + (size_t)(row0 + ar) * K + k0 + fc);
            int kk = ch >> 5;
            int nc = (ch & 31) << 2;
            CP_ASYNC16(bsb[s] + (kk * BPAD + nc) * 4,
                       B + (size_t)(k0 + kk) * N + col0 + nc);
        }
    };

    float acc[4][4][4] = {};
    const int NC = K >> 4;

    prefetch(0, 0);
    CP_COMMIT();

    for (int c = 0; c < NC; c++) {
        if (c + 1 < NC) prefetch(c + 1, (c + 1) & 1);
        CP_COMMIT();
        CP_WAIT1();
        __syncthreads();

        const float* as = As[c & 1];
        const float* bs = Bs[c & 1];
        #pragma unroll
        for (int ks = 0; ks < 16; ks += 8) {
            uint32_t af[4][4];
            uint32_t bf[4][2];
            #pragma unroll
            for (int mt = 0; mt < 4; mt++) {
                int m = wm + mt * 16 + gid;
                af[mt][0] = tf32u(as[m * APAD + ks + tig]);
                af[mt][1] = tf32u(as[(m + 8) * APAD + ks + tig]);
                af[mt][2] = tf32u(as[m * APAD + ks + tig + 4]);
                af[mt][3] = tf32u(as[(m + 8) * APAD + ks + tig + 4]);
            }
            #pragma unroll
            for (int nt = 0; nt < 4; nt++) {
                int n = wn + nt * 8 + gid;
                bf[nt][0] = tf32u(bs[(ks + tig) * BPAD + n]);
                bf[nt][1] = tf32u(bs[(ks + tig + 4) * BPAD + n]);
            }
            #pragma unroll
            for (int mt = 0; mt < 4; mt++)
                #pragma unroll
                for (int nt = 0; nt < 4; nt++)
                    mma_tf32(acc[mt][nt], af[mt], bf[nt]);
        }
        __syncthreads();
    }

    #pragma unroll
    for (int mt = 0; mt < 4; mt++) {
        int ra = row0 + wm + mt * 16 + gid;
        int rb = ra + 8;
        #pragma unroll
        for (int nt = 0; nt < 4; nt++) {
            int col = col0 + wn + nt * 8 + tig * 2;
            float o0 = acc[mt][nt][0], o1 = acc[mt][nt][1];
            float o2 = acc[mt][nt][2], o3 = acc[mt][nt][3];
            if (BIAS) {
                float b0 = bias[col], b1 = bias[col + 1];
                o0 += b0; o1 += b1; o2 += b0; o3 += b1;
            }
            if (RELU) {
                o0 = fmaxf(o0, 0.f); o1 = fmaxf(o1, 0.f);
                o2 = fmaxf(o2, 0.f); o3 = fmaxf(o3, 0.f);
            }
            *(float2*)(C + (size_t)ra * N + col) = make_float2(o0, o1);
            *(float2*)(C + (size_t)rb * N + col) = make_float2(o2, o3);
        }
    }
}

// ===========================================================================
// Embedding
// ===========================================================================
__global__ void embed_kernel(const float* __restrict__ x,
                             const float* __restrict__ in_w,
                             const float* __restrict__ in_b,
                             float* __restrict__ h)
{
    int idx = blockIdx.x * 256 + threadIdx.x;
    if (idx >= MROWS * DM) return;
    int r = idx >> 9;
    int c = idx & 511;
    const float* xr = x + (size_t)r * 50;
    float acc = in_b[c];
    #pragma unroll 10
    for (int i = 0; i < 50; i++)
        acc = fmaf(xr[i], in_w[i * DM + c], acc);
    int s = r & (SEQ - 1);
    int two_i = c & ~1;
    float earg = (float)two_i * (-9.210340371976184f / 512.0f);
    float div32 = expf(earg);
    float argf = (float)s * div32;
    double pe = (c & 1) ? cos((double)argf) : sin((double)argf);
    h[idx] = acc + (float)pe;
}

// ===========================================================================
// SGEMM 128x128 (fp32) — head p1 gemm
// ===========================================================================
template <bool BIAS, bool RELU>
__global__ __launch_bounds__(256)
void sgemm128(const float* __restrict__ A, const float* __restrict__ Bm,
              const float* __restrict__ bias, float* __restrict__ C,
              int M, int N, int K)
{
    __shared__ float As2[16][128];
    __shared__ float Bs2[16][128];

    int tid = threadIdx.x;
    int row0 = blockIdx.y * 128;
    int col0 = blockIdx.x * 128;
    int tx = tid & 15;
    int ty = tid >> 4;

    float acc[8][8] = {};

    for (int k0 = 0; k0 < K; k0 += 16) {
        #pragma unroll
        for (int i = 0; i < 2; i++) {
            int f = tid + i * 256;
            int ar = f >> 2;
            int ac = (f & 3) << 2;
            float4 av = *(const float4*)(A + (size_t)(row0 + ar) * K + k0 + ac);
            As2[ac + 0][ar] = av.x;
            As2[ac + 1][ar] = av.y;
            As2[ac + 2][ar] = av.z;
            As2[ac + 3][ar] = av.w;
        }
        #pragma unroll
        for (int i = 0; i < 2; i++) {
            int f = tid + i * 256;
            int br = f >> 5;
            int bc = (f & 31) << 2;
            *(float4*)&Bs2[br][bc] = *(const float4*)(Bm + (size_t)(k0 + br) * N + col0 + bc);
        }
        __syncthreads();

        #pragma unroll
        for (int kk = 0; kk < 16; kk++) {
            float4 a0 = *(const float4*)&As2[kk][ty * 8];
            float4 a1 = *(const float4*)&As2[kk][ty * 8 + 4];
            float4 b0 = *(const float4*)&Bs2[kk][tx * 8];
            float4 b1 = *(const float4*)&Bs2[kk][tx * 8 + 4];
            float av[8] = {a0.x, a0.y, a0.z, a0.w, a1.x, a1.y, a1.z, a1.w};
            float bv[8] = {b0.x, b0.y, b0.z, b0.w, b1.x, b1.y, b1.z, b1.w};
            #pragma unroll
            for (int i = 0; i < 8; i++)
                #pragma unroll
                for (int j = 0; j < 8; j++)
                    acc[i][j] = fmaf(av[i], bv[j], acc[i][j]);
        }
        __syncthreads();
    }

    float bvv[8] = {};
    if (BIAS) {
        float4 c0 = *(const float4*)(bias + col0 + tx * 8);
        float4 c1 = *(const float4*)(bias + col0 + tx * 8 + 4);
        bvv[0]=c0.x; bvv[1]=c0.y; bvv[2]=c0.z; bvv[3]=c0.w;
        bvv[4]=c1.x; bvv[5]=c1.y; bvv[6]=c1.z; bvv[7]=c1.w;
    }
    #pragma unroll
    for (int i = 0; i < 8; i++) {
        int row = row0 + ty * 8 + i;
        float o[8];
        #pragma unroll
        for (int j = 0; j < 8; j++) {
            o[j] = acc[i][j];
            if (BIAS) o[j] += bvv[j];
            if (RELU) o[j] = fmaxf(o[j], 0.f);
        }
        *(float4*)(C + (size_t)row * N + col0 + tx * 8)     = make_float4(o[0],o[1],o[2],o[3]);
        *(float4*)(C + (size_t)row * N + col0 + tx * 8 + 4) = make_float4(o[4],o[5],o[6],o[7]);
    }
}

// ===========================================================================
// qrel
// ===========================================================================
#define REL_FLOATS  ((NREL * 65 + 15) & ~15)
#define QREL_SMEM   ((REL_FLOATS + 64 * 64) * (int)sizeof(float))
__global__ __launch_bounds__(256)
void qrel_kernel(const float* __restrict__ qb, const float* __restrict__ rel,
                 float* __restrict__ qr)
{
    extern __shared__ float sm[];
    float* rel_s = sm;
    float* Qs    = sm + REL_FLOATS;

    int tid = threadIdx.x;
    int row0 = blockIdx.x * 64;
    int h = blockIdx.y;

    for (int idx = tid; idx < NREL * 16; idx += 256) {
        int j = idx >> 4;
        int d0 = (idx & 15) << 2;
        float4 rv = *(const float4*)(rel + (size_t)j * HD + d0);
        rel_s[j * 65 + d0 + 0] = rv.x;
        rel_s[j * 65 + d0 + 1] = rv.y;
        rel_s[j * 65 + d0 + 2] = rv.z;
        rel_s[j * 65 + d0 + 3] = rv.w;
    }
    for (int idx = tid; idx < 64 * 16; idx += 256) {
        int r = idx >> 4;
        int d0 = (idx & 15) << 2;
        *(float4*)&Qs[r * HD + d0] =
            *(const float4*)(qb + (size_t)(row0 + r) * DM + h * HD + d0);
    }
    __syncthreads();

    for (int j = tid; j < NREL; j += 256) {
        for (int r0 = 0; r0 < 64; r0 += 8) {
            float acc8[8] = {};
            for (int d = 0; d < HD; d++) {
                float rv = rel_s[j * 65 + d];
                #pragma unroll
                for (int t = 0; t < 8; t++)
                    acc8[t] = fmaf(Qs[(r0 + t) * HD + d], rv, acc8[t]);
            }
            #pragma unroll
            for (int t = 0; t < 8; t++)
                qr[((size_t)h * MROWS + row0 + r0 + t) * NREL + j] = acc8[t];
        }
    }
}

// ===========================================================================
// attn_score (tf32 mma): S = QK/8 + rel-bias. 128x128 tile, K=64.
// Q,K tiles stored [row][68] (pad-68) -> conflict-free fragments.
// ===========================================================================
#define SPAD 68
#define SCORE_SMEM (2 * 128 * SPAD * (int)sizeof(float))
__global__ __launch_bounds__(256)
void attn_score(const float* __restrict__ qb, const float* __restrict__ kb,
                const float* __restrict__ qr, float* __restrict__ sc)
{
    extern __shared__ float sm[];
    float* Qs = sm;                // [128][68]
    float* Ks = sm + 128 * SPAD;   // [128][68]

    int tid = threadIdx.x;
    int k0 = blockIdx.x * 128;
    int q0 = blockIdx.y * 128;
    int bh = blockIdx.z;
    int b = bh >> 3;
    int h = bh & 7;
    int bs = b * SEQ;

    #pragma unroll
    for (int i = 0; i < 8; i++) {
        int ch = tid + i * 256;        // 0..2047
        int r  = ch >> 4;
        int d0 = (ch & 15) << 2;
        *(float4*)&Qs[r * SPAD + d0] =
            *(const float4*)(qb + (size_t)(bs + q0 + r) * DM + h * HD + d0);
        *(float4*)&Ks[r * SPAD + d0] =
            *(const float4*)(kb + (size_t)(bs + k0 + r) * DM + h * HD + d0);
    }
    __syncthreads();

    int warp = tid >> 5, lane = tid & 31;
    int gid = lane >> 2, tig = lane & 3;
    int wm = (warp & 1) * 64;
    int wn = (warp >> 1) * 32;

    float acc[4][4][4] = {};
    #pragma unroll
    for (int ks = 0; ks < 64; ks += 8) {
        uint32_t af[4][4], bf[4][2];
        #pragma unroll
        for (int mt = 0; mt < 4; mt++) {
            int m = wm + mt * 16 + gid;
            af[mt][0] = tf32u(Qs[m * SPAD + ks + tig]);
            af[mt][1] = tf32u(Qs[(m + 8) * SPAD + ks + tig]);
            af[mt][2] = tf32u(Qs[m * SPAD + ks + tig + 4]);
            af[mt][3] = tf32u(Qs[(m + 8) * SPAD + ks + tig + 4]);
        }
        #pragma unroll
        for (int nt = 0; nt < 4; nt++) {
            int n = wn + nt * 8 + gid;
            bf[nt][0] = tf32u(Ks[n * SPAD + ks + tig]);
            bf[nt][1] = tf32u(Ks[n * SPAD + ks + tig + 4]);
        }
        #pragma unroll
        for (int mt = 0; mt < 4; mt++)
            #pragma unroll
            for (int nt = 0; nt < 4; nt++)
                mma_tf32(acc[mt][nt], af[mt], bf[nt]);
    }

    // epilogue: scale + rel bias
    #pragma unroll
    for (int mt = 0; mt < 4; mt++) {
        int ra = q0 + wm + mt * 16 + gid;
        int rb = ra + 8;
        const float* qra = qr + ((size_t)h * MROWS + bs + ra) * NREL;
        const float* qrb = qr + ((size_t)h * MROWS + bs + rb) * NREL;
        #pragma unroll
        for (int nt = 0; nt < 4; nt++) {
            int kg = k0 + wn + nt * 8 + tig * 2;
            int d0a = min(max(kg     - ra, -MAXREL), MAXREL) + MAXREL;
            int d1a = min(max(kg + 1 - ra, -MAXREL), MAXREL) + MAXREL;
            int d0b = min(max(kg     - rb, -MAXREL), MAXREL) + MAXREL;
            int d1b = min(max(kg + 1 - rb, -MAXREL), MAXREL) + MAXREL;
            float o0 = acc[mt][nt][0] * 0.125f + qra[d0a];
            float o1 = acc[mt][nt][1] * 0.125f + qra[d1a];
            float o2 = acc[mt][nt][2] * 0.125f + qrb[d0b];
            float o3 = acc[mt][nt][3] * 0.125f + qrb[d1b];
            *(float2*)(sc + ((size_t)bh * SEQ + ra) * SEQ + kg) = make_float2(o0, o1);
            *(float2*)(sc + ((size_t)bh * SEQ + rb) * SEQ + kg) = make_float2(o2, o3);
        }
    }
}

// ===========================================================================
// softmax rows
// ===========================================================================
__global__ __launch_bounds__(128)
void softmax_rows(float* __restrict__ sc)
{
    __shared__ float ws[4];
    int tid = threadIdx.x;
    int lane = tid & 31, w = tid >> 5;
    float* row = sc + (size_t)blockIdx.x * SEQ;
    float4 v = ((float4*)row)[tid];

    float m = fmaxf(fmaxf(v.x, v.y), fmaxf(v.z, v.w));
    #pragma unroll
    for (int o = 16; o > 0; o >>= 1) m = fmaxf(m, __shfl_xor_sync(0xffffffffu, m, o));
    if (lane == 0) ws[w] = m;
    __syncthreads();
    m = fmaxf(fmaxf(ws[0], ws[1]), fmaxf(ws[2], ws[3]));
    __syncthreads();

    v.x = __expf(v.x - m); v.y = __expf(v.y - m);
    v.z = __expf(v.z - m); v.w = __expf(v.w - m);
    float s = v.x + v.y + v.z + v.w;
    #pragma unroll
    for (int o = 16; o > 0; o >>= 1) s += __shfl_xor_sync(0xffffffffu, s, o);
    if (lane == 0) ws[w] = s;
    __syncthreads();
    s = ws[0] + ws[1] + ws[2] + ws[3];
    float inv = 1.0f / s;
    v.x *= inv; v.y *= inv; v.z *= inv; v.w *= inv;
    ((float4*)row)[tid] = v;
}

// ===========================================================================
// attn_pv (tf32 mma, cp.async double-buffered K-chunks of 64):
// ctx[128,64] = P[128,512] @ V[512,64]. P stage [q][68], V stage [key][68].
// ===========================================================================
#define PV_P (128 * SPAD)
#define PV_V (64 * SPAD)
#define PV_STAGE (PV_P + PV_V)
#define PV_SMEM (2 * PV_STAGE * (int)sizeof(float))
__global__ __launch_bounds__(256)
void attn_pv(const float* __restrict__ p, const float* __restrict__ vb,
             float* __restrict__ ctx)
{
    extern __shared__ float sm[];
    uint32_t base = smem_u32(sm);

    int tid = threadIdx.x;
    int q0 = blockIdx.x * 128;
    int bh = blockIdx.y;
    int b = bh >> 3;
    int h = bh & 7;
    int bs = b * SEQ;

    auto prefetch = [&](int c, int s) {
        int kc = c << 6;
        uint32_t stage = base + (uint32_t)(s * PV_STAGE) * 4;
        #pragma unroll
        for (int i = 0; i < 8; i++) {
            int ch = tid + i * 256;        // 0..2047
            int r  = ch >> 4;
            int c4 = (ch & 15) << 2;
            CP_ASYNC16(stage + (r * SPAD + c4) * 4,
                       p + ((size_t)bh * SEQ + q0 + r) * SEQ + kc + c4);
        }
        #pragma unroll
        for (int i = 0; i < 4; i++) {
            int ch = tid + i * 256;        // 0..1023
            int kk = ch >> 4;
            int d0 = (ch & 15) << 2;
            CP_ASYNC16(stage + (PV_P + kk * SPAD + d0) * 4,
                       vb + (size_t)(bs + kc + kk) * DM + h * HD + d0);
        }
    };

    int warp = tid >> 5, lane = tid & 31;
    int gid = lane >> 2, tig = lane & 3;
    int wm = (warp & 3) * 32;
    int wn = (warp >> 2) * 32;

    float acc[2][4][4] = {};

    prefetch(0, 0);
    CP_COMMIT();

    for (int c = 0; c < 8; c++) {
        if (c + 1 < 8) prefetch(c + 1, (c + 1) & 1);
        CP_COMMIT();
        CP_WAIT1();
        __syncthreads();

        const float* Ps = sm + (c & 1) * PV_STAGE;
        const float* Vs = Ps + PV_P;
        #pragma unroll
        for (int ks = 0; ks < 64; ks += 8) {
            uint32_t af[2][4], bf[4][2];
            #pragma unroll
            for (int mt = 0; mt < 2; mt++) {
                int m = wm + mt * 16 + gid;
                af[mt][0] = tf32u(Ps[m * SPAD + ks + tig]);
                af[mt][1] = tf32u(Ps[(m + 8) * SPAD + ks + tig]);
                af[mt][2] = tf32u(Ps[m * SPAD + ks + tig + 4]);
                af[mt][3] = tf32u(Ps[(m + 8) * SPAD + ks + tig + 4]);
            }
            #pragma unroll
            for (int nt = 0; nt < 4; nt++) {
                int n = wn + nt * 8 + gid;
                bf[nt][0] = tf32u(Vs[(ks + tig) * SPAD + n]);
                bf[nt][1] = tf32u(Vs[(ks + tig + 4) * SPAD + n]);
            }
            #pragma unroll
            for (int mt = 0; mt < 2; mt++)
                #pragma unroll
                for (int nt = 0; nt < 4; nt++)
                    mma_tf32(acc[mt][nt], af[mt], bf[nt]);
        }
        __syncthreads();
    }

    #pragma unroll
    for (int mt = 0; mt < 2; mt++) {
        int ra = q0 + wm + mt * 16 + gid;
        int rb = ra + 8;
        #pragma unroll
        for (int nt = 0; nt < 4; nt++) {
            int col = h * HD + wn + nt * 8 + tig * 2;
            *(float2*)(ctx + (size_t)(bs + ra) * DM + col) =
                make_float2(acc[mt][nt][0], acc[mt][nt][1]);
            *(float2*)(ctx + (size_t)(bs + rb) * DM + col) =
                make_float2(acc[mt][nt][2], acc[mt][nt][3]);
        }
    }
}

// ===========================================================================
// residual add + LayerNorm
// ===========================================================================
__device__ __forceinline__ float block_sum128(float v, float* ws)
{
    #pragma unroll
    for (int o = 16; o > 0; o >>= 1) v += __shfl_xor_sync(0xffffffffu, v, o);
    int lane = threadIdx.x & 31, w = threadIdx.x >> 5;
    if (lane == 0) ws[w] = v;
    __syncthreads();
    v = ws[0] + ws[1] + ws[2] + ws[3];
    __syncthreads();
    return v;
}

__global__ __launch_bounds__(128)
void add_ln_kernel(const float* __restrict__ x, const float* __restrict__ add,
                   const float* __restrict__ g, const float* __restrict__ bta,
                   float* __restrict__ out)
{
    __shared__ float ws[4];
    int row = blockIdx.x;
    int tid = threadIdx.x;
    float4 v = ((const float4*)(x + (size_t)row * DM))[tid];
    if (add != nullptr) {
        float4 a = ((const float4*)(add + (size_t)row * DM))[tid];
        v.x += a.x; v.y += a.y; v.z += a.z; v.w += a.w;
    }
    float s = block_sum128(v.x + v.y + v.z + v.w, ws);
    float mean = s * (1.0f / DM);
    float dx = v.x - mean, dy = v.y - mean, dz = v.z - mean, dw = v.w - mean;
    float sq = block_sum128(dx*dx + dy*dy + dz*dz + dw*dw, ws);
    float rstd = rsqrtf(sq * (1.0f / DM) + 1e-5f);
    float4 gg = ((const float4*)g)[tid];
    float4 bb = ((const float4*)bta)[tid];
    float4 o;
    o.x = dx * rstd * gg.x + bb.x;
    o.y = dy * rstd * gg.y + bb.y;
    o.z = dz * rstd * gg.z + bb.z;
    o.w = dw * rstd * gg.w + bb.w;
    ((float4*)(out + (size_t)row * DM))[tid] = o;
}

// ===========================================================================
// head stage 2
// ===========================================================================
__global__ __launch_bounds__(256)
void head2_kernel(const float* __restrict__ tmp, const float* __restrict__ p2_w,
                  const float* __restrict__ p2_b, float* __restrict__ out)
{
    int wid = threadIdx.x >> 5;
    int lane = threadIdx.x & 31;
    int row = blockIdx.x * 8 + wid;
    const float* tr = tmp + (size_t)row * 256;
    float acc = 0.f;
    #pragma unroll
    for (int j = lane; j < 256; j += 32) acc = fmaf(tr[j], p2_w[j], acc);
    #pragma unroll
    for (int o = 16; o > 0; o >>= 1) acc += __shfl_xor_sync(0xffffffffu, acc, o);
    if (lane == 0) out[row] = acc + p2_b[0];
}

// ===========================================================================
// Launcher
// ===========================================================================
extern "C" void kernel_launch(void* const* d_in, const int* in_sizes, int n_in,
                              void* d_out, int out_size)
{
    const float* x     = (const float*)d_in[0];
    const float* in_w  = (const float*)d_in[1];
    const float* in_b  = (const float*)d_in[2];
    const float* Wq    = (const float*)d_in[3];
    const float* Wk    = (const float*)d_in[4];
    const float* Wv    = (const float*)d_in[5];
    const float* Wo    = (const float*)d_in[6];
    const float* bo    = (const float*)d_in[7];
    const float* relE  = (const float*)d_in[8];
    const float* w1    = (const float*)d_in[9];
    const float* b1    = (const float*)d_in[10];
    const float* w2    = (const float*)d_in[11];
    const float* b2    = (const float*)d_in[12];
    const float* ln1_g = (const float*)d_in[13];
    const float* ln1_b = (const float*)d_in[14];
    const float* ln2_g = (const float*)d_in[15];
    const float* ln2_b = (const float*)d_in[16];
    const float* on_g  = (const float*)d_in[17];
    const float* on_b  = (const float*)d_in[18];
    const float* p1_w  = (const float*)d_in[19];
    const float* p1_b  = (const float*)d_in[20];
    const float* p2_w  = (const float*)d_in[21];
    const float* p2_b  = (const float*)d_in[22];
    float* out = (float*)d_out;

    float *h, *q, *k, *v, *ctx, *tmp, *qr, *sc;
    cudaGetSymbolAddress((void**)&h,   g_h);
    cudaGetSymbolAddress((void**)&q,   g_q);
    cudaGetSymbolAddress((void**)&k,   g_k);
    cudaGetSymbolAddress((void**)&v,   g_v);
    cudaGetSymbolAddress((void**)&ctx, g_ctx);
    cudaGetSymbolAddress((void**)&tmp, g_tmp);
    cudaGetSymbolAddress((void**)&qr,  g_qr);
    cudaGetSymbolAddress((void**)&sc,  g_sc);

    static bool attr_set = false;
    if (!attr_set) {
        cudaFuncSetAttribute(qrel_kernel, cudaFuncAttributeMaxDynamicSharedMemorySize, QREL_SMEM);
        cudaFuncSetAttribute(attn_score, cudaFuncAttributeMaxDynamicSharedMemorySize, SCORE_SMEM);
        cudaFuncSetAttribute(attn_pv, cudaFuncAttributeMaxDynamicSharedMemorySize, PV_SMEM);
        attr_set = true;
    }

    embed_kernel<<<(MROWS * DM) / 256, 256>>>(x, in_w, in_b, h);

    dim3 gD(DM / 128, MROWS / 128);
    dim3 gF(FFD / 128, MROWS / 128);
    dim3 gP(256 / 128, MROWS / 128);
    dim3 gQR(MROWS / 64, NH);
    dim3 gS(SEQ / 128, SEQ / 128, BATCH * NH);
    dim3 gPV(SEQ / 128, BATCH * NH);

    for (int l = 0; l < NLAYER; l++) {
        const float* wq  = Wq + (size_t)l * DM * DM;
        const float* wk  = Wk + (size_t)l * DM * DM;
        const float* wv  = Wv + (size_t)l * DM * DM;
        const float* wo  = Wo + (size_t)l * DM * DM;
        const float* bol = bo + (size_t)l * DM;
        const float* rl  = relE + (size_t)l * NREL * HD;
        const float* w1l = w1 + (size_t)l * DM * FFD;
        const float* b1l = b1 + (size_t)l * FFD;
        const float* w2l = w2 + (size_t)l * FFD * DM;
        const float* b2l = b2 + (size_t)l * DM;

        tgemm<false, false><<<gD, 256>>>(h, wq, nullptr, q, DM, DM);
        tgemm<false, false><<<gD, 256>>>(h, wk, nullptr, k, DM, DM);
        tgemm<false, false><<<gD, 256>>>(h, wv, nullptr, v, DM, DM);

        qrel_kernel<<<gQR, 256, QREL_SMEM>>>(q, rl, qr);
        attn_score<<<gS, 256, SCORE_SMEM>>>(q, k, qr, sc);
        softmax_rows<<<BATCH * NH * SEQ, 128>>>(sc);
        attn_pv<<<gPV, 256, PV_SMEM>>>(sc, v, ctx);

        tgemm<true, false><<<gD, 256>>>(ctx, wo, bol, q, DM, DM);
        add_ln_kernel<<<MROWS, 128>>>(h, q, ln1_g + (size_t)l * DM, ln1_b + (size_t)l * DM, h);

        tgemm<true, true><<<gF, 256>>>(h, w1l, b1l, tmp, FFD, DM);
        tgemm<true, false><<<gD, 256>>>(tmp, w2l, b2l, q, DM, FFD);
        add_ln_kernel<<<MROWS, 128>>>(h, q, ln2_g + (size_t)l * DM, ln2_b + (size_t)l * DM, h);
    }

    add_ln_kernel<<<MROWS, 128>>>(h, nullptr, on_g, on_b, q);
    sgemm128<true, true><<<gP, 256>>>(q, p1_w, p1_b, tmp, MROWS, 256, DM);
    head2_kernel<<<MROWS / 8, 256>>>(tmp, p2_w, p2_b, out);
}

// round 13
// speedup vs baseline: 7.9680x; 1.1866x over previous
#include <cuda_runtime.h>
#include <cuda_bf16.h>
#include <math.h>
#include <stdint.h>

// Problem constants  (L, D, H, FF, I, MAXREL = 6, 512, 8, 2048, 50, 128)
#define BATCH 16
#define SEQ   512
#define DM    512
#define NH    8
#define HD    64
#define FFD   2048
#define NLAYER 6
#define MAXREL 128
#define NREL  257
#define MROWS (BATCH*SEQ)  // 8192

// Scratch (no allocation allowed)
__device__ float g_h[MROWS*DM];
__device__ float g_q[MROWS*DM];
__device__ float g_k[MROWS*DM];
__device__ float g_v[MROWS*DM];
__device__ float g_ctx[MROWS*DM];
__device__ float g_tmp[MROWS*FFD];
__device__ float g_qr[(size_t)NH*MROWS*NREL];
__device__ float g_sc[(size_t)BATCH*NH*SEQ*SEQ];

// TF32 round-to-nearest -> bits
__device__ __forceinline__ uint32_t tf32u(float x)
{
    uint32_t u;
    asm("cvt.rna.tf32.f32 %0, %1;" : "=r"(u) : "f"(x));
    return u;
}

// m16n8k8 tf32 mma (row.col), fp32 accumulate
__device__ __forceinline__ void mma_tf32(float* c, const uint32_t* a, const uint32_t* b)
{
    asm volatile(
        "mma.sync.aligned.m16n8k8.row.col.f32.tf32.tf32.f32 "
        "{%0,%1,%2,%3}, {%4,%5,%6,%7}, {%8,%9}, {%0,%1,%2,%3};"
        : "+f"(c[0]), "+f"(c[1]), "+f"(c[2]), "+f"(c[3])
        : "r"(a[0]), "r"(a[1]), "r"(a[2]), "r"(a[3]), "r"(b[0]), "r"(b[1]));
}

__device__ __forceinline__ uint32_t smem_u32(const void* p) {
    uint32_t a;
    asm("{ .reg .u64 t; cvta.to.shared.u64 t, %1; cvt.u32.u64 %0, t; }" : "=r"(a) : "l"(p));
    return a;
}
#define CP_ASYNC16(dst, src) \
    asm volatile("cp.async.cg.shared.global [%0], [%1], 16;" :: "r"(dst), "l"(src))
#define CP_COMMIT() asm volatile("cp.async.commit_group;" ::: "memory")
#define CP_WAIT1()  asm volatile("cp.async.wait_group 1;" ::: "memory")

// ===========================================================================
// tgemm body: 128x128 tile, BK=32, 128 threads, 4 warps of 64x64.
// A smem [m][36], B smem [k][136], 2 stages, cp.async.
// ===========================================================================
#define APAD 36
#define BPAD 136
#define A_ST (128 * APAD)            // 4608 floats
#define B_ST (32 * BPAD)             // 4352 floats
#define TG_STAGE (A_ST + B_ST)       // 8960 floats
#define TG_SMEM (2 * TG_STAGE * (int)sizeof(float))   // 71680 B

template <bool BIAS, bool RELU>
__device__ __forceinline__
void tgemm_body(const float* __restrict__ A, const float* __restrict__ B,
                const float* __restrict__ bias, float* __restrict__ C,
                int N, int K, int row0, int col0, float* sm)
{
    int tid = threadIdx.x;
    int warp = tid >> 5;
    int lane = tid & 31;
    int gid = lane >> 2;
    int tig = lane & 3;
    int wm = (warp & 1) * 64;
    int wn = (warp >> 1) * 64;

    uint32_t sb = smem_u32(sm);

    auto prefetch = [&](int c, int s) {
        int k0 = c << 5;
        uint32_t stage = sb + (uint32_t)(s * TG_STAGE) * 4;
        #pragma unroll
        for (int i = 0; i < 8; i++) {
            int ch = tid + i * 128;          // 0..1023
            int ar = ch >> 3;
            int fc = (ch & 7) << 2;
            CP_ASYNC16(stage + (ar * APAD + fc) * 4,
                       A + (size_t)(row0 + ar) * K + k0 + fc);
            int kk = ch >> 5;
            int nc = (ch & 31) << 2;
            CP_ASYNC16(stage + (A_ST + kk * BPAD + nc) * 4,
                       B + (size_t)(k0 + kk) * N + col0 + nc);
        }
    };

    float acc[4][8][4] = {};
    const int NC = K >> 5;

    prefetch(0, 0);
    CP_COMMIT();

    for (int c = 0; c < NC; c++) {
        if (c + 1 < NC) prefetch(c + 1, (c + 1) & 1);
        CP_COMMIT();
        CP_WAIT1();
        __syncthreads();

        const float* as = sm + (c & 1) * TG_STAGE;
        const float* bs = as + A_ST;
        #pragma unroll
        for (int ks = 0; ks < 32; ks += 8) {
            uint32_t af[4][4], bf[8][2];
            #pragma unroll
            for (int mt = 0; mt < 4; mt++) {
                int m = wm + mt * 16 + gid;
                af[mt][0] = tf32u(as[m * APAD + ks + tig]);
                af[mt][1] = tf32u(as[(m + 8) * APAD + ks + tig]);
                af[mt][2] = tf32u(as[m * APAD + ks + tig + 4]);
                af[mt][3] = tf32u(as[(m + 8) * APAD + ks + tig + 4]);
            }
            #pragma unroll
            for (int nt = 0; nt < 8; nt++) {
                int n = wn + nt * 8 + gid;
                bf[nt][0] = tf32u(bs[(ks + tig) * BPAD + n]);
                bf[nt][1] = tf32u(bs[(ks + tig + 4) * BPAD + n]);
            }
            #pragma unroll
            for (int mt = 0; mt < 4; mt++)
                #pragma unroll
                for (int nt = 0; nt < 8; nt++)
                    mma_tf32(acc[mt][nt], af[mt], bf[nt]);
        }
        __syncthreads();
    }

    #pragma unroll
    for (int mt = 0; mt < 4; mt++) {
        int ra = row0 + wm + mt * 16 + gid;
        int rb = ra + 8;
        #pragma unroll
        for (int nt = 0; nt < 8; nt++) {
            int col = col0 + wn + nt * 8 + tig * 2;
            float o0 = acc[mt][nt][0], o1 = acc[mt][nt][1];
            float o2 = acc[mt][nt][2], o3 = acc[mt][nt][3];
            if (BIAS) {
                float b0 = bias[col], b1 = bias[col + 1];
                o0 += b0; o1 += b1; o2 += b0; o3 += b1;
            }
            if (RELU) {
                o0 = fmaxf(o0, 0.f); o1 = fmaxf(o1, 0.f);
                o2 = fmaxf(o2, 0.f); o3 = fmaxf(o3, 0.f);
            }
            *(float2*)(C + (size_t)ra * N + col) = make_float2(o0, o1);
            *(float2*)(C + (size_t)rb * N + col) = make_float2(o2, o3);
        }
    }
}

template <bool BIAS, bool RELU>
__global__ __launch_bounds__(128, 2)
void tgemm(const float* __restrict__ A, const float* __restrict__ B,
           const float* __restrict__ bias, float* __restrict__ C,
           int N, int K)
{
    extern __shared__ float sm[];
    tgemm_body<BIAS, RELU>(A, B, bias, C, N, K, blockIdx.y * 128, blockIdx.x * 128, sm);
}

// Batched QKV: grid.z selects weight/output
__global__ __launch_bounds__(128, 2)
void tgemm_qkv(const float* __restrict__ A,
               const float* __restrict__ B0, const float* __restrict__ B1,
               const float* __restrict__ B2,
               float* __restrict__ C0, float* __restrict__ C1, float* __restrict__ C2)
{
    extern __shared__ float sm[];
    int z = blockIdx.z;
    const float* B = (z == 0) ? B0 : ((z == 1) ? B1 : B2);
    float* C = (z == 0) ? C0 : ((z == 1) ? C1 : C2);
    tgemm_body<false, false>(A, B, nullptr, C, DM, DM, blockIdx.y * 128, blockIdx.x * 128, sm);
}

// ===========================================================================
// Embedding
// ===========================================================================
__global__ void embed_kernel(const float* __restrict__ x,
                             const float* __restrict__ in_w,
                             const float* __restrict__ in_b,
                             float* __restrict__ h)
{
    int idx = blockIdx.x * 256 + threadIdx.x;
    if (idx >= MROWS * DM) return;
    int r = idx >> 9;
    int c = idx & 511;
    const float* xr = x + (size_t)r * 50;
    float acc = in_b[c];
    #pragma unroll 10
    for (int i = 0; i < 50; i++)
        acc = fmaf(xr[i], in_w[i * DM + c], acc);
    int s = r & (SEQ - 1);
    int two_i = c & ~1;
    float earg = (float)two_i * (-9.210340371976184f / 512.0f);
    float div32 = expf(earg);
    float argf = (float)s * div32;
    double pe = (c & 1) ? cos((double)argf) : sin((double)argf);
    h[idx] = acc + (float)pe;
}

// ===========================================================================
// SGEMM 128x128 (fp32) — head p1 gemm
// ===========================================================================
template <bool BIAS, bool RELU>
__global__ __launch_bounds__(256)
void sgemm128(const float* __restrict__ A, const float* __restrict__ Bm,
              const float* __restrict__ bias, float* __restrict__ C,
              int M, int N, int K)
{
    __shared__ float As2[16][128];
    __shared__ float Bs2[16][128];

    int tid = threadIdx.x;
    int row0 = blockIdx.y * 128;
    int col0 = blockIdx.x * 128;
    int tx = tid & 15;
    int ty = tid >> 4;

    float acc[8][8] = {};

    for (int k0 = 0; k0 < K; k0 += 16) {
        #pragma unroll
        for (int i = 0; i < 2; i++) {
            int f = tid + i * 256;
            int ar = f >> 2;
            int ac = (f & 3) << 2;
            float4 av = *(const float4*)(A + (size_t)(row0 + ar) * K + k0 + ac);
            As2[ac + 0][ar] = av.x;
            As2[ac + 1][ar] = av.y;
            As2[ac + 2][ar] = av.z;
            As2[ac + 3][ar] = av.w;
        }
        #pragma unroll
        for (int i = 0; i < 2; i++) {
            int f = tid + i * 256;
            int br = f >> 5;
            int bc = (f & 31) << 2;
            *(float4*)&Bs2[br][bc] = *(const float4*)(Bm + (size_t)(k0 + br) * N + col0 + bc);
        }
        __syncthreads();

        #pragma unroll
        for (int kk = 0; kk < 16; kk++) {
            float4 a0 = *(const float4*)&As2[kk][ty * 8];
            float4 a1 = *(const float4*)&As2[kk][ty * 8 + 4];
            float4 b0 = *(const float4*)&Bs2[kk][tx * 8];
            float4 b1 = *(const float4*)&Bs2[kk][tx * 8 + 4];
            float av[8] = {a0.x, a0.y, a0.z, a0.w, a1.x, a1.y, a1.z, a1.w};
            float bv[8] = {b0.x, b0.y, b0.z, b0.w, b1.x, b1.y, b1.z, b1.w};
            #pragma unroll
            for (int i = 0; i < 8; i++)
                #pragma unroll
                for (int j = 0; j < 8; j++)
                    acc[i][j] = fmaf(av[i], bv[j], acc[i][j]);
        }
        __syncthreads();
    }

    float bvv[8] = {};
    if (BIAS) {
        float4 c0 = *(const float4*)(bias + col0 + tx * 8);
        float4 c1 = *(const float4*)(bias + col0 + tx * 8 + 4);
        bvv[0]=c0.x; bvv[1]=c0.y; bvv[2]=c0.z; bvv[3]=c0.w;
        bvv[4]=c1.x; bvv[5]=c1.y; bvv[6]=c1.z; bvv[7]=c1.w;
    }
    #pragma unroll
    for (int i = 0; i < 8; i++) {
        int row = row0 + ty * 8 + i;
        float o[8];
        #pragma unroll
        for (int j = 0; j < 8; j++) {
            o[j] = acc[i][j];
            if (BIAS) o[j] += bvv[j];
            if (RELU) o[j] = fmaxf(o[j], 0.f);
        }
        *(float4*)(C + (size_t)row * N + col0 + tx * 8)     = make_float4(o[0],o[1],o[2],o[3]);
        *(float4*)(C + (size_t)row * N + col0 + tx * 8 + 4) = make_float4(o[4],o[5],o[6],o[7]);
    }
}

// ===========================================================================
// qrel via tf32 mma: QR[h][row][j] = q[row,h*64:] . rel[j], j in [0,256)
// grid (MROWS/128, 2, NH). NOTE: qr row stride 257 is ODD -> scalar stores.
// ===========================================================================
#define SPAD 68
#define QRELM_SMEM (2 * 128 * SPAD * (int)sizeof(float))
__global__ __launch_bounds__(256)
void qrel_mma(const float* __restrict__ qb, const float* __restrict__ rel,
              float* __restrict__ qr)
{
    extern __shared__ float sm[];
    float* Qs = sm;                // [128][68]
    float* Rs = sm + 128 * SPAD;   // [128][68]

    int tid = threadIdx.x;
    int row0 = blockIdx.x * 128;
    int j0 = blockIdx.y * 128;
    int h = blockIdx.z;

    #pragma unroll
    for (int i = 0; i < 8; i++) {
        int ch = tid + i * 256;
        int r  = ch >> 4;
        int d0 = (ch & 15) << 2;
        *(float4*)&Qs[r * SPAD + d0] =
            *(const float4*)(qb + (size_t)(row0 + r) * DM + h * HD + d0);
        *(float4*)&Rs[r * SPAD + d0] =
            *(const float4*)(rel + (size_t)(j0 + r) * HD + d0);
    }
    __syncthreads();

    int warp = tid >> 5, lane = tid & 31;
    int gid = lane >> 2, tig = lane & 3;
    int wm = (warp & 1) * 64;
    int wn = (warp >> 1) * 32;

    float acc[4][4][4] = {};
    #pragma unroll
    for (int ks = 0; ks < 64; ks += 8) {
        uint32_t af[4][4], bf[4][2];
        #pragma unroll
        for (int mt = 0; mt < 4; mt++) {
            int m = wm + mt * 16 + gid;
            af[mt][0] = tf32u(Qs[m * SPAD + ks + tig]);
            af[mt][1] = tf32u(Qs[(m + 8) * SPAD + ks + tig]);
            af[mt][2] = tf32u(Qs[m * SPAD + ks + tig + 4]);
            af[mt][3] = tf32u(Qs[(m + 8) * SPAD + ks + tig + 4]);
        }
        #pragma unroll
        for (int nt = 0; nt < 4; nt++) {
            int n = wn + nt * 8 + gid;
            bf[nt][0] = tf32u(Rs[n * SPAD + ks + tig]);
            bf[nt][1] = tf32u(Rs[n * SPAD + ks + tig + 4]);
        }
        #pragma unroll
        for (int mt = 0; mt < 4; mt++)
            #pragma unroll
            for (int nt = 0; nt < 4; nt++)
                mma_tf32(acc[mt][nt], af[mt], bf[nt]);
    }

    // scalar stores: qr row stride NREL=257 (odd) breaks float2 alignment
    #pragma unroll
    for (int mt = 0; mt < 4; mt++) {
        int ra = row0 + wm + mt * 16 + gid;
        int rb = ra + 8;
        float* pa = qr + ((size_t)h * MROWS + ra) * NREL;
        float* pb = qr + ((size_t)h * MROWS + rb) * NREL;
        #pragma unroll
        for (int nt = 0; nt < 4; nt++) {
            int j = j0 + wn + nt * 8 + tig * 2;
            pa[j]     = acc[mt][nt][0];
            pa[j + 1] = acc[mt][nt][1];
            pb[j]     = acc[mt][nt][2];
            pb[j + 1] = acc[mt][nt][3];
        }
    }
}

// j = 256 column (fp32, tiny)
__global__ __launch_bounds__(256)
void qrel_last(const float* __restrict__ qb, const float* __restrict__ rel256,
               float* __restrict__ qr)
{
    int idx = blockIdx.x * 256 + threadIdx.x;   // 0 .. NH*MROWS-1
    int h = idx >> 13;          // / MROWS
    int row = idx & (MROWS - 1);
    const float4* qv = (const float4*)(qb + (size_t)row * DM + h * HD);
    const float4* rv = (const float4*)rel256;
    float a = 0.f;
    #pragma unroll
    for (int d4 = 0; d4 < HD / 4; d4++) {
        float4 qf = qv[d4];
        float4 rf = rv[d4];
        a = fmaf(qf.x, rf.x, a);
        a = fmaf(qf.y, rf.y, a);
        a = fmaf(qf.z, rf.z, a);
        a = fmaf(qf.w, rf.w, a);
    }
    qr[((size_t)h * MROWS + row) * NREL + 256] = a;
}

// ===========================================================================
// attn_score (tf32 mma)
// ===========================================================================
#define SCORE_SMEM (2 * 128 * SPAD * (int)sizeof(float))
__global__ __launch_bounds__(256)
void attn_score(const float* __restrict__ qb, const float* __restrict__ kb,
                const float* __restrict__ qr, float* __restrict__ sc)
{
    extern __shared__ float sm[];
    float* Qs = sm;
    float* Ks = sm + 128 * SPAD;

    int tid = threadIdx.x;
    int k0 = blockIdx.x * 128;
    int q0 = blockIdx.y * 128;
    int bh = blockIdx.z;
    int b = bh >> 3;
    int h = bh & 7;
    int bs = b * SEQ;

    #pragma unroll
    for (int i = 0; i < 8; i++) {
        int ch = tid + i * 256;
        int r  = ch >> 4;
        int d0 = (ch & 15) << 2;
        *(float4*)&Qs[r * SPAD + d0] =
            *(const float4*)(qb + (size_t)(bs + q0 + r) * DM + h * HD + d0);
        *(float4*)&Ks[r * SPAD + d0] =
            *(const float4*)(kb + (size_t)(bs + k0 + r) * DM + h * HD + d0);
    }
    __syncthreads();

    int warp = tid >> 5, lane = tid & 31;
    int gid = lane >> 2, tig = lane & 3;
    int wm = (warp & 1) * 64;
    int wn = (warp >> 1) * 32;

    float acc[4][4][4] = {};
    #pragma unroll
    for (int ks = 0; ks < 64; ks += 8) {
        uint32_t af[4][4], bf[4][2];
        #pragma unroll
        for (int mt = 0; mt < 4; mt++) {
            int m = wm + mt * 16 + gid;
            af[mt][0] = tf32u(Qs[m * SPAD + ks + tig]);
            af[mt][1] = tf32u(Qs[(m + 8) * SPAD + ks + tig]);
            af[mt][2] = tf32u(Qs[m * SPAD + ks + tig + 4]);
            af[mt][3] = tf32u(Qs[(m + 8) * SPAD + ks + tig + 4]);
        }
        #pragma unroll
        for (int nt = 0; nt < 4; nt++) {
            int n = wn + nt * 8 + gid;
            bf[nt][0] = tf32u(Ks[n * SPAD + ks + tig]);
            bf[nt][1] = tf32u(Ks[n * SPAD + ks + tig + 4]);
        }
        #pragma unroll
        for (int mt = 0; mt < 4; mt++)
            #pragma unroll
            for (int nt = 0; nt < 4; nt++)
                mma_tf32(acc[mt][nt], af[mt], bf[nt]);
    }

    #pragma unroll
    for (int mt = 0; mt < 4; mt++) {
        int ra = q0 + wm + mt * 16 + gid;
        int rb = ra + 8;
        const float* qra = qr + ((size_t)h * MROWS + bs + ra) * NREL;
        const float* qrb = qr + ((size_t)h * MROWS + bs + rb) * NREL;
        #pragma unroll
        for (int nt = 0; nt < 4; nt++) {
            int kg = k0 + wn + nt * 8 + tig * 2;
            int d0a = min(max(kg     - ra, -MAXREL), MAXREL) + MAXREL;
            int d1a = min(max(kg + 1 - ra, -MAXREL), MAXREL) + MAXREL;
            int d0b = min(max(kg     - rb, -MAXREL), MAXREL) + MAXREL;
            int d1b = min(max(kg + 1 - rb, -MAXREL), MAXREL) + MAXREL;
            float o0 = acc[mt][nt][0] * 0.125f + qra[d0a];
            float o1 = acc[mt][nt][1] * 0.125f + qra[d1a];
            float o2 = acc[mt][nt][2] * 0.125f + qrb[d0b];
            float o3 = acc[mt][nt][3] * 0.125f + qrb[d1b];
            *(float2*)(sc + ((size_t)bh * SEQ + ra) * SEQ + kg) = make_float2(o0, o1);
            *(float2*)(sc + ((size_t)bh * SEQ + rb) * SEQ + kg) = make_float2(o2, o3);
        }
    }
}

// ===========================================================================
// softmax rows
// ===========================================================================
__global__ __launch_bounds__(128)
void softmax_rows(float* __restrict__ sc)
{
    __shared__ float ws[4];
    int tid = threadIdx.x;
    int lane = tid & 31, w = tid >> 5;
    float* row = sc + (size_t)blockIdx.x * SEQ;
    float4 v = ((float4*)row)[tid];

    float m = fmaxf(fmaxf(v.x, v.y), fmaxf(v.z, v.w));
    #pragma unroll
    for (int o = 16; o > 0; o >>= 1) m = fmaxf(m, __shfl_xor_sync(0xffffffffu, m, o));
    if (lane == 0) ws[w] = m;
    __syncthreads();
    m = fmaxf(fmaxf(ws[0], ws[1]), fmaxf(ws[2], ws[3]));
    __syncthreads();

    v.x = __expf(v.x - m); v.y = __expf(v.y - m);
    v.z = __expf(v.z - m); v.w = __expf(v.w - m);
    float s = v.x + v.y + v.z + v.w;
    #pragma unroll
    for (int o = 16; o > 0; o >>= 1) s += __shfl_xor_sync(0xffffffffu, s, o);
    if (lane == 0) ws[w] = s;
    __syncthreads();
    s = ws[0] + ws[1] + ws[2] + ws[3];
    float inv = 1.0f / s;
    v.x *= inv; v.y *= inv; v.z *= inv; v.w *= inv;
    ((float4*)row)[tid] = v;
}

// ===========================================================================
// attn_pv (tf32 mma, cp.async double-buffered)
// ===========================================================================
#define PV_P (128 * SPAD)
#define PV_V (64 * SPAD)
#define PV_STAGE (PV_P + PV_V)
#define PV_SMEM (2 * PV_STAGE * (int)sizeof(float))
__global__ __launch_bounds__(256)
void attn_pv(const float* __restrict__ p, const float* __restrict__ vb,
             float* __restrict__ ctx)
{
    extern __shared__ float sm[];
    uint32_t base = smem_u32(sm);

    int tid = threadIdx.x;
    int q0 = blockIdx.x * 128;
    int bh = blockIdx.y;
    int b = bh >> 3;
    int h = bh & 7;
    int bs = b * SEQ;

    auto prefetch = [&](int c, int s) {
        int kc = c << 6;
        uint32_t stage = base + (uint32_t)(s * PV_STAGE) * 4;
        #pragma unroll
        for (int i = 0; i < 8; i++) {
            int ch = tid + i * 256;
            int r  = ch >> 4;
            int c4 = (ch & 15) << 2;
            CP_ASYNC16(stage + (r * SPAD + c4) * 4,
                       p + ((size_t)bh * SEQ + q0 + r) * SEQ + kc + c4);
        }
        #pragma unroll
        for (int i = 0; i < 4; i++) {
            int ch = tid + i * 256;
            int kk = ch >> 4;
            int d0 = (ch & 15) << 2;
            CP_ASYNC16(stage + (PV_P + kk * SPAD + d0) * 4,
                       vb + (size_t)(bs + kc + kk) * DM + h * HD + d0);
        }
    };

    int warp = tid >> 5, lane = tid & 31;
    int gid = lane >> 2, tig = lane & 3;
    int wm = (warp & 3) * 32;
    int wn = (warp >> 2) * 32;

    float acc[2][4][4] = {};

    prefetch(0, 0);
    CP_COMMIT();

    for (int c = 0; c < 8; c++) {
        if (c + 1 < 8) prefetch(c + 1, (c + 1) & 1);
        CP_COMMIT();
        CP_WAIT1();
        __syncthreads();

        const float* Ps = sm + (c & 1) * PV_STAGE;
        const float* Vs = Ps + PV_P;
        #pragma unroll
        for (int ks = 0; ks < 64; ks += 8) {
            uint32_t af[2][4], bf[4][2];
            #pragma unroll
            for (int mt = 0; mt < 2; mt++) {
                int m = wm + mt * 16 + gid;
                af[mt][0] = tf32u(Ps[m * SPAD + ks + tig]);
                af[mt][1] = tf32u(Ps[(m + 8) * SPAD + ks + tig]);
                af[mt][2] = tf32u(Ps[m * SPAD + ks + tig + 4]);
                af[mt][3] = tf32u(Ps[(m + 8) * SPAD + ks + tig + 4]);
            }
            #pragma unroll
            for (int nt = 0; nt < 4; nt++) {
                int n = wn + nt * 8 + gid;
                bf[nt][0] = tf32u(Vs[(ks + tig) * SPAD + n]);
                bf[nt][1] = tf32u(Vs[(ks + tig + 4) * SPAD + n]);
            }
            #pragma unroll
            for (int mt = 0; mt < 2; mt++)
                #pragma unroll
                for (int nt = 0; nt < 4; nt++)
                    mma_tf32(acc[mt][nt], af[mt], bf[nt]);
        }
        __syncthreads();
    }

    #pragma unroll
    for (int mt = 0; mt < 2; mt++) {
        int ra = q0 + wm + mt * 16 + gid;
        int rb = ra + 8;
        #pragma unroll
        for (int nt = 0; nt < 4; nt++) {
            int col = h * HD + wn + nt * 8 + tig * 2;
            *(float2*)(ctx + (size_t)(bs + ra) * DM + col) =
                make_float2(acc[mt][nt][0], acc[mt][nt][1]);
            *(float2*)(ctx + (size_t)(bs + rb) * DM + col) =
                make_float2(acc[mt][nt][2], acc[mt][nt][3]);
        }
    }
}

// ===========================================================================
// residual add + LayerNorm
// ===========================================================================
__device__ __forceinline__ float block_sum128(float v, float* ws)
{
    #pragma unroll
    for (int o = 16; o > 0; o >>= 1) v += __shfl_xor_sync(0xffffffffu, v, o);
    int lane = threadIdx.x & 31, w = threadIdx.x >> 5;
    if (lane == 0) ws[w] = v;
    __syncthreads();
    v = ws[0] + ws[1] + ws[2] + ws[3];
    __syncthreads();
    return v;
}

__global__ __launch_bounds__(128)
void add_ln_kernel(const float* __restrict__ x, const float* __restrict__ add,
                   const float* __restrict__ g, const float* __restrict__ bta,
                   float* __restrict__ out)
{
    __shared__ float ws[4];
    int row = blockIdx.x;
    int tid = threadIdx.x;
    float4 v = ((const float4*)(x + (size_t)row * DM))[tid];
    if (add != nullptr) {
        float4 a = ((const float4*)(add + (size_t)row * DM))[tid];
        v.x += a.x; v.y += a.y; v.z += a.z; v.w += a.w;
    }
    float s = block_sum128(v.x + v.y + v.z + v.w, ws);
    float mean = s * (1.0f / DM);
    float dx = v.x - mean, dy = v.y - mean, dz = v.z - mean, dw = v.w - mean;
    float sq = block_sum128(dx*dx + dy*dy + dz*dz + dw*dw, ws);
    float rstd = rsqrtf(sq * (1.0f / DM) + 1e-5f);
    float4 gg = ((const float4*)g)[tid];
    float4 bb = ((const float4*)bta)[tid];
    float4 o;
    o.x = dx * rstd * gg.x + bb.x;
    o.y = dy * rstd * gg.y + bb.y;
    o.z = dz * rstd * gg.z + bb.z;
    o.w = dw * rstd * gg.w + bb.w;
    ((float4*)(out + (size_t)row * DM))[tid] = o;
}

// ===========================================================================
// head stage 2
// ===========================================================================
__global__ __launch_bounds__(256)
void head2_kernel(const float* __restrict__ tmp, const float* __restrict__ p2_w,
                  const float* __restrict__ p2_b, float* __restrict__ out)
{
    int wid = threadIdx.x >> 5;
    int lane = threadIdx.x & 31;
    int row = blockIdx.x * 8 + wid;
    const float* tr = tmp + (size_t)row * 256;
    float acc = 0.f;
    #pragma unroll
    for (int j = lane; j < 256; j += 32) acc = fmaf(tr[j], p2_w[j], acc);
    #pragma unroll
    for (int o = 16; o > 0; o >>= 1) acc += __shfl_xor_sync(0xffffffffu, acc, o);
    if (lane == 0) out[row] = acc + p2_b[0];
}

// ===========================================================================
// Launcher
// ===========================================================================
extern "C" void kernel_launch(void* const* d_in, const int* in_sizes, int n_in,
                              void* d_out, int out_size)
{
    const float* x     = (const float*)d_in[0];
    const float* in_w  = (const float*)d_in[1];
    const float* in_b  = (const float*)d_in[2];
    const float* Wq    = (const float*)d_in[3];
    const float* Wk    = (const float*)d_in[4];
    const float* Wv    = (const float*)d_in[5];
    const float* Wo    = (const float*)d_in[6];
    const float* bo    = (const float*)d_in[7];
    const float* relE  = (const float*)d_in[8];
    const float* w1    = (const float*)d_in[9];
    const float* b1    = (const float*)d_in[10];
    const float* w2    = (const float*)d_in[11];
    const float* b2    = (const float*)d_in[12];
    const float* ln1_g = (const float*)d_in[13];
    const float* ln1_b = (const float*)d_in[14];
    const float* ln2_g = (const float*)d_in[15];
    const float* ln2_b = (const float*)d_in[16];
    const float* on_g  = (const float*)d_in[17];
    const float* on_b  = (const float*)d_in[18];
    const float* p1_w  = (const float*)d_in[19];
    const float* p1_b  = (const float*)d_in[20];
    const float* p2_w  = (const float*)d_in[21];
    const float* p2_b  = (const float*)d_in[22];
    float* out = (float*)d_out;

    float *h, *q, *k, *v, *ctx, *tmp, *qr, *sc;
    cudaGetSymbolAddress((void**)&h,   g_h);
    cudaGetSymbolAddress((void**)&q,   g_q);
    cudaGetSymbolAddress((void**)&k,   g_k);
    cudaGetSymbolAddress((void**)&v,   g_v);
    cudaGetSymbolAddress((void**)&ctx, g_ctx);
    cudaGetSymbolAddress((void**)&tmp, g_tmp);
    cudaGetSymbolAddress((void**)&qr,  g_qr);
    cudaGetSymbolAddress((void**)&sc,  g_sc);

    static bool attr_set = false;
    if (!attr_set) {
        cudaFuncSetAttribute(qrel_mma,   cudaFuncAttributeMaxDynamicSharedMemorySize, QRELM_SMEM);
        cudaFuncSetAttribute(attn_score, cudaFuncAttributeMaxDynamicSharedMemorySize, SCORE_SMEM);
        cudaFuncSetAttribute(attn_pv,    cudaFuncAttributeMaxDynamicSharedMemorySize, PV_SMEM);
        cudaFuncSetAttribute(tgemm<false, false>, cudaFuncAttributeMaxDynamicSharedMemorySize, TG_SMEM);
        cudaFuncSetAttribute(tgemm<true, false>,  cudaFuncAttributeMaxDynamicSharedMemorySize, TG_SMEM);
        cudaFuncSetAttribute(tgemm<true, true>,   cudaFuncAttributeMaxDynamicSharedMemorySize, TG_SMEM);
        cudaFuncSetAttribute(tgemm_qkv,  cudaFuncAttributeMaxDynamicSharedMemorySize, TG_SMEM);
        attr_set = true;
    }

    embed_kernel<<<(MROWS * DM) / 256, 256>>>(x, in_w, in_b, h);

    dim3 gD(DM / 128, MROWS / 128);         // 4 x 64
    dim3 gQKV(DM / 128, MROWS / 128, 3);    // 4 x 64 x 3
    dim3 gF(FFD / 128, MROWS / 128);        // 16 x 64
    dim3 gP(256 / 128, MROWS / 128);
    dim3 gQR(MROWS / 128, 2, NH);           // 64 x 2 x 8
    dim3 gS(SEQ / 128, SEQ / 128, BATCH * NH);
    dim3 gPV(SEQ / 128, BATCH * NH);

    for (int l = 0; l < NLAYER; l++) {
        const float* wq  = Wq + (size_t)l * DM * DM;
        const float* wk  = Wk + (size_t)l * DM * DM;
        const float* wv  = Wv + (size_t)l * DM * DM;
        const float* wo  = Wo + (size_t)l * DM * DM;
        const float* bol = bo + (size_t)l * DM;
        const float* rl  = relE + (size_t)l * NREL * HD;
        const float* w1l = w1 + (size_t)l * DM * FFD;
        const float* b1l = b1 + (size_t)l * FFD;
        const float* w2l = w2 + (size_t)l * FFD * DM;
        const float* b2l = b2 + (size_t)l * DM;

        tgemm_qkv<<<gQKV, 128, TG_SMEM>>>(h, wq, wk, wv, q, k, v);

        qrel_mma<<<gQR, 256, QRELM_SMEM>>>(q, rl, qr);
        qrel_last<<<(NH * MROWS) / 256, 256>>>(q, rl + 256 * HD, qr);
        attn_score<<<gS, 256, SCORE_SMEM>>>(q, k, qr, sc);
        softmax_rows<<<BATCH * NH * SEQ, 128>>>(sc);
        attn_pv<<<gPV, 256, PV_SMEM>>>(sc, v, ctx);

        tgemm<true, false><<<gD, 128, TG_SMEM>>>(ctx, wo, bol, q, DM, DM);
        add_ln_kernel<<<MROWS, 128>>>(h, q, ln1_g + (size_t)l * DM, ln1_b + (size_t)l * DM, h);

        tgemm<true, true><<<gF, 128, TG_SMEM>>>(h, w1l, b1l, tmp, FFD, DM);
        tgemm<true, false><<<gD, 128, TG_SMEM>>>(tmp, w2l, b2l, q, DM, FFD);
        add_ln_kernel<<<MROWS, 128>>>(h, q, ln2_g + (size_t)l * DM, ln2_b + (size_t)l * DM, h);
    }

    add_ln_kernel<<<MROWS, 128>>>(h, nullptr, on_g, on_b, q);
    sgemm128<true, true><<<gP, 256>>>(q, p1_w, p1_b, tmp, MROWS, 256, DM);
    head2_kernel<<<MROWS / 8, 256>>>(tmp, p2_w, p2_b, out);
}

// round 14
// speedup vs baseline: 8.7780x; 1.1017x over previous
#include <cuda_runtime.h>
#include <cuda_bf16.h>
#include <math.h>
#include <stdint.h>

// Problem constants  (L, D, H, FF, I, MAXREL = 6, 512, 8, 2048, 50, 128)
#define BATCH 16
#define SEQ   512
#define DM    512
#define NH    8
#define HD    64
#define FFD   2048
#define NLAYER 6
#define MAXREL 128
#define NREL  257
#define MROWS (BATCH*SEQ)  // 8192

// Scratch (no allocation allowed)
__device__ float g_h[MROWS*DM];
__device__ float g_q[MROWS*DM];
__device__ float g_k[MROWS*DM];
__device__ float g_v[MROWS*DM];
__device__ float g_ctx[MROWS*DM];
__device__ float g_tmp[MROWS*FFD];
__device__ float g_qr[(size_t)NH*MROWS*NREL];

// TF32 round-to-nearest -> bits
__device__ __forceinline__ uint32_t tf32u(float x)
{
    uint32_t u;
    asm("cvt.rna.tf32.f32 %0, %1;" : "=r"(u) : "f"(x));
    return u;
}

// m16n8k8 tf32 mma (row.col), fp32 accumulate
__device__ __forceinline__ void mma_tf32(float* c, const uint32_t* a, const uint32_t* b)
{
    asm volatile(
        "mma.sync.aligned.m16n8k8.row.col.f32.tf32.tf32.f32 "
        "{%0,%1,%2,%3}, {%4,%5,%6,%7}, {%8,%9}, {%0,%1,%2,%3};"
        : "+f"(c[0]), "+f"(c[1]), "+f"(c[2]), "+f"(c[3])
        : "r"(a[0]), "r"(a[1]), "r"(a[2]), "r"(a[3]), "r"(b[0]), "r"(b[1]));
}

__device__ __forceinline__ uint32_t smem_u32(const void* p) {
    uint32_t a;
    asm("{ .reg .u64 t; cvta.to.shared.u64 t, %1; cvt.u32.u64 %0, t; }" : "=r"(a) : "l"(p));
    return a;
}
#define CP_ASYNC16(dst, src) \
    asm volatile("cp.async.cg.shared.global [%0], [%1], 16;" :: "r"(dst), "l"(src))
#define CP_COMMIT() asm volatile("cp.async.commit_group;" ::: "memory")
#define CP_WAIT1()  asm volatile("cp.async.wait_group 1;" ::: "memory")
#define CP_WAIT0()  asm volatile("cp.async.wait_group 0;" ::: "memory")

// ===========================================================================
// tgemm body: 128x128 tile, BK=32, 128 threads, 4 warps of 64x64.
// ===========================================================================
#define APAD 36
#define BPAD 136
#define A_ST (128 * APAD)
#define B_ST (32 * BPAD)
#define TG_STAGE (A_ST + B_ST)
#define TG_SMEM (2 * TG_STAGE * (int)sizeof(float))

template <bool BIAS, bool RELU>
__device__ __forceinline__
void tgemm_body(const float* __restrict__ A, const float* __restrict__ B,
                const float* __restrict__ bias, float* __restrict__ C,
                int N, int K, int row0, int col0, float* sm)
{
    int tid = threadIdx.x;
    int warp = tid >> 5;
    int lane = tid & 31;
    int gid = lane >> 2;
    int tig = lane & 3;
    int wm = (warp & 1) * 64;
    int wn = (warp >> 1) * 64;

    uint32_t sb = smem_u32(sm);

    auto prefetch = [&](int c, int s) {
        int k0 = c << 5;
        uint32_t stage = sb + (uint32_t)(s * TG_STAGE) * 4;
        #pragma unroll
        for (int i = 0; i < 8; i++) {
            int ch = tid + i * 128;
            int ar = ch >> 3;
            int fc = (ch & 7) << 2;
            CP_ASYNC16(stage + (ar * APAD + fc) * 4,
                       A + (size_t)(row0 + ar) * K + k0 + fc);
            int kk = ch >> 5;
            int nc = (ch & 31) << 2;
            CP_ASYNC16(stage + (A_ST + kk * BPAD + nc) * 4,
                       B + (size_t)(k0 + kk) * N + col0 + nc);
        }
    };

    float acc[4][8][4] = {};
    const int NC = K >> 5;

    prefetch(0, 0);
    CP_COMMIT();

    for (int c = 0; c < NC; c++) {
        if (c + 1 < NC) prefetch(c + 1, (c + 1) & 1);
        CP_COMMIT();
        CP_WAIT1();
        __syncthreads();

        const float* as = sm + (c & 1) * TG_STAGE;
        const float* bs = as + A_ST;
        #pragma unroll
        for (int ks = 0; ks < 32; ks += 8) {
            uint32_t af[4][4], bf[8][2];
            #pragma unroll
            for (int mt = 0; mt < 4; mt++) {
                int m = wm + mt * 16 + gid;
                af[mt][0] = tf32u(as[m * APAD + ks + tig]);
                af[mt][1] = tf32u(as[(m + 8) * APAD + ks + tig]);
                af[mt][2] = tf32u(as[m * APAD + ks + tig + 4]);
                af[mt][3] = tf32u(as[(m + 8) * APAD + ks + tig + 4]);
            }
            #pragma unroll
            for (int nt = 0; nt < 8; nt++) {
                int n = wn + nt * 8 + gid;
                bf[nt][0] = tf32u(bs[(ks + tig) * BPAD + n]);
                bf[nt][1] = tf32u(bs[(ks + tig + 4) * BPAD + n]);
            }
            #pragma unroll
            for (int mt = 0; mt < 4; mt++)
                #pragma unroll
                for (int nt = 0; nt < 8; nt++)
                    mma_tf32(acc[mt][nt], af[mt], bf[nt]);
        }
        __syncthreads();
    }

    #pragma unroll
    for (int mt = 0; mt < 4; mt++) {
        int ra = row0 + wm + mt * 16 + gid;
        int rb = ra + 8;
        #pragma unroll
        for (int nt = 0; nt < 8; nt++) {
            int col = col0 + wn + nt * 8 + tig * 2;
            float o0 = acc[mt][nt][0], o1 = acc[mt][nt][1];
            float o2 = acc[mt][nt][2], o3 = acc[mt][nt][3];
            if (BIAS) {
                float b0 = bias[col], b1 = bias[col + 1];
                o0 += b0; o1 += b1; o2 += b0; o3 += b1;
            }
            if (RELU) {
                o0 = fmaxf(o0, 0.f); o1 = fmaxf(o1, 0.f);
                o2 = fmaxf(o2, 0.f); o3 = fmaxf(o3, 0.f);
            }
            *(float2*)(C + (size_t)ra * N + col) = make_float2(o0, o1);
            *(float2*)(C + (size_t)rb * N + col) = make_float2(o2, o3);
        }
    }
}

template <bool BIAS, bool RELU>
__global__ __launch_bounds__(128, 2)
void tgemm(const float* __restrict__ A, const float* __restrict__ B,
           const float* __restrict__ bias, float* __restrict__ C,
           int N, int K)
{
    extern __shared__ float sm[];
    tgemm_body<BIAS, RELU>(A, B, bias, C, N, K, blockIdx.y * 128, blockIdx.x * 128, sm);
}

__global__ __launch_bounds__(128, 2)
void tgemm_qkv(const float* __restrict__ A,
               const float* __restrict__ B0, const float* __restrict__ B1,
               const float* __restrict__ B2,
               float* __restrict__ C0, float* __restrict__ C1, float* __restrict__ C2)
{
    extern __shared__ float sm[];
    int z = blockIdx.z;
    const float* B = (z == 0) ? B0 : ((z == 1) ? B1 : B2);
    float* C = (z == 0) ? C0 : ((z == 1) ? C1 : C2);
    tgemm_body<false, false>(A, B, nullptr, C, DM, DM, blockIdx.y * 128, blockIdx.x * 128, sm);
}

// ===========================================================================
// Embedding
// ===========================================================================
__global__ void embed_kernel(const float* __restrict__ x,
                             const float* __restrict__ in_w,
                             const float* __restrict__ in_b,
                             float* __restrict__ h)
{
    int idx = blockIdx.x * 256 + threadIdx.x;
    if (idx >= MROWS * DM) return;
    int r = idx >> 9;
    int c = idx & 511;
    const float* xr = x + (size_t)r * 50;
    float acc = in_b[c];
    #pragma unroll 10
    for (int i = 0; i < 50; i++)
        acc = fmaf(xr[i], in_w[i * DM + c], acc);
    int s = r & (SEQ - 1);
    int two_i = c & ~1;
    float earg = (float)two_i * (-9.210340371976184f / 512.0f);
    float div32 = expf(earg);
    float argf = (float)s * div32;
    double pe = (c & 1) ? cos((double)argf) : sin((double)argf);
    h[idx] = acc + (float)pe;
}

// ===========================================================================
// SGEMM 128x128 (fp32) — head p1 gemm
// ===========================================================================
template <bool BIAS, bool RELU>
__global__ __launch_bounds__(256)
void sgemm128(const float* __restrict__ A, const float* __restrict__ Bm,
              const float* __restrict__ bias, float* __restrict__ C,
              int M, int N, int K)
{
    __shared__ float As2[16][128];
    __shared__ float Bs2[16][128];

    int tid = threadIdx.x;
    int row0 = blockIdx.y * 128;
    int col0 = blockIdx.x * 128;
    int tx = tid & 15;
    int ty = tid >> 4;

    float acc[8][8] = {};

    for (int k0 = 0; k0 < K; k0 += 16) {
        #pragma unroll
        for (int i = 0; i < 2; i++) {
            int f = tid + i * 256;
            int ar = f >> 2;
            int ac = (f & 3) << 2;
            float4 av = *(const float4*)(A + (size_t)(row0 + ar) * K + k0 + ac);
            As2[ac + 0][ar] = av.x;
            As2[ac + 1][ar] = av.y;
            As2[ac + 2][ar] = av.z;
            As2[ac + 3][ar] = av.w;
        }
        #pragma unroll
        for (int i = 0; i < 2; i++) {
            int f = tid + i * 256;
            int br = f >> 5;
            int bc = (f & 31) << 2;
            *(float4*)&Bs2[br][bc] = *(const float4*)(Bm + (size_t)(k0 + br) * N + col0 + bc);
        }
        __syncthreads();

        #pragma unroll
        for (int kk = 0; kk < 16; kk++) {
            float4 a0 = *(const float4*)&As2[kk][ty * 8];
            float4 a1 = *(const float4*)&As2[kk][ty * 8 + 4];
            float4 b0 = *(const float4*)&Bs2[kk][tx * 8];
            float4 b1 = *(const float4*)&Bs2[kk][tx * 8 + 4];
            float av[8] = {a0.x, a0.y, a0.z, a0.w, a1.x, a1.y, a1.z, a1.w};
            float bv[8] = {b0.x, b0.y, b0.z, b0.w, b1.x, b1.y, b1.z, b1.w};
            #pragma unroll
            for (int i = 0; i < 8; i++)
                #pragma unroll
                for (int j = 0; j < 8; j++)
                    acc[i][j] = fmaf(av[i], bv[j], acc[i][j]);
        }
        __syncthreads();
    }

    float bvv[8] = {};
    if (BIAS) {
        float4 c0 = *(const float4*)(bias + col0 + tx * 8);
        float4 c1 = *(const float4*)(bias + col0 + tx * 8 + 4);
        bvv[0]=c0.x; bvv[1]=c0.y; bvv[2]=c0.z; bvv[3]=c0.w;
        bvv[4]=c1.x; bvv[5]=c1.y; bvv[6]=c1.z; bvv[7]=c1.w;
    }
    #pragma unroll
    for (int i = 0; i < 8; i++) {
        int row = row0 + ty * 8 + i;
        float o[8];
        #pragma unroll
        for (int j = 0; j < 8; j++) {
            o[j] = acc[i][j];
            if (BIAS) o[j] += bvv[j];
            if (RELU) o[j] = fmaxf(o[j], 0.f);
        }
        *(float4*)(C + (size_t)row * N + col0 + tx * 8)     = make_float4(o[0],o[1],o[2],o[3]);
        *(float4*)(C + (size_t)row * N + col0 + tx * 8 + 4) = make_float4(o[4],o[5],o[6],o[7]);
    }
}

// ===========================================================================
// qrel via tf32 mma (scalar stores: NREL=257 odd stride)
// ===========================================================================
#define SPAD 68
#define QRELM_SMEM (2 * 128 * SPAD * (int)sizeof(float))
__global__ __launch_bounds__(256)
void qrel_mma(const float* __restrict__ qb, const float* __restrict__ rel,
              float* __restrict__ qr)
{
    extern __shared__ float sm[];
    float* Qs = sm;
    float* Rs = sm + 128 * SPAD;

    int tid = threadIdx.x;
    int row0 = blockIdx.x * 128;
    int j0 = blockIdx.y * 128;
    int h = blockIdx.z;

    #pragma unroll
    for (int i = 0; i < 8; i++) {
        int ch = tid + i * 256;
        int r  = ch >> 4;
        int d0 = (ch & 15) << 2;
        *(float4*)&Qs[r * SPAD + d0] =
            *(const float4*)(qb + (size_t)(row0 + r) * DM + h * HD + d0);
        *(float4*)&Rs[r * SPAD + d0] =
            *(const float4*)(rel + (size_t)(j0 + r) * HD + d0);
    }
    __syncthreads();

    int warp = tid >> 5, lane = tid & 31;
    int gid = lane >> 2, tig = lane & 3;
    int wm = (warp & 1) * 64;
    int wn = (warp >> 1) * 32;

    float acc[4][4][4] = {};
    #pragma unroll
    for (int ks = 0; ks < 64; ks += 8) {
        uint32_t af[4][4], bf[4][2];
        #pragma unroll
        for (int mt = 0; mt < 4; mt++) {
            int m = wm + mt * 16 + gid;
            af[mt][0] = tf32u(Qs[m * SPAD + ks + tig]);
            af[mt][1] = tf32u(Qs[(m + 8) * SPAD + ks + tig]);
            af[mt][2] = tf32u(Qs[m * SPAD + ks + tig + 4]);
            af[mt][3] = tf32u(Qs[(m + 8) * SPAD + ks + tig + 4]);
        }
        #pragma unroll
        for (int nt = 0; nt < 4; nt++) {
            int n = wn + nt * 8 + gid;
            bf[nt][0] = tf32u(Rs[n * SPAD + ks + tig]);
            bf[nt][1] = tf32u(Rs[n * SPAD + ks + tig + 4]);
        }
        #pragma unroll
        for (int mt = 0; mt < 4; mt++)
            #pragma unroll
            for (int nt = 0; nt < 4; nt++)
                mma_tf32(acc[mt][nt], af[mt], bf[nt]);
    }

    #pragma unroll
    for (int mt = 0; mt < 4; mt++) {
        int ra = row0 + wm + mt * 16 + gid;
        int rb = ra + 8;
        float* pa = qr + ((size_t)h * MROWS + ra) * NREL;
        float* pb = qr + ((size_t)h * MROWS + rb) * NREL;
        #pragma unroll
        for (int nt = 0; nt < 4; nt++) {
            int j = j0 + wn + nt * 8 + tig * 2;
            pa[j]     = acc[mt][nt][0];
            pa[j + 1] = acc[mt][nt][1];
            pb[j]     = acc[mt][nt][2];
            pb[j + 1] = acc[mt][nt][3];
        }
    }
}

__global__ __launch_bounds__(256)
void qrel_last(const float* __restrict__ qb, const float* __restrict__ rel256,
               float* __restrict__ qr)
{
    int idx = blockIdx.x * 256 + threadIdx.x;
    int h = idx >> 13;
    int row = idx & (MROWS - 1);
    const float4* qv = (const float4*)(qb + (size_t)row * DM + h * HD);
    const float4* rv = (const float4*)rel256;
    float a = 0.f;
    #pragma unroll
    for (int d4 = 0; d4 < HD / 4; d4++) {
        float4 qf = qv[d4];
        float4 rf = rv[d4];
        a = fmaf(qf.x, rf.x, a);
        a = fmaf(qf.y, rf.y, a);
        a = fmaf(qf.z, rf.z, a);
        a = fmaf(qf.w, rf.w, a);
    }
    qr[((size_t)h * MROWS + row) * NREL + 256] = a;
}

// ===========================================================================
// Fused flash attention: per block, 128 queries of one (b,h); loops 4 K/V
// tiles of 128. Online softmax; rel bias from g_qr. 256 threads.
// ===========================================================================
#define FPAD 132
#define AF_QS  0
#define AF_KS  (128 * SPAD)
#define AF_VS  (2 * 128 * SPAD)
#define AF_PS  (3 * 128 * SPAD)
#define AF_MS  (AF_PS + 128 * FPAD)
#define AF_SS  (AF_MS + 128)
#define AF_FS  (AF_SS + 128)
#define AF_RED (AF_FS + 128)
#define AF_TOTAL (AF_RED + 512)
#define AF_SMEM (AF_TOTAL * (int)sizeof(float))

__global__ __launch_bounds__(256, 1)
void attn_fused(const float* __restrict__ qb, const float* __restrict__ kb,
                const float* __restrict__ vb, const float* __restrict__ qr,
                float* __restrict__ ctx)
{
    extern __shared__ float sm[];
    float* Qs = sm + AF_QS;
    float* Ks = sm + AF_KS;
    float* Vs = sm + AF_VS;
    float* Ps = sm + AF_PS;
    float* Msh = sm + AF_MS;
    float* Ssh = sm + AF_SS;
    float* Fsh = sm + AF_FS;
    float* red = sm + AF_RED;
    uint32_t base = smem_u32(sm);

    int tid = threadIdx.x;
    int q0 = blockIdx.x * 128;
    int bh = blockIdx.y;
    int b = bh >> 3, h = bh & 7;
    int bs = b * SEQ;

    // Q tile
    #pragma unroll
    for (int i = 0; i < 8; i++) {
        int ch = tid + i * 256;
        int r = ch >> 4;
        int d0 = (ch & 15) << 2;
        *(float4*)&Qs[r * SPAD + d0] =
            *(const float4*)(qb + (size_t)(bs + q0 + r) * DM + h * HD + d0);
    }
    if (tid < 128) { Msh[tid] = -1e30f; Ssh[tid] = 0.f; }

    auto loadK = [&](int t) {
        int k0 = t << 7;
        #pragma unroll
        for (int i = 0; i < 8; i++) {
            int ch = tid + i * 256;
            int r = ch >> 4, d0 = (ch & 15) << 2;
            CP_ASYNC16(base + (AF_KS + r * SPAD + d0) * 4,
                       kb + (size_t)(bs + k0 + r) * DM + h * HD + d0);
        }
    };
    auto loadV = [&](int t) {
        int k0 = t << 7;
        #pragma unroll
        for (int i = 0; i < 8; i++) {
            int ch = tid + i * 256;
            int r = ch >> 4, d0 = (ch & 15) << 2;
            CP_ASYNC16(base + (AF_VS + r * SPAD + d0) * 4,
                       vb + (size_t)(bs + k0 + r) * DM + h * HD + d0);
        }
    };

    int warp = tid >> 5, lane = tid & 31;
    int gid = lane >> 2, tig = lane & 3;
    int wm = (warp & 1) * 64;       // score layout
    int wn = (warp >> 1) * 32;
    int wg = warp >> 1;             // 0..3
    int wmP = (warp & 3) * 32;      // PV layout
    int wnP = (warp >> 2) * 32;

    float O[2][4][4] = {};

    loadK(0); CP_COMMIT();
    __syncthreads();

    for (int t = 0; t < 4; t++) {
        loadV(t); CP_COMMIT();
        CP_WAIT1();                     // K_t ready
        __syncthreads();

        // --- scores: Q @ K_t^T ---
        float acc[4][4][4] = {};
        #pragma unroll
        for (int ks = 0; ks < 64; ks += 8) {
            uint32_t af[4][4], bf[4][2];
            #pragma unroll
            for (int mt = 0; mt < 4; mt++) {
                int m = wm + mt * 16 + gid;
                af[mt][0] = tf32u(Qs[m * SPAD + ks + tig]);
                af[mt][1] = tf32u(Qs[(m + 8) * SPAD + ks + tig]);
                af[mt][2] = tf32u(Qs[m * SPAD + ks + tig + 4]);
                af[mt][3] = tf32u(Qs[(m + 8) * SPAD + ks + tig + 4]);
            }
            #pragma unroll
            for (int nt = 0; nt < 4; nt++) {
                int n = wn + nt * 8 + gid;
                bf[nt][0] = tf32u(Ks[n * SPAD + ks + tig]);
                bf[nt][1] = tf32u(Ks[n * SPAD + ks + tig + 4]);
            }
            #pragma unroll
            for (int mt = 0; mt < 4; mt++)
                #pragma unroll
                for (int nt = 0; nt < 4; nt++)
                    mma_tf32(acc[mt][nt], af[mt], bf[nt]);
        }
        __syncthreads();                // done reading Ks
        if (t < 3) { loadK(t + 1); CP_COMMIT(); }

        // --- scale + rel bias, local row max ---
        int k0 = t << 7;
        float ma[4], mb[4];
        #pragma unroll
        for (int mt = 0; mt < 4; mt++) {
            int ra = wm + mt * 16 + gid;
            int rb = ra + 8;
            int qga = q0 + ra, qgb = q0 + rb;
            const float* qra = qr + ((size_t)h * MROWS + bs + qga) * NREL;
            const float* qrb = qr + ((size_t)h * MROWS + bs + qgb) * NREL;
            ma[mt] = -1e30f; mb[mt] = -1e30f;
            #pragma unroll
            for (int nt = 0; nt < 4; nt++) {
                int kg = k0 + wn + nt * 8 + tig * 2;
                int d0a = min(max(kg     - qga, -MAXREL), MAXREL) + MAXREL;
                int d1a = min(max(kg + 1 - qga, -MAXREL), MAXREL) + MAXREL;
                int d0b = min(max(kg     - qgb, -MAXREL), MAXREL) + MAXREL;
                int d1b = min(max(kg + 1 - qgb, -MAXREL), MAXREL) + MAXREL;
                acc[mt][nt][0] = acc[mt][nt][0] * 0.125f + qra[d0a];
                acc[mt][nt][1] = acc[mt][nt][1] * 0.125f + qra[d1a];
                acc[mt][nt][2] = acc[mt][nt][2] * 0.125f + qrb[d0b];
                acc[mt][nt][3] = acc[mt][nt][3] * 0.125f + qrb[d1b];
                ma[mt] = fmaxf(ma[mt], fmaxf(acc[mt][nt][0], acc[mt][nt][1]));
                mb[mt] = fmaxf(mb[mt], fmaxf(acc[mt][nt][2], acc[mt][nt][3]));
            }
            // quad reduce (lanes differ in tig)
            #pragma unroll
            for (int o = 1; o < 4; o <<= 1) {
                ma[mt] = fmaxf(ma[mt], __shfl_xor_sync(0xffffffffu, ma[mt], o));
                mb[mt] = fmaxf(mb[mt], __shfl_xor_sync(0xffffffffu, mb[mt], o));
            }
            if (tig == 0) {
                red[ra * 4 + wg] = ma[mt];
                red[rb * 4 + wg] = mb[mt];
            }
        }
        __syncthreads();

        // --- tile max -> P = exp(s - Mnew), partial sums ---
        float MnA[4], MnB[4];
        #pragma unroll
        for (int mt = 0; mt < 4; mt++) {
            int ra = wm + mt * 16 + gid;
            int rb = ra + 8;
            float tma = fmaxf(fmaxf(red[ra*4+0], red[ra*4+1]), fmaxf(red[ra*4+2], red[ra*4+3]));
            float tmb = fmaxf(fmaxf(red[rb*4+0], red[rb*4+1]), fmaxf(red[rb*4+2], red[rb*4+3]));
            MnA[mt] = fmaxf(Msh[ra], tma);
            MnB[mt] = fmaxf(Msh[rb], tmb);
            float sa = 0.f, sb = 0.f;
            #pragma unroll
            for (int nt = 0; nt < 4; nt++) {
                float p0 = __expf(acc[mt][nt][0] - MnA[mt]);
                float p1 = __expf(acc[mt][nt][1] - MnA[mt]);
                float p2 = __expf(acc[mt][nt][2] - MnB[mt]);
                float p3 = __expf(acc[mt][nt][3] - MnB[mt]);
                sa += p0 + p1;
                sb += p2 + p3;
                int c = wn + nt * 8 + tig * 2;
                *(float2*)&Ps[ra * FPAD + c] = make_float2(p0, p1);
                *(float2*)&Ps[rb * FPAD + c] = make_float2(p2, p3);
            }
            #pragma unroll
            for (int o = 1; o < 4; o <<= 1) {
                sa += __shfl_xor_sync(0xffffffffu, sa, o);
                sb += __shfl_xor_sync(0xffffffffu, sb, o);
            }
            if (tig == 0) {
                red[ra * 4 + wg] = sa;
                red[rb * 4 + wg] = sb;
            }
        }
        __syncthreads();

        // --- writers: update M/S/F per row ---
        if (wg == 0 && tig == 0) {
            #pragma unroll
            for (int mt = 0; mt < 4; mt++) {
                int ra = wm + mt * 16 + gid;
                int rb = ra + 8;
                float tsa = red[ra*4+0] + red[ra*4+1] + red[ra*4+2] + red[ra*4+3];
                float tsb = red[rb*4+0] + red[rb*4+1] + red[rb*4+2] + red[rb*4+3];
                float fa = __expf(Msh[ra] - MnA[mt]);
                float fb = __expf(Msh[rb] - MnB[mt]);
                Ssh[ra] = Ssh[ra] * fa + tsa;
                Ssh[rb] = Ssh[rb] * fb + tsb;
                Msh[ra] = MnA[mt];
                Msh[rb] = MnB[mt];
                Fsh[ra] = fa;
                Fsh[rb] = fb;
            }
        }
        if (t < 3) CP_WAIT1(); else CP_WAIT0();   // V_t ready
        __syncthreads();

        // --- PV: rescale O, accumulate P @ V_t ---
        #pragma unroll
        for (int mt = 0; mt < 2; mt++) {
            int ra = wmP + mt * 16 + gid;
            int rb = ra + 8;
            float fa = Fsh[ra], fb = Fsh[rb];
            #pragma unroll
            for (int nt = 0; nt < 4; nt++) {
                O[mt][nt][0] *= fa; O[mt][nt][1] *= fa;
                O[mt][nt][2] *= fb; O[mt][nt][3] *= fb;
            }
        }
        #pragma unroll
        for (int ks = 0; ks < 128; ks += 8) {
            uint32_t af[2][4], bf[4][2];
            #pragma unroll
            for (int mt = 0; mt < 2; mt++) {
                int m = wmP + mt * 16 + gid;
                af[mt][0] = tf32u(Ps[m * FPAD + ks + tig]);
                af[mt][1] = tf32u(Ps[(m + 8) * FPAD + ks + tig]);
                af[mt][2] = tf32u(Ps[m * FPAD + ks + tig + 4]);
                af[mt][3] = tf32u(Ps[(m + 8) * FPAD + ks + tig + 4]);
            }
            #pragma unroll
            for (int nt = 0; nt < 4; nt++) {
                int n = wnP + nt * 8 + gid;
                bf[nt][0] = tf32u(Vs[(ks + tig) * SPAD + n]);
                bf[nt][1] = tf32u(Vs[(ks + tig + 4) * SPAD + n]);
            }
            #pragma unroll
            for (int mt = 0; mt < 2; mt++)
                #pragma unroll
                for (int nt = 0; nt < 4; nt++)
                    mma_tf32(O[mt][nt], af[mt], bf[nt]);
        }
        __syncthreads();   // before next V/P overwrite
    }

    // epilogue: normalize, write ctx
    #pragma unroll
    for (int mt = 0; mt < 2; mt++) {
        int ra = wmP + mt * 16 + gid;
        int rb = ra + 8;
        float ia = 1.0f / Ssh[ra];
        float ib = 1.0f / Ssh[rb];
        #pragma unroll
        for (int nt = 0; nt < 4; nt++) {
            int col = h * HD + wnP + nt * 8 + tig * 2;
            *(float2*)(ctx + (size_t)(bs + q0 + ra) * DM + col) =
                make_float2(O[mt][nt][0] * ia, O[mt][nt][1] * ia);
            *(float2*)(ctx + (size_t)(bs + q0 + rb) * DM + col) =
                make_float2(O[mt][nt][2] * ib, O[mt][nt][3] * ib);
        }
    }
}

// ===========================================================================
// residual add + LayerNorm
// ===========================================================================
__device__ __forceinline__ float block_sum128(float v, float* ws)
{
    #pragma unroll
    for (int o = 16; o > 0; o >>= 1) v += __shfl_xor_sync(0xffffffffu, v, o);
    int lane = threadIdx.x & 31, w = threadIdx.x >> 5;
    if (lane == 0) ws[w] = v;
    __syncthreads();
    v = ws[0] + ws[1] + ws[2] + ws[3];
    __syncthreads();
    return v;
}

__global__ __launch_bounds__(128)
void add_ln_kernel(const float* __restrict__ x, const float* __restrict__ add,
                   const float* __restrict__ g, const float* __restrict__ bta,
                   float* __restrict__ out)
{
    __shared__ float ws[4];
    int row = blockIdx.x;
    int tid = threadIdx.x;
    float4 v = ((const float4*)(x + (size_t)row * DM))[tid];
    if (add != nullptr) {
        float4 a = ((const float4*)(add + (size_t)row * DM))[tid];
        v.x += a.x; v.y += a.y; v.z += a.z; v.w += a.w;
    }
    float s = block_sum128(v.x + v.y + v.z + v.w, ws);
    float mean = s * (1.0f / DM);
    float dx = v.x - mean, dy = v.y - mean, dz = v.z - mean, dw = v.w - mean;
    float sq = block_sum128(dx*dx + dy*dy + dz*dz + dw*dw, ws);
    float rstd = rsqrtf(sq * (1.0f / DM) + 1e-5f);
    float4 gg = ((const float4*)g)[tid];
    float4 bb = ((const float4*)bta)[tid];
    float4 o;
    o.x = dx * rstd * gg.x + bb.x;
    o.y = dy * rstd * gg.y + bb.y;
    o.z = dz * rstd * gg.z + bb.z;
    o.w = dw * rstd * gg.w + bb.w;
    ((float4*)(out + (size_t)row * DM))[tid] = o;
}

// ===========================================================================
// head stage 2
// ===========================================================================
__global__ __launch_bounds__(256)
void head2_kernel(const float* __restrict__ tmp, const float* __restrict__ p2_w,
                  const float* __restrict__ p2_b, float* __restrict__ out)
{
    int wid = threadIdx.x >> 5;
    int lane = threadIdx.x & 31;
    int row = blockIdx.x * 8 + wid;
    const float* tr = tmp + (size_t)row * 256;
    float acc = 0.f;
    #pragma unroll
    for (int j = lane; j < 256; j += 32) acc = fmaf(tr[j], p2_w[j], acc);
    #pragma unroll
    for (int o = 16; o > 0; o >>= 1) acc += __shfl_xor_sync(0xffffffffu, acc, o);
    if (lane == 0) out[row] = acc + p2_b[0];
}

// ===========================================================================
// Launcher
// ===========================================================================
extern "C" void kernel_launch(void* const* d_in, const int* in_sizes, int n_in,
                              void* d_out, int out_size)
{
    const float* x     = (const float*)d_in[0];
    const float* in_w  = (const float*)d_in[1];
    const float* in_b  = (const float*)d_in[2];
    const float* Wq    = (const float*)d_in[3];
    const float* Wk    = (const float*)d_in[4];
    const float* Wv    = (const float*)d_in[5];
    const float* Wo    = (const float*)d_in[6];
    const float* bo    = (const float*)d_in[7];
    const float* relE  = (const float*)d_in[8];
    const float* w1    = (const float*)d_in[9];
    const float* b1    = (const float*)d_in[10];
    const float* w2    = (const float*)d_in[11];
    const float* b2    = (const float*)d_in[12];
    const float* ln1_g = (const float*)d_in[13];
    const float* ln1_b = (const float*)d_in[14];
    const float* ln2_g = (const float*)d_in[15];
    const float* ln2_b = (const float*)d_in[16];
    const float* on_g  = (const float*)d_in[17];
    const float* on_b  = (const float*)d_in[18];
    const float* p1_w  = (const float*)d_in[19];
    const float* p1_b  = (const float*)d_in[20];
    const float* p2_w  = (const float*)d_in[21];
    const float* p2_b  = (const float*)d_in[22];
    float* out = (float*)d_out;

    float *h, *q, *k, *v, *ctx, *tmp, *qr;
    cudaGetSymbolAddress((void**)&h,   g_h);
    cudaGetSymbolAddress((void**)&q,   g_q);
    cudaGetSymbolAddress((void**)&k,   g_k);
    cudaGetSymbolAddress((void**)&v,   g_v);
    cudaGetSymbolAddress((void**)&ctx, g_ctx);
    cudaGetSymbolAddress((void**)&tmp, g_tmp);
    cudaGetSymbolAddress((void**)&qr,  g_qr);

    static bool attr_set = false;
    if (!attr_set) {
        cudaFuncSetAttribute(qrel_mma,   cudaFuncAttributeMaxDynamicSharedMemorySize, QRELM_SMEM);
        cudaFuncSetAttribute(attn_fused, cudaFuncAttributeMaxDynamicSharedMemorySize, AF_SMEM);
        cudaFuncSetAttribute(tgemm<false, false>, cudaFuncAttributeMaxDynamicSharedMemorySize, TG_SMEM);
        cudaFuncSetAttribute(tgemm<true, false>,  cudaFuncAttributeMaxDynamicSharedMemorySize, TG_SMEM);
        cudaFuncSetAttribute(tgemm<true, true>,   cudaFuncAttributeMaxDynamicSharedMemorySize, TG_SMEM);
        cudaFuncSetAttribute(tgemm_qkv,  cudaFuncAttributeMaxDynamicSharedMemorySize, TG_SMEM);
        attr_set = true;
    }

    embed_kernel<<<(MROWS * DM) / 256, 256>>>(x, in_w, in_b, h);

    dim3 gD(DM / 128, MROWS / 128);
    dim3 gQKV(DM / 128, MROWS / 128, 3);
    dim3 gF(FFD / 128, MROWS / 128);
    dim3 gP(256 / 128, MROWS / 128);
    dim3 gQR(MROWS / 128, 2, NH);
    dim3 gAF(SEQ / 128, BATCH * NH);

    for (int l = 0; l < NLAYER; l++) {
        const float* wq  = Wq + (size_t)l * DM * DM;
        const float* wk  = Wk + (size_t)l * DM * DM;
        const float* wv  = Wv + (size_t)l * DM * DM;
        const float* wo  = Wo + (size_t)l * DM * DM;
        const float* bol = bo + (size_t)l * DM;
        const float* rl  = relE + (size_t)l * NREL * HD;
        const float* w1l = w1 + (size_t)l * DM * FFD;
        const float* b1l = b1 + (size_t)l * FFD;
        const float* w2l = w2 + (size_t)l * FFD * DM;
        const float* b2l = b2 + (size_t)l * DM;

        tgemm_qkv<<<gQKV, 128, TG_SMEM>>>(h, wq, wk, wv, q, k, v);

        qrel_mma<<<gQR, 256, QRELM_SMEM>>>(q, rl, qr);
        qrel_last<<<(NH * MROWS) / 256, 256>>>(q, rl + 256 * HD, qr);
        attn_fused<<<gAF, 256, AF_SMEM>>>(q, k, v, qr, ctx);

        tgemm<true, false><<<gD, 128, TG_SMEM>>>(ctx, wo, bol, q, DM, DM);
        add_ln_kernel<<<MROWS, 128>>>(h, q, ln1_g + (size_t)l * DM, ln1_b + (size_t)l * DM, h);

        tgemm<true, true><<<gF, 128, TG_SMEM>>>(h, w1l, b1l, tmp, FFD, DM);
        tgemm<true, false><<<gD, 128, TG_SMEM>>>(tmp, w2l, b2l, q, DM, FFD);
        add_ln_kernel<<<MROWS, 128>>>(h, q, ln2_g + (size_t)l * DM, ln2_b + (size_t)l * DM, h);
    }

    add_ln_kernel<<<MROWS, 128>>>(h, nullptr, on_g, on_b, q);
    sgemm128<true, true><<<gP, 256>>>(q, p1_w, p1_b, tmp, MROWS, 256, DM);
    head2_kernel<<<MROWS / 8, 256>>>(tmp, p2_w, p2_b, out);
}

// round 16
// speedup vs baseline: 8.9009x; 1.0140x over previous
#include <cuda_runtime.h>
#include <cuda_bf16.h>
#include <math.h>
#include <stdint.h>

// Problem constants  (L, D, H, FF, I, MAXREL = 6, 512, 8, 2048, 50, 128)
#define BATCH 16
#define SEQ   512
#define DM    512
#define NH    8
#define HD    64
#define FFD   2048
#define NLAYER 6
#define MAXREL 128
#define NREL  257
#define MROWS (BATCH*SEQ)  // 8192

// Scratch (no allocation allowed)
__device__ float g_h[MROWS*DM];
__device__ float g_q[MROWS*DM];
__device__ float g_k[MROWS*DM];
__device__ float g_v[MROWS*DM];
__device__ float g_ctx[MROWS*DM];
__device__ float g_tmp[MROWS*FFD];
__device__ float g_qr[(size_t)NH*MROWS*NREL];

// TF32 round-to-nearest -> bits
__device__ __forceinline__ uint32_t tf32u(float x)
{
    uint32_t u;
    asm("cvt.rna.tf32.f32 %0, %1;" : "=r"(u) : "f"(x));
    return u;
}

// m16n8k8 tf32 mma (row.col), fp32 accumulate
__device__ __forceinline__ void mma_tf32(float* c, const uint32_t* a, const uint32_t* b)
{
    asm volatile(
        "mma.sync.aligned.m16n8k8.row.col.f32.tf32.tf32.f32 "
        "{%0,%1,%2,%3}, {%4,%5,%6,%7}, {%8,%9}, {%0,%1,%2,%3};"
        : "+f"(c[0]), "+f"(c[1]), "+f"(c[2]), "+f"(c[3])
        : "r"(a[0]), "r"(a[1]), "r"(a[2]), "r"(a[3]), "r"(b[0]), "r"(b[1]));
}

__device__ __forceinline__ uint32_t smem_u32(const void* p) {
    uint32_t a;
    asm("{ .reg .u64 t; cvta.to.shared.u64 t, %1; cvt.u32.u64 %0, t; }" : "=r"(a) : "l"(p));
    return a;
}
#define CP_ASYNC16(dst, src) \
    asm volatile("cp.async.cg.shared.global [%0], [%1], 16;" :: "r"(dst), "l"(src))
#define CP_COMMIT() asm volatile("cp.async.commit_group;" ::: "memory")
#define CP_WAIT1()  asm volatile("cp.async.wait_group 1;" ::: "memory")
#define CP_WAIT0()  asm volatile("cp.async.wait_group 0;" ::: "memory")

// ===========================================================================
// tgemm body: 128x128 tile, BK=32, 128 threads, 4 warps of 64x64.
// RNA tf32 rounding on fragments (required for accuracy). Optional fused
// residual add (ADDRES).
// ===========================================================================
#define APAD 36
#define BPAD 136
#define A_ST (128 * APAD)
#define B_ST (32 * BPAD)
#define TG_STAGE (A_ST + B_ST)
#define TG_SMEM (2 * TG_STAGE * (int)sizeof(float))

template <bool BIAS, bool RELU, bool ADDRES>
__device__ __forceinline__
void tgemm_body(const float* __restrict__ A, const float* __restrict__ B,
                const float* __restrict__ bias, const float* __restrict__ R,
                float* __restrict__ C,
                int N, int K, int row0, int col0, float* sm)
{
    int tid = threadIdx.x;
    int warp = tid >> 5;
    int lane = tid & 31;
    int gid = lane >> 2;
    int tig = lane & 3;
    int wm = (warp & 1) * 64;
    int wn = (warp >> 1) * 64;

    uint32_t sb = smem_u32(sm);

    auto prefetch = [&](int c, int s) {
        int k0 = c << 5;
        uint32_t stage = sb + (uint32_t)(s * TG_STAGE) * 4;
        #pragma unroll
        for (int i = 0; i < 8; i++) {
            int ch = tid + i * 128;
            int ar = ch >> 3;
            int fc = (ch & 7) << 2;
            CP_ASYNC16(stage + (ar * APAD + fc) * 4,
                       A + (size_t)(row0 + ar) * K + k0 + fc);
            int kk = ch >> 5;
            int nc = (ch & 31) << 2;
            CP_ASYNC16(stage + (A_ST + kk * BPAD + nc) * 4,
                       B + (size_t)(k0 + kk) * N + col0 + nc);
        }
    };

    float acc[4][8][4] = {};
    const int NC = K >> 5;

    prefetch(0, 0);
    CP_COMMIT();

    for (int c = 0; c < NC; c++) {
        if (c + 1 < NC) prefetch(c + 1, (c + 1) & 1);
        CP_COMMIT();
        CP_WAIT1();
        __syncthreads();

        const float* as = sm + (c & 1) * TG_STAGE;
        const float* bs = as + A_ST;
        #pragma unroll
        for (int ks = 0; ks < 32; ks += 8) {
            uint32_t af[4][4], bf[8][2];
            #pragma unroll
            for (int mt = 0; mt < 4; mt++) {
                int m = wm + mt * 16 + gid;
                af[mt][0] = tf32u(as[m * APAD + ks + tig]);
                af[mt][1] = tf32u(as[(m + 8) * APAD + ks + tig]);
                af[mt][2] = tf32u(as[m * APAD + ks + tig + 4]);
                af[mt][3] = tf32u(as[(m + 8) * APAD + ks + tig + 4]);
            }
            #pragma unroll
            for (int nt = 0; nt < 8; nt++) {
                int n = wn + nt * 8 + gid;
                bf[nt][0] = tf32u(bs[(ks + tig) * BPAD + n]);
                bf[nt][1] = tf32u(bs[(ks + tig + 4) * BPAD + n]);
            }
            #pragma unroll
            for (int mt = 0; mt < 4; mt++)
                #pragma unroll
                for (int nt = 0; nt < 8; nt++)
                    mma_tf32(acc[mt][nt], af[mt], bf[nt]);
        }
        __syncthreads();
    }

    #pragma unroll
    for (int mt = 0; mt < 4; mt++) {
        int ra = row0 + wm + mt * 16 + gid;
        int rb = ra + 8;
        #pragma unroll
        for (int nt = 0; nt < 8; nt++) {
            int col = col0 + wn + nt * 8 + tig * 2;
            float o0 = acc[mt][nt][0], o1 = acc[mt][nt][1];
            float o2 = acc[mt][nt][2], o3 = acc[mt][nt][3];
            if (BIAS) {
                float b0 = bias[col], b1 = bias[col + 1];
                o0 += b0; o1 += b1; o2 += b0; o3 += b1;
            }
            if (ADDRES) {
                float2 r0 = *(const float2*)(R + (size_t)ra * N + col);
                float2 r1 = *(const float2*)(R + (size_t)rb * N + col);
                o0 += r0.x; o1 += r0.y; o2 += r1.x; o3 += r1.y;
            }
            if (RELU) {
                o0 = fmaxf(o0, 0.f); o1 = fmaxf(o1, 0.f);
                o2 = fmaxf(o2, 0.f); o3 = fmaxf(o3, 0.f);
            }
            *(float2*)(C + (size_t)ra * N + col) = make_float2(o0, o1);
            *(float2*)(C + (size_t)rb * N + col) = make_float2(o2, o3);
        }
    }
}

template <bool BIAS, bool RELU, bool ADDRES>
__global__ __launch_bounds__(128, 2)
void tgemm(const float* __restrict__ A, const float* __restrict__ B,
           const float* __restrict__ bias, const float* __restrict__ R,
           float* __restrict__ C, int N, int K)
{
    extern __shared__ float sm[];
    tgemm_body<BIAS, RELU, ADDRES>(A, B, bias, R, C, N, K,
                                   blockIdx.y * 128, blockIdx.x * 128, sm);
}

__global__ __launch_bounds__(128, 2)
void tgemm_qkv(const float* __restrict__ A,
               const float* __restrict__ B0, const float* __restrict__ B1,
               const float* __restrict__ B2,
               float* __restrict__ C0, float* __restrict__ C1, float* __restrict__ C2)
{
    extern __shared__ float sm[];
    int z = blockIdx.z;
    const float* B = (z == 0) ? B0 : ((z == 1) ? B1 : B2);
    float* C = (z == 0) ? C0 : ((z == 1) ? C1 : C2);
    tgemm_body<false, false, false>(A, B, nullptr, nullptr, C, DM, DM,
                                    blockIdx.y * 128, blockIdx.x * 128, sm);
}

// ===========================================================================
// Embedding
// ===========================================================================
__global__ void embed_kernel(const float* __restrict__ x,
                             const float* __restrict__ in_w,
                             const float* __restrict__ in_b,
                             float* __restrict__ h)
{
    int idx = blockIdx.x * 256 + threadIdx.x;
    if (idx >= MROWS * DM) return;
    int r = idx >> 9;
    int c = idx & 511;
    const float* xr = x + (size_t)r * 50;
    float acc = in_b[c];
    #pragma unroll 10
    for (int i = 0; i < 50; i++)
        acc = fmaf(xr[i], in_w[i * DM + c], acc);
    int s = r & (SEQ - 1);
    int two_i = c & ~1;
    float earg = (float)two_i * (-9.210340371976184f / 512.0f);
    float div32 = expf(earg);
    float argf = (float)s * div32;
    double pe = (c & 1) ? cos((double)argf) : sin((double)argf);
    h[idx] = acc + (float)pe;
}

// ===========================================================================
// qrel via tf32 mma; j=256 handled by blockIdx.y==1 blocks (serial dot).
// ===========================================================================
#define SPAD 68
#define QRELM_SMEM (2 * 128 * SPAD * (int)sizeof(float))
__global__ __launch_bounds__(256)
void qrel_mma(const float* __restrict__ qb, const float* __restrict__ rel,
              float* __restrict__ qr)
{
    extern __shared__ float sm[];
    float* Qs = sm;
    float* Rs = sm + 128 * SPAD;

    int tid = threadIdx.x;
    int row0 = blockIdx.x * 128;
    int j0 = blockIdx.y * 128;
    int h = blockIdx.z;

    #pragma unroll
    for (int i = 0; i < 8; i++) {
        int ch = tid + i * 256;
        int r  = ch >> 4;
        int d0 = (ch & 15) << 2;
        *(float4*)&Qs[r * SPAD + d0] =
            *(const float4*)(qb + (size_t)(row0 + r) * DM + h * HD + d0);
        *(float4*)&Rs[r * SPAD + d0] =
            *(const float4*)(rel + (size_t)(j0 + r) * HD + d0);
    }
    __syncthreads();

    int warp = tid >> 5, lane = tid & 31;
    int gid = lane >> 2, tig = lane & 3;
    int wm = (warp & 1) * 64;
    int wn = (warp >> 1) * 32;

    float acc[4][4][4] = {};
    #pragma unroll
    for (int ks = 0; ks < 64; ks += 8) {
        uint32_t af[4][4], bf[4][2];
        #pragma unroll
        for (int mt = 0; mt < 4; mt++) {
            int m = wm + mt * 16 + gid;
            af[mt][0] = tf32u(Qs[m * SPAD + ks + tig]);
            af[mt][1] = tf32u(Qs[(m + 8) * SPAD + ks + tig]);
            af[mt][2] = tf32u(Qs[m * SPAD + ks + tig + 4]);
            af[mt][3] = tf32u(Qs[(m + 8) * SPAD + ks + tig + 4]);
        }
        #pragma unroll
        for (int nt = 0; nt < 4; nt++) {
            int n = wn + nt * 8 + gid;
            bf[nt][0] = tf32u(Rs[n * SPAD + ks + tig]);
            bf[nt][1] = tf32u(Rs[n * SPAD + ks + tig + 4]);
        }
        #pragma unroll
        for (int mt = 0; mt < 4; mt++)
            #pragma unroll
            for (int nt = 0; nt < 4; nt++)
                mma_tf32(acc[mt][nt], af[mt], bf[nt]);
    }

    // scalar stores (NREL=257 odd stride)
    #pragma unroll
    for (int mt = 0; mt < 4; mt++) {
        int ra = row0 + wm + mt * 16 + gid;
        int rb = ra + 8;
        float* pa = qr + ((size_t)h * MROWS + ra) * NREL;
        float* pb = qr + ((size_t)h * MROWS + rb) * NREL;
        #pragma unroll
        for (int nt = 0; nt < 4; nt++) {
            int j = j0 + wn + nt * 8 + tig * 2;
            pa[j]     = acc[mt][nt][0];
            pa[j + 1] = acc[mt][nt][1];
            pb[j]     = acc[mt][nt][2];
            pb[j + 1] = acc[mt][nt][3];
        }
    }

    // j = 256 (tf32-rounded serial dot), done by the y==1 blocks
    if (blockIdx.y == 1 && tid < 128) {
        const float* r256 = rel + (size_t)256 * HD;
        float a = 0.f;
        #pragma unroll
        for (int d = 0; d < HD; d++)
            a = fmaf(__uint_as_float(tf32u(Qs[tid * SPAD + d])),
                     __uint_as_float(tf32u(r256[d])), a);
        qr[((size_t)h * MROWS + row0 + tid) * NREL + 256] = a;
    }
}

// ===========================================================================
// Fused flash attention
// ===========================================================================
#define FPAD 132
#define AF_QS  0
#define AF_KS  (128 * SPAD)
#define AF_VS  (2 * 128 * SPAD)
#define AF_PS  (3 * 128 * SPAD)
#define AF_MS  (AF_PS + 128 * FPAD)
#define AF_SS  (AF_MS + 128)
#define AF_FS  (AF_SS + 128)
#define AF_RED (AF_FS + 128)
#define AF_TOTAL (AF_RED + 512)
#define AF_SMEM (AF_TOTAL * (int)sizeof(float))

__global__ __launch_bounds__(256, 1)
void attn_fused(const float* __restrict__ qb, const float* __restrict__ kb,
                const float* __restrict__ vb, const float* __restrict__ qr,
                float* __restrict__ ctx)
{
    extern __shared__ float sm[];
    float* Qs = sm + AF_QS;
    float* Ks = sm + AF_KS;
    float* Vs = sm + AF_VS;
    float* Ps = sm + AF_PS;
    float* Msh = sm + AF_MS;
    float* Ssh = sm + AF_SS;
    float* Fsh = sm + AF_FS;
    float* red = sm + AF_RED;
    uint32_t base = smem_u32(sm);

    int tid = threadIdx.x;
    int q0 = blockIdx.x * 128;
    int bh = blockIdx.y;
    int b = bh >> 3, h = bh & 7;
    int bs = b * SEQ;

    #pragma unroll
    for (int i = 0; i < 8; i++) {
        int ch = tid + i * 256;
        int r = ch >> 4;
        int d0 = (ch & 15) << 2;
        *(float4*)&Qs[r * SPAD + d0] =
            *(const float4*)(qb + (size_t)(bs + q0 + r) * DM + h * HD + d0);
    }
    if (tid < 128) { Msh[tid] = -1e30f; Ssh[tid] = 0.f; }

    auto loadK = [&](int t) {
        int k0 = t << 7;
        #pragma unroll
        for (int i = 0; i < 8; i++) {
            int ch = tid + i * 256;
            int r = ch >> 4, d0 = (ch & 15) << 2;
            CP_ASYNC16(base + (AF_KS + r * SPAD + d0) * 4,
                       kb + (size_t)(bs + k0 + r) * DM + h * HD + d0);
        }
    };
    auto loadV = [&](int t) {
        int k0 = t << 7;
        #pragma unroll
        for (int i = 0; i < 8; i++) {
            int ch = tid + i * 256;
            int r = ch >> 4, d0 = (ch & 15) << 2;
            CP_ASYNC16(base + (AF_VS + r * SPAD + d0) * 4,
                       vb + (size_t)(bs + k0 + r) * DM + h * HD + d0);
        }
    };

    int warp = tid >> 5, lane = tid & 31;
    int gid = lane >> 2, tig = lane & 3;
    int wm = (warp & 1) * 64;
    int wn = (warp >> 1) * 32;
    int wg = warp >> 1;
    int wmP = (warp & 3) * 32;
    int wnP = (warp >> 2) * 32;

    float O[2][4][4] = {};

    loadK(0); CP_COMMIT();
    __syncthreads();

    for (int t = 0; t < 4; t++) {
        loadV(t); CP_COMMIT();
        CP_WAIT1();
        __syncthreads();

        float acc[4][4][4] = {};
        #pragma unroll
        for (int ks = 0; ks < 64; ks += 8) {
            uint32_t af[4][4], bf[4][2];
            #pragma unroll
            for (int mt = 0; mt < 4; mt++) {
                int m = wm + mt * 16 + gid;
                af[mt][0] = tf32u(Qs[m * SPAD + ks + tig]);
                af[mt][1] = tf32u(Qs[(m + 8) * SPAD + ks + tig]);
                af[mt][2] = tf32u(Qs[m * SPAD + ks + tig + 4]);
                af[mt][3] = tf32u(Qs[(m + 8) * SPAD + ks + tig + 4]);
            }
            #pragma unroll
            for (int nt = 0; nt < 4; nt++) {
                int n = wn + nt * 8 + gid;
                bf[nt][0] = tf32u(Ks[n * SPAD + ks + tig]);
                bf[nt][1] = tf32u(Ks[n * SPAD + ks + tig + 4]);
            }
            #pragma unroll
            for (int mt = 0; mt < 4; mt++)
                #pragma unroll
                for (int nt = 0; nt < 4; nt++)
                    mma_tf32(acc[mt][nt], af[mt], bf[nt]);
        }
        __syncthreads();
        if (t < 3) { loadK(t + 1); CP_COMMIT(); }

        int k0 = t << 7;
        float ma[4], mb[4];
        #pragma unroll
        for (int mt = 0; mt < 4; mt++) {
            int ra = wm + mt * 16 + gid;
            int rb = ra + 8;
            int qga = q0 + ra, qgb = q0 + rb;
            const float* qra = qr + ((size_t)h * MROWS + bs + qga) * NREL;
            const float* qrb = qr + ((size_t)h * MROWS + bs + qgb) * NREL;
            ma[mt] = -1e30f; mb[mt] = -1e30f;
            #pragma unroll
            for (int nt = 0; nt < 4; nt++) {
                int kg = k0 + wn + nt * 8 + tig * 2;
                int d0a = min(max(kg     - qga, -MAXREL), MAXREL) + MAXREL;
                int d1a = min(max(kg + 1 - qga, -MAXREL), MAXREL) + MAXREL;
                int d0b = min(max(kg     - qgb, -MAXREL), MAXREL) + MAXREL;
                int d1b = min(max(kg + 1 - qgb, -MAXREL), MAXREL) + MAXREL;
                acc[mt][nt][0] = acc[mt][nt][0] * 0.125f + qra[d0a];
                acc[mt][nt][1] = acc[mt][nt][1] * 0.125f + qra[d1a];
                acc[mt][nt][2] = acc[mt][nt][2] * 0.125f + qrb[d0b];
                acc[mt][nt][3] = acc[mt][nt][3] * 0.125f + qrb[d1b];
                ma[mt] = fmaxf(ma[mt], fmaxf(acc[mt][nt][0], acc[mt][nt][1]));
                mb[mt] = fmaxf(mb[mt], fmaxf(acc[mt][nt][2], acc[mt][nt][3]));
            }
            #pragma unroll
            for (int o = 1; o < 4; o <<= 1) {
                ma[mt] = fmaxf(ma[mt], __shfl_xor_sync(0xffffffffu, ma[mt], o));
                mb[mt] = fmaxf(mb[mt], __shfl_xor_sync(0xffffffffu, mb[mt], o));
            }
            if (tig == 0) {
                red[ra * 4 + wg] = ma[mt];
                red[rb * 4 + wg] = mb[mt];
            }
        }
        __syncthreads();

        float MnA[4], MnB[4];
        #pragma unroll
        for (int mt = 0; mt < 4; mt++) {
            int ra = wm + mt * 16 + gid;
            int rb = ra + 8;
            float tma = fmaxf(fmaxf(red[ra*4+0], red[ra*4+1]), fmaxf(red[ra*4+2], red[ra*4+3]));
            float tmb = fmaxf(fmaxf(red[rb*4+0], red[rb*4+1]), fmaxf(red[rb*4+2], red[rb*4+3]));
            MnA[mt] = fmaxf(Msh[ra], tma);
            MnB[mt] = fmaxf(Msh[rb], tmb);
            float sa = 0.f, sb = 0.f;
            #pragma unroll
            for (int nt = 0; nt < 4; nt++) {
                float p0 = __expf(acc[mt][nt][0] - MnA[mt]);
                float p1 = __expf(acc[mt][nt][1] - MnA[mt]);
                float p2 = __expf(acc[mt][nt][2] - MnB[mt]);
                float p3 = __expf(acc[mt][nt][3] - MnB[mt]);
                sa += p0 + p1;
                sb += p2 + p3;
                int c = wn + nt * 8 + tig * 2;
                *(float2*)&Ps[ra * FPAD + c] = make_float2(p0, p1);
                *(float2*)&Ps[rb * FPAD + c] = make_float2(p2, p3);
            }
            #pragma unroll
            for (int o = 1; o < 4; o <<= 1) {
                sa += __shfl_xor_sync(0xffffffffu, sa, o);
                sb += __shfl_xor_sync(0xffffffffu, sb, o);
            }
            if (tig == 0) {
                red[ra * 4 + wg] = sa;
                red[rb * 4 + wg] = sb;
            }
        }
        __syncthreads();

        if (wg == 0 && tig == 0) {
            #pragma unroll
            for (int mt = 0; mt < 4; mt++) {
                int ra = wm + mt * 16 + gid;
                int rb = ra + 8;
                float tsa = red[ra*4+0] + red[ra*4+1] + red[ra*4+2] + red[ra*4+3];
                float tsb = red[rb*4+0] + red[rb*4+1] + red[rb*4+2] + red[rb*4+3];
                float fa = __expf(Msh[ra] - MnA[mt]);
                float fb = __expf(Msh[rb] - MnB[mt]);
                Ssh[ra] = Ssh[ra] * fa + tsa;
                Ssh[rb] = Ssh[rb] * fb + tsb;
                Msh[ra] = MnA[mt];
                Msh[rb] = MnB[mt];
                Fsh[ra] = fa;
                Fsh[rb] = fb;
            }
        }
        if (t < 3) CP_WAIT1(); else CP_WAIT0();
        __syncthreads();

        #pragma unroll
        for (int mt = 0; mt < 2; mt++) {
            int ra = wmP + mt * 16 + gid;
            int rb = ra + 8;
            float fa = Fsh[ra], fb = Fsh[rb];
            #pragma unroll
            for (int nt = 0; nt < 4; nt++) {
                O[mt][nt][0] *= fa; O[mt][nt][1] *= fa;
                O[mt][nt][2] *= fb; O[mt][nt][3] *= fb;
            }
        }
        #pragma unroll
        for (int ks = 0; ks < 128; ks += 8) {
            uint32_t af[2][4], bf[4][2];
            #pragma unroll
            for (int mt = 0; mt < 2; mt++) {
                int m = wmP + mt * 16 + gid;
                af[mt][0] = tf32u(Ps[m * FPAD + ks + tig]);
                af[mt][1] = tf32u(Ps[(m + 8) * FPAD + ks + tig]);
                af[mt][2] = tf32u(Ps[m * FPAD + ks + tig + 4]);
                af[mt][3] = tf32u(Ps[(m + 8) * FPAD + ks + tig + 4]);
            }
            #pragma unroll
            for (int nt = 0; nt < 4; nt++) {
                int n = wnP + nt * 8 + gid;
                bf[nt][0] = tf32u(Vs[(ks + tig) * SPAD + n]);
                bf[nt][1] = tf32u(Vs[(ks + tig + 4) * SPAD + n]);
            }
            #pragma unroll
            for (int mt = 0; mt < 2; mt++)
                #pragma unroll
                for (int nt = 0; nt < 4; nt++)
                    mma_tf32(O[mt][nt], af[mt], bf[nt]);
        }
        __syncthreads();
    }

    #pragma unroll
    for (int mt = 0; mt < 2; mt++) {
        int ra = wmP + mt * 16 + gid;
        int rb = ra + 8;
        float ia = 1.0f / Ssh[ra];
        float ib = 1.0f / Ssh[rb];
        #pragma unroll
        for (int nt = 0; nt < 4; nt++) {
            int col = h * HD + wnP + nt * 8 + tig * 2;
            *(float2*)(ctx + (size_t)(bs + q0 + ra) * DM + col) =
                make_float2(O[mt][nt][0] * ia, O[mt][nt][1] * ia);
            *(float2*)(ctx + (size_t)(bs + q0 + rb) * DM + col) =
                make_float2(O[mt][nt][2] * ib, O[mt][nt][3] * ib);
        }
    }
}

// ===========================================================================
// LayerNorm (plain; input already has residual)
// ===========================================================================
__device__ __forceinline__ float block_sum128(float v, float* ws)
{
    #pragma unroll
    for (int o = 16; o > 0; o >>= 1) v += __shfl_xor_sync(0xffffffffu, v, o);
    int lane = threadIdx.x & 31, w = threadIdx.x >> 5;
    if (lane == 0) ws[w] = v;
    __syncthreads();
    v = ws[0] + ws[1] + ws[2] + ws[3];
    __syncthreads();
    return v;
}

__global__ __launch_bounds__(128)
void ln_kernel(const float* __restrict__ x,
               const float* __restrict__ g, const float* __restrict__ bta,
               float* __restrict__ out)
{
    __shared__ float ws[4];
    int row = blockIdx.x;
    int tid = threadIdx.x;
    float4 v = ((const float4*)(x + (size_t)row * DM))[tid];
    float s = block_sum128(v.x + v.y + v.z + v.w, ws);
    float mean = s * (1.0f / DM);
    float dx = v.x - mean, dy = v.y - mean, dz = v.z - mean, dw = v.w - mean;
    float sq = block_sum128(dx*dx + dy*dy + dz*dz + dw*dw, ws);
    float rstd = rsqrtf(sq * (1.0f / DM) + 1e-5f);
    float4 gg = ((const float4*)g)[tid];
    float4 bb = ((const float4*)bta)[tid];
    float4 o;
    o.x = dx * rstd * gg.x + bb.x;
    o.y = dy * rstd * gg.y + bb.y;
    o.z = dz * rstd * gg.z + bb.z;
    o.w = dw * rstd * gg.w + bb.w;
    ((float4*)(out + (size_t)row * DM))[tid] = o;
}

// ===========================================================================
// head stage 2
// ===========================================================================
__global__ __launch_bounds__(256)
void head2_kernel(const float* __restrict__ tmp, const float* __restrict__ p2_w,
                  const float* __restrict__ p2_b, float* __restrict__ out)
{
    int wid = threadIdx.x >> 5;
    int lane = threadIdx.x & 31;
    int row = blockIdx.x * 8 + wid;
    const float* tr = tmp + (size_t)row * 256;
    float acc = 0.f;
    #pragma unroll
    for (int j = lane; j < 256; j += 32) acc = fmaf(tr[j], p2_w[j], acc);
    #pragma unroll
    for (int o = 16; o > 0; o >>= 1) acc += __shfl_xor_sync(0xffffffffu, acc, o);
    if (lane == 0) out[row] = acc + p2_b[0];
}

// ===========================================================================
// Launcher
// ===========================================================================
extern "C" void kernel_launch(void* const* d_in, const int* in_sizes, int n_in,
                              void* d_out, int out_size)
{
    const float* x     = (const float*)d_in[0];
    const float* in_w  = (const float*)d_in[1];
    const float* in_b  = (const float*)d_in[2];
    const float* Wq    = (const float*)d_in[3];
    const float* Wk    = (const float*)d_in[4];
    const float* Wv    = (const float*)d_in[5];
    const float* Wo    = (const float*)d_in[6];
    const float* bo    = (const float*)d_in[7];
    const float* relE  = (const float*)d_in[8];
    const float* w1    = (const float*)d_in[9];
    const float* b1    = (const float*)d_in[10];
    const float* w2    = (const float*)d_in[11];
    const float* b2    = (const float*)d_in[12];
    const float* ln1_g = (const float*)d_in[13];
    const float* ln1_b = (const float*)d_in[14];
    const float* ln2_g = (const float*)d_in[15];
    const float* ln2_b = (const float*)d_in[16];
    const float* on_g  = (const float*)d_in[17];
    const float* on_b  = (const float*)d_in[18];
    const float* p1_w  = (const float*)d_in[19];
    const float* p1_b  = (const float*)d_in[20];
    const float* p2_w  = (const float*)d_in[21];
    const float* p2_b  = (const float*)d_in[22];
    float* out = (float*)d_out;

    float *h, *q, *k, *v, *ctx, *tmp, *qr;
    cudaGetSymbolAddress((void**)&h,   g_h);
    cudaGetSymbolAddress((void**)&q,   g_q);
    cudaGetSymbolAddress((void**)&k,   g_k);
    cudaGetSymbolAddress((void**)&v,   g_v);
    cudaGetSymbolAddress((void**)&ctx, g_ctx);
    cudaGetSymbolAddress((void**)&tmp, g_tmp);
    cudaGetSymbolAddress((void**)&qr,  g_qr);

    static bool attr_set = false;
    if (!attr_set) {
        cudaFuncSetAttribute(qrel_mma,   cudaFuncAttributeMaxDynamicSharedMemorySize, QRELM_SMEM);
        cudaFuncSetAttribute(attn_fused, cudaFuncAttributeMaxDynamicSharedMemorySize, AF_SMEM);
        cudaFuncSetAttribute(tgemm<false, false, false>, cudaFuncAttributeMaxDynamicSharedMemorySize, TG_SMEM);
        cudaFuncSetAttribute(tgemm<true, false, true>,   cudaFuncAttributeMaxDynamicSharedMemorySize, TG_SMEM);
        cudaFuncSetAttribute(tgemm<true, true, false>,   cudaFuncAttributeMaxDynamicSharedMemorySize, TG_SMEM);
        cudaFuncSetAttribute(tgemm_qkv,  cudaFuncAttributeMaxDynamicSharedMemorySize, TG_SMEM);
        attr_set = true;
    }

    embed_kernel<<<(MROWS * DM) / 256, 256>>>(x, in_w, in_b, h);

    dim3 gD(DM / 128, MROWS / 128);
    dim3 gQKV(DM / 128, MROWS / 128, 3);
    dim3 gF(FFD / 128, MROWS / 128);
    dim3 gP(256 / 128, MROWS / 128);
    dim3 gQR(MROWS / 128, 2, NH);
    dim3 gAF(SEQ / 128, BATCH * NH);

    for (int l = 0; l < NLAYER; l++) {
        const float* wq  = Wq + (size_t)l * DM * DM;
        const float* wk  = Wk + (size_t)l * DM * DM;
        const float* wv  = Wv + (size_t)l * DM * DM;
        const float* wo  = Wo + (size_t)l * DM * DM;
        const float* bol = bo + (size_t)l * DM;
        const float* rl  = relE + (size_t)l * NREL * HD;
        const float* w1l = w1 + (size_t)l * DM * FFD;
        const float* b1l = b1 + (size_t)l * FFD;
        const float* w2l = w2 + (size_t)l * FFD * DM;
        const float* b2l = b2 + (size_t)l * DM;

        tgemm_qkv<<<gQKV, 128, TG_SMEM>>>(h, wq, wk, wv, q, k, v);

        qrel_mma<<<gQR, 256, QRELM_SMEM>>>(q, rl, qr);
        attn_fused<<<gAF, 256, AF_SMEM>>>(q, k, v, qr, ctx);

        // q = ctx@Wo + bo + h (residual fused), then h = LN(q)
        tgemm<true, false, true><<<gD, 128, TG_SMEM>>>(ctx, wo, bol, h, q, DM, DM);
        ln_kernel<<<MROWS, 128>>>(q, ln1_g + (size_t)l * DM, ln1_b + (size_t)l * DM, h);

        tgemm<true, true, false><<<gF, 128, TG_SMEM>>>(h, w1l, b1l, nullptr, tmp, FFD, DM);
        // q = tmp@W2 + b2 + h (residual fused), then h = LN(q)
        tgemm<true, false, true><<<gD, 128, TG_SMEM>>>(tmp, w2l, b2l, h, q, DM, FFD);
        ln_kernel<<<MROWS, 128>>>(q, ln2_g + (size_t)l * DM, ln2_b + (size_t)l * DM, h);
    }

    ln_kernel<<<MROWS, 128>>>(h, on_g, on_b, q);
    tgemm<true, true, false><<<gP, 128, TG_SMEM>>>(q, p1_w, p1_b, nullptr, tmp, 256, DM);
    head2_kernel<<<MROWS / 8, 256>>>(tmp, p2_w, p2_b, out);
}

// round 17
// speedup vs baseline: 9.4258x; 1.0590x over previous
#include <cuda_runtime.h>
#include <cuda_bf16.h>
#include <math.h>
#include <stdint.h>

// Problem constants  (L, D, H, FF, I, MAXREL = 6, 512, 8, 2048, 50, 128)
#define BATCH 16
#define SEQ   512
#define DM    512
#define NH    8
#define HD    64
#define FFD   2048
#define NLAYER 6
#define MAXREL 128
#define NREL  257
#define MROWS (BATCH*SEQ)  // 8192

// Scratch (no allocation allowed)
__device__ float g_h[MROWS*DM];
__device__ float g_q[MROWS*DM];
__device__ float g_k[MROWS*DM];
__device__ float g_v[MROWS*DM];
__device__ float g_ctx[MROWS*DM];
__device__ float g_tmp[MROWS*FFD];
__device__ float g_qr[(size_t)NH*MROWS*NREL];

// Pre-rounded (tf32-RNA) weights
#define OFF_WQ  0
#define OFF_WK  1572864
#define OFF_WV  3145728
#define OFF_WO  4718592
#define OFF_W1  6291456
#define OFF_W2  12582912
#define OFF_P1  18874368
#define OFF_REL 19005440
#define WR_TOTAL 19104128
__device__ float g_wr[WR_TOTAL];

// TF32 round-to-nearest -> bits
__device__ __forceinline__ uint32_t tf32u(float x)
{
    uint32_t u;
    asm("cvt.rna.tf32.f32 %0, %1;" : "=r"(u) : "f"(x));
    return u;
}
__device__ __forceinline__ float tf32f(float x) { return __uint_as_float(tf32u(x)); }

// m16n8k8 tf32 mma (row.col), fp32 accumulate
__device__ __forceinline__ void mma_tf32(float* c, const uint32_t* a, const uint32_t* b)
{
    asm volatile(
        "mma.sync.aligned.m16n8k8.row.col.f32.tf32.tf32.f32 "
        "{%0,%1,%2,%3}, {%4,%5,%6,%7}, {%8,%9}, {%0,%1,%2,%3};"
        : "+f"(c[0]), "+f"(c[1]), "+f"(c[2]), "+f"(c[3])
        : "r"(a[0]), "r"(a[1]), "r"(a[2]), "r"(a[3]), "r"(b[0]), "r"(b[1]));
}

__device__ __forceinline__ uint32_t smem_u32(const void* p) {
    uint32_t a;
    asm("{ .reg .u64 t; cvta.to.shared.u64 t, %1; cvt.u32.u64 %0, t; }" : "=r"(a) : "l"(p));
    return a;
}
#define CP_ASYNC16(dst, src) \
    asm volatile("cp.async.cg.shared.global [%0], [%1], 16;" :: "r"(dst), "l"(src))
#define CP_COMMIT() asm volatile("cp.async.commit_group;" ::: "memory")
#define CP_WAIT1()  asm volatile("cp.async.wait_group 1;" ::: "memory")
#define CP_WAIT0()  asm volatile("cp.async.wait_group 0;" ::: "memory")

// ===========================================================================
// round_copy: dst[i] = tf32_rna(src[i])
// ===========================================================================
__global__ void round_copy(const float* __restrict__ src, float* __restrict__ dst, int n4)
{
    int idx = blockIdx.x * 256 + threadIdx.x;
    if (idx >= n4) return;
    float4 v = ((const float4*)src)[idx];
    v.x = tf32f(v.x); v.y = tf32f(v.y); v.z = tf32f(v.z); v.w = tf32f(v.w);
    ((float4*)dst)[idx] = v;
}

// ===========================================================================
// tgemm body: 128x128 tile, BK=32, 128 threads, 4 warps of 64x64.
// B always pre-rounded (raw bits). ACVT: round A fragments; OUTROUND: round C.
// ===========================================================================
#define APAD 36
#define BPAD 136
#define A_ST (128 * APAD)
#define B_ST (32 * BPAD)
#define TG_STAGE (A_ST + B_ST)
#define TG_SMEM (2 * TG_STAGE * (int)sizeof(float))

template <bool BIAS, bool RELU, bool ADDRES, bool ACVT, bool OUTROUND>
__device__ __forceinline__
void tgemm_body(const float* __restrict__ A, const float* __restrict__ B,
                const float* __restrict__ bias, const float* __restrict__ R,
                float* __restrict__ C,
                int N, int K, int row0, int col0, float* sm)
{
    int tid = threadIdx.x;
    int warp = tid >> 5;
    int lane = tid & 31;
    int gid = lane >> 2;
    int tig = lane & 3;
    int wm = (warp & 1) * 64;
    int wn = (warp >> 1) * 64;

    uint32_t sb = smem_u32(sm);

    auto prefetch = [&](int c, int s) {
        int k0 = c << 5;
        uint32_t stage = sb + (uint32_t)(s * TG_STAGE) * 4;
        #pragma unroll
        for (int i = 0; i < 8; i++) {
            int ch = tid + i * 128;
            int ar = ch >> 3;
            int fc = (ch & 7) << 2;
            CP_ASYNC16(stage + (ar * APAD + fc) * 4,
                       A + (size_t)(row0 + ar) * K + k0 + fc);
            int kk = ch >> 5;
            int nc = (ch & 31) << 2;
            CP_ASYNC16(stage + (A_ST + kk * BPAD + nc) * 4,
                       B + (size_t)(k0 + kk) * N + col0 + nc);
        }
    };

    float acc[4][8][4] = {};
    const int NC = K >> 5;

    prefetch(0, 0);
    CP_COMMIT();

    for (int c = 0; c < NC; c++) {
        if (c + 1 < NC) prefetch(c + 1, (c + 1) & 1);
        CP_COMMIT();
        CP_WAIT1();
        __syncthreads();

        const float* as = sm + (c & 1) * TG_STAGE;
        const uint32_t* asu = (const uint32_t*)as;
        const uint32_t* bsu = asu + A_ST;
        #pragma unroll
        for (int ks = 0; ks < 32; ks += 8) {
            uint32_t af[4][4], bf[8][2];
            #pragma unroll
            for (int mt = 0; mt < 4; mt++) {
                int m = wm + mt * 16 + gid;
                if (ACVT) {
                    af[mt][0] = tf32u(as[m * APAD + ks + tig]);
                    af[mt][1] = tf32u(as[(m + 8) * APAD + ks + tig]);
                    af[mt][2] = tf32u(as[m * APAD + ks + tig + 4]);
                    af[mt][3] = tf32u(as[(m + 8) * APAD + ks + tig + 4]);
                } else {
                    af[mt][0] = asu[m * APAD + ks + tig];
                    af[mt][1] = asu[(m + 8) * APAD + ks + tig];
                    af[mt][2] = asu[m * APAD + ks + tig + 4];
                    af[mt][3] = asu[(m + 8) * APAD + ks + tig + 4];
                }
            }
            #pragma unroll
            for (int nt = 0; nt < 8; nt++) {
                int n = wn + nt * 8 + gid;
                bf[nt][0] = bsu[(ks + tig) * BPAD + n];
                bf[nt][1] = bsu[(ks + tig + 4) * BPAD + n];
            }
            #pragma unroll
            for (int mt = 0; mt < 4; mt++)
                #pragma unroll
                for (int nt = 0; nt < 8; nt++)
                    mma_tf32(acc[mt][nt], af[mt], bf[nt]);
        }
        __syncthreads();
    }

    #pragma unroll
    for (int mt = 0; mt < 4; mt++) {
        int ra = row0 + wm + mt * 16 + gid;
        int rb = ra + 8;
        #pragma unroll
        for (int nt = 0; nt < 8; nt++) {
            int col = col0 + wn + nt * 8 + tig * 2;
            float o0 = acc[mt][nt][0], o1 = acc[mt][nt][1];
            float o2 = acc[mt][nt][2], o3 = acc[mt][nt][3];
            if (BIAS) {
                float b0 = bias[col], b1 = bias[col + 1];
                o0 += b0; o1 += b1; o2 += b0; o3 += b1;
            }
            if (ADDRES) {
                float2 r0 = *(const float2*)(R + (size_t)ra * N + col);
                float2 r1 = *(const float2*)(R + (size_t)rb * N + col);
                o0 += r0.x; o1 += r0.y; o2 += r1.x; o3 += r1.y;
            }
            if (RELU) {
                o0 = fmaxf(o0, 0.f); o1 = fmaxf(o1, 0.f);
                o2 = fmaxf(o2, 0.f); o3 = fmaxf(o3, 0.f);
            }
            if (OUTROUND) {
                o0 = tf32f(o0); o1 = tf32f(o1); o2 = tf32f(o2); o3 = tf32f(o3);
            }
            *(float2*)(C + (size_t)ra * N + col) = make_float2(o0, o1);
            *(float2*)(C + (size_t)rb * N + col) = make_float2(o2, o3);
        }
    }
}

template <bool BIAS, bool RELU, bool ADDRES, bool ACVT, bool OUTROUND>
__global__ __launch_bounds__(128, 2)
void tgemm(const float* __restrict__ A, const float* __restrict__ B,
           const float* __restrict__ bias, const float* __restrict__ R,
           float* __restrict__ C, int N, int K)
{
    extern __shared__ float sm[];
    tgemm_body<BIAS, RELU, ADDRES, ACVT, OUTROUND>(A, B, bias, R, C, N, K,
                                   blockIdx.y * 128, blockIdx.x * 128, sm);
}

__global__ __launch_bounds__(128, 2)
void tgemm_qkv(const float* __restrict__ A,
               const float* __restrict__ B0, const float* __restrict__ B1,
               const float* __restrict__ B2,
               float* __restrict__ C0, float* __restrict__ C1, float* __restrict__ C2)
{
    extern __shared__ float sm[];
    int z = blockIdx.z;
    const float* B = (z == 0) ? B0 : ((z == 1) ? B1 : B2);
    float* C = (z == 0) ? C0 : ((z == 1) ? C1 : C2);
    tgemm_body<false, false, false, true, true>(A, B, nullptr, nullptr, C, DM, DM,
                                    blockIdx.y * 128, blockIdx.x * 128, sm);
}

// ===========================================================================
// Embedding
// ===========================================================================
__global__ void embed_kernel(const float* __restrict__ x,
                             const float* __restrict__ in_w,
                             const float* __restrict__ in_b,
                             float* __restrict__ h)
{
    int idx = blockIdx.x * 256 + threadIdx.x;
    if (idx >= MROWS * DM) return;
    int r = idx >> 9;
    int c = idx & 511;
    const float* xr = x + (size_t)r * 50;
    float acc = in_b[c];
    #pragma unroll 10
    for (int i = 0; i < 50; i++)
        acc = fmaf(xr[i], in_w[i * DM + c], acc);
    int s = r & (SEQ - 1);
    int two_i = c & ~1;
    float earg = (float)two_i * (-9.210340371976184f / 512.0f);
    float div32 = expf(earg);
    float argf = (float)s * div32;
    double pe = (c & 1) ? cos((double)argf) : sin((double)argf);
    h[idx] = acc + (float)pe;
}

// ===========================================================================
// qrel via tf32 mma. Q and rel are pre-rounded -> raw fragments.
// j=256 handled by blockIdx.y==1 blocks (serial fp32 dot on rounded values).
// ===========================================================================
#define SPAD 68
#define QRELM_SMEM (2 * 128 * SPAD * (int)sizeof(float))
__global__ __launch_bounds__(256)
void qrel_mma(const float* __restrict__ qb, const float* __restrict__ rel,
              float* __restrict__ qr)
{
    extern __shared__ float sm[];
    float* Qs = sm;
    float* Rs = sm + 128 * SPAD;

    int tid = threadIdx.x;
    int row0 = blockIdx.x * 128;
    int j0 = blockIdx.y * 128;
    int h = blockIdx.z;

    #pragma unroll
    for (int i = 0; i < 8; i++) {
        int ch = tid + i * 256;
        int r  = ch >> 4;
        int d0 = (ch & 15) << 2;
        *(float4*)&Qs[r * SPAD + d0] =
            *(const float4*)(qb + (size_t)(row0 + r) * DM + h * HD + d0);
        *(float4*)&Rs[r * SPAD + d0] =
            *(const float4*)(rel + (size_t)(j0 + r) * HD + d0);
    }
    __syncthreads();

    int warp = tid >> 5, lane = tid & 31;
    int gid = lane >> 2, tig = lane & 3;
    int wm = (warp & 1) * 64;
    int wn = (warp >> 1) * 32;

    const uint32_t* Qu = (const uint32_t*)Qs;
    const uint32_t* Ru = (const uint32_t*)Rs;

    float acc[4][4][4] = {};
    #pragma unroll
    for (int ks = 0; ks < 64; ks += 8) {
        uint32_t af[4][4], bf[4][2];
        #pragma unroll
        for (int mt = 0; mt < 4; mt++) {
            int m = wm + mt * 16 + gid;
            af[mt][0] = Qu[m * SPAD + ks + tig];
            af[mt][1] = Qu[(m + 8) * SPAD + ks + tig];
            af[mt][2] = Qu[m * SPAD + ks + tig + 4];
            af[mt][3] = Qu[(m + 8) * SPAD + ks + tig + 4];
        }
        #pragma unroll
        for (int nt = 0; nt < 4; nt++) {
            int n = wn + nt * 8 + gid;
            bf[nt][0] = Ru[n * SPAD + ks + tig];
            bf[nt][1] = Ru[n * SPAD + ks + tig + 4];
        }
        #pragma unroll
        for (int mt = 0; mt < 4; mt++)
            #pragma unroll
            for (int nt = 0; nt < 4; nt++)
                mma_tf32(acc[mt][nt], af[mt], bf[nt]);
    }

    // scalar stores (NREL=257 odd stride)
    #pragma unroll
    for (int mt = 0; mt < 4; mt++) {
        int ra = row0 + wm + mt * 16 + gid;
        int rb = ra + 8;
        float* pa = qr + ((size_t)h * MROWS + ra) * NREL;
        float* pb = qr + ((size_t)h * MROWS + rb) * NREL;
        #pragma unroll
        for (int nt = 0; nt < 4; nt++) {
            int j = j0 + wn + nt * 8 + tig * 2;
            pa[j]     = acc[mt][nt][0];
            pa[j + 1] = acc[mt][nt][1];
            pb[j]     = acc[mt][nt][2];
            pb[j + 1] = acc[mt][nt][3];
        }
    }

    // j = 256 (values already rounded)
    if (blockIdx.y == 1 && tid < 128) {
        const float* r256 = rel + (size_t)256 * HD;
        float a = 0.f;
        #pragma unroll
        for (int d = 0; d < HD; d++)
            a = fmaf(Qs[tid * SPAD + d], r256[d], a);
        qr[((size_t)h * MROWS + row0 + tid) * NREL + 256] = a;
    }
}

// ===========================================================================
// Fused flash attention. Q/K/V pre-rounded -> raw fragments; P rounds via CVT.
// ===========================================================================
#define FPAD 132
#define AF_QS  0
#define AF_KS  (128 * SPAD)
#define AF_VS  (2 * 128 * SPAD)
#define AF_PS  (3 * 128 * SPAD)
#define AF_MS  (AF_PS + 128 * FPAD)
#define AF_SS  (AF_MS + 128)
#define AF_FS  (AF_SS + 128)
#define AF_RED (AF_FS + 128)
#define AF_TOTAL (AF_RED + 512)
#define AF_SMEM (AF_TOTAL * (int)sizeof(float))

__global__ __launch_bounds__(256, 1)
void attn_fused(const float* __restrict__ qb, const float* __restrict__ kb,
                const float* __restrict__ vb, const float* __restrict__ qr,
                float* __restrict__ ctx)
{
    extern __shared__ float sm[];
    float* Qs = sm + AF_QS;
    float* Ks = sm + AF_KS;
    float* Vs = sm + AF_VS;
    float* Ps = sm + AF_PS;
    float* Msh = sm + AF_MS;
    float* Ssh = sm + AF_SS;
    float* Fsh = sm + AF_FS;
    float* red = sm + AF_RED;
    uint32_t base = smem_u32(sm);

    int tid = threadIdx.x;
    int q0 = blockIdx.x * 128;
    int bh = blockIdx.y;
    int b = bh >> 3, h = bh & 7;
    int bs = b * SEQ;

    #pragma unroll
    for (int i = 0; i < 8; i++) {
        int ch = tid + i * 256;
        int r = ch >> 4;
        int d0 = (ch & 15) << 2;
        *(float4*)&Qs[r * SPAD + d0] =
            *(const float4*)(qb + (size_t)(bs + q0 + r) * DM + h * HD + d0);
    }
    if (tid < 128) { Msh[tid] = -1e30f; Ssh[tid] = 0.f; }

    auto loadK = [&](int t) {
        int k0 = t << 7;
        #pragma unroll
        for (int i = 0; i < 8; i++) {
            int ch = tid + i * 256;
            int r = ch >> 4, d0 = (ch & 15) << 2;
            CP_ASYNC16(base + (AF_KS + r * SPAD + d0) * 4,
                       kb + (size_t)(bs + k0 + r) * DM + h * HD + d0);
        }
    };
    auto loadV = [&](int t) {
        int k0 = t << 7;
        #pragma unroll
        for (int i = 0; i < 8; i++) {
            int ch = tid + i * 256;
            int r = ch >> 4, d0 = (ch & 15) << 2;
            CP_ASYNC16(base + (AF_VS + r * SPAD + d0) * 4,
                       vb + (size_t)(bs + k0 + r) * DM + h * HD + d0);
        }
    };

    int warp = tid >> 5, lane = tid & 31;
    int gid = lane >> 2, tig = lane & 3;
    int wm = (warp & 1) * 64;
    int wn = (warp >> 1) * 32;
    int wg = warp >> 1;
    int wmP = (warp & 3) * 32;
    int wnP = (warp >> 2) * 32;

    const uint32_t* Qu = (const uint32_t*)Qs;
    const uint32_t* Ku = (const uint32_t*)Ks;
    const uint32_t* Vu = (const uint32_t*)Vs;

    float O[2][4][4] = {};

    loadK(0); CP_COMMIT();
    __syncthreads();

    for (int t = 0; t < 4; t++) {
        loadV(t); CP_COMMIT();
        CP_WAIT1();
        __syncthreads();

        float acc[4][4][4] = {};
        #pragma unroll
        for (int ks = 0; ks < 64; ks += 8) {
            uint32_t af[4][4], bf[4][2];
            #pragma unroll
            for (int mt = 0; mt < 4; mt++) {
                int m = wm + mt * 16 + gid;
                af[mt][0] = Qu[m * SPAD + ks + tig];
                af[mt][1] = Qu[(m + 8) * SPAD + ks + tig];
                af[mt][2] = Qu[m * SPAD + ks + tig + 4];
                af[mt][3] = Qu[(m + 8) * SPAD + ks + tig + 4];
            }
            #pragma unroll
            for (int nt = 0; nt < 4; nt++) {
                int n = wn + nt * 8 + gid;
                bf[nt][0] = Ku[n * SPAD + ks + tig];
                bf[nt][1] = Ku[n * SPAD + ks + tig + 4];
            }
            #pragma unroll
            for (int mt = 0; mt < 4; mt++)
                #pragma unroll
                for (int nt = 0; nt < 4; nt++)
                    mma_tf32(acc[mt][nt], af[mt], bf[nt]);
        }
        __syncthreads();
        if (t < 3) { loadK(t + 1); CP_COMMIT(); }

        int k0 = t << 7;
        float ma[4], mb[4];
        #pragma unroll
        for (int mt = 0; mt < 4; mt++) {
            int ra = wm + mt * 16 + gid;
            int rb = ra + 8;
            int qga = q0 + ra, qgb = q0 + rb;
            const float* qra = qr + ((size_t)h * MROWS + bs + qga) * NREL;
            const float* qrb = qr + ((size_t)h * MROWS + bs + qgb) * NREL;
            ma[mt] = -1e30f; mb[mt] = -1e30f;
            #pragma unroll
            for (int nt = 0; nt < 4; nt++) {
                int kg = k0 + wn + nt * 8 + tig * 2;
                int d0a = min(max(kg     - qga, -MAXREL), MAXREL) + MAXREL;
                int d1a = min(max(kg + 1 - qga, -MAXREL), MAXREL) + MAXREL;
                int d0b = min(max(kg     - qgb, -MAXREL), MAXREL) + MAXREL;
                int d1b = min(max(kg + 1 - qgb, -MAXREL), MAXREL) + MAXREL;
                acc[mt][nt][0] = acc[mt][nt][0] * 0.125f + qra[d0a];
                acc[mt][nt][1] = acc[mt][nt][1] * 0.125f + qra[d1a];
                acc[mt][nt][2] = acc[mt][nt][2] * 0.125f + qrb[d0b];
                acc[mt][nt][3] = acc[mt][nt][3] * 0.125f + qrb[d1b];
                ma[mt] = fmaxf(ma[mt], fmaxf(acc[mt][nt][0], acc[mt][nt][1]));
                mb[mt] = fmaxf(mb[mt], fmaxf(acc[mt][nt][2], acc[mt][nt][3]));
            }
            #pragma unroll
            for (int o = 1; o < 4; o <<= 1) {
                ma[mt] = fmaxf(ma[mt], __shfl_xor_sync(0xffffffffu, ma[mt], o));
                mb[mt] = fmaxf(mb[mt], __shfl_xor_sync(0xffffffffu, mb[mt], o));
            }
            if (tig == 0) {
                red[ra * 4 + wg] = ma[mt];
                red[rb * 4 + wg] = mb[mt];
            }
        }
        __syncthreads();

        float MnA[4], MnB[4];
        #pragma unroll
        for (int mt = 0; mt < 4; mt++) {
            int ra = wm + mt * 16 + gid;
            int rb = ra + 8;
            float tma = fmaxf(fmaxf(red[ra*4+0], red[ra*4+1]), fmaxf(red[ra*4+2], red[ra*4+3]));
            float tmb = fmaxf(fmaxf(red[rb*4+0], red[rb*4+1]), fmaxf(red[rb*4+2], red[rb*4+3]));
            MnA[mt] = fmaxf(Msh[ra], tma);
            MnB[mt] = fmaxf(Msh[rb], tmb);
            float sa = 0.f, sb = 0.f;
            #pragma unroll
            for (int nt = 0; nt < 4; nt++) {
                float p0 = __expf(acc[mt][nt][0] - MnA[mt]);
                float p1 = __expf(acc[mt][nt][1] - MnA[mt]);
                float p2 = __expf(acc[mt][nt][2] - MnB[mt]);
                float p3 = __expf(acc[mt][nt][3] - MnB[mt]);
                sa += p0 + p1;
                sb += p2 + p3;
                int c = wn + nt * 8 + tig * 2;
                *(float2*)&Ps[ra * FPAD + c] = make_float2(p0, p1);
                *(float2*)&Ps[rb * FPAD + c] = make_float2(p2, p3);
            }
            #pragma unroll
            for (int o = 1; o < 4; o <<= 1) {
                sa += __shfl_xor_sync(0xffffffffu, sa, o);
                sb += __shfl_xor_sync(0xffffffffu, sb, o);
            }
            if (tig == 0) {
                red[ra * 4 + wg] = sa;
                red[rb * 4 + wg] = sb;
            }
        }
        __syncthreads();

        if (wg == 0 && tig == 0) {
            #pragma unroll
            for (int mt = 0; mt < 4; mt++) {
                int ra = wm + mt * 16 + gid;
                int rb = ra + 8;
                float tsa = red[ra*4+0] + red[ra*4+1] + red[ra*4+2] + red[ra*4+3];
                float tsb = red[rb*4+0] + red[rb*4+1] + red[rb*4+2] + red[rb*4+3];
                float fa = __expf(Msh[ra] - MnA[mt]);
                float fb = __expf(Msh[rb] - MnB[mt]);
                Ssh[ra] = Ssh[ra] * fa + tsa;
                Ssh[rb] = Ssh[rb] * fb + tsb;
                Msh[ra] = MnA[mt];
                Msh[rb] = MnB[mt];
                Fsh[ra] = fa;
                Fsh[rb] = fb;
            }
        }
        if (t < 3) CP_WAIT1(); else CP_WAIT0();
        __syncthreads();

        #pragma unroll
        for (int mt = 0; mt < 2; mt++) {
            int ra = wmP + mt * 16 + gid;
            int rb = ra + 8;
            float fa = Fsh[ra], fb = Fsh[rb];
            #pragma unroll
            for (int nt = 0; nt < 4; nt++) {
                O[mt][nt][0] *= fa; O[mt][nt][1] *= fa;
                O[mt][nt][2] *= fb; O[mt][nt][3] *= fb;
            }
        }
        #pragma unroll
        for (int ks = 0; ks < 128; ks += 8) {
            uint32_t af[2][4], bf[4][2];
            #pragma unroll
            for (int mt = 0; mt < 2; mt++) {
                int m = wmP + mt * 16 + gid;
                af[mt][0] = tf32u(Ps[m * FPAD + ks + tig]);
                af[mt][1] = tf32u(Ps[(m + 8) * FPAD + ks + tig]);
                af[mt][2] = tf32u(Ps[m * FPAD + ks + tig + 4]);
                af[mt][3] = tf32u(Ps[(m + 8) * FPAD + ks + tig + 4]);
            }
            #pragma unroll
            for (int nt = 0; nt < 4; nt++) {
                int n = wnP + nt * 8 + gid;
                bf[nt][0] = Vu[(ks + tig) * SPAD + n];
                bf[nt][1] = Vu[(ks + tig + 4) * SPAD + n];
            }
            #pragma unroll
            for (int mt = 0; mt < 2; mt++)
                #pragma unroll
                for (int nt = 0; nt < 4; nt++)
                    mma_tf32(O[mt][nt], af[mt], bf[nt]);
        }
        __syncthreads();
    }

    // epilogue: normalize, round (ctx only feeds tf32 GEMM A), write
    #pragma unroll
    for (int mt = 0; mt < 2; mt++) {
        int ra = wmP + mt * 16 + gid;
        int rb = ra + 8;
        float ia = 1.0f / Ssh[ra];
        float ib = 1.0f / Ssh[rb];
        #pragma unroll
        for (int nt = 0; nt < 4; nt++) {
            int col = h * HD + wnP + nt * 8 + tig * 2;
            *(float2*)(ctx + (size_t)(bs + q0 + ra) * DM + col) =
                make_float2(tf32f(O[mt][nt][0] * ia), tf32f(O[mt][nt][1] * ia));
            *(float2*)(ctx + (size_t)(bs + q0 + rb) * DM + col) =
                make_float2(tf32f(O[mt][nt][2] * ib), tf32f(O[mt][nt][3] * ib));
        }
    }
}

// ===========================================================================
// LayerNorm (plain; input already has residual)
// ===========================================================================
__device__ __forceinline__ float block_sum128(float v, float* ws)
{
    #pragma unroll
    for (int o = 16; o > 0; o >>= 1) v += __shfl_xor_sync(0xffffffffu, v, o);
    int lane = threadIdx.x & 31, w = threadIdx.x >> 5;
    if (lane == 0) ws[w] = v;
    __syncthreads();
    v = ws[0] + ws[1] + ws[2] + ws[3];
    __syncthreads();
    return v;
}

__global__ __launch_bounds__(128)
void ln_kernel(const float* __restrict__ x,
               const float* __restrict__ g, const float* __restrict__ bta,
               float* __restrict__ out)
{
    __shared__ float ws[4];
    int row = blockIdx.x;
    int tid = threadIdx.x;
    float4 v = ((const float4*)(x + (size_t)row * DM))[tid];
    float s = block_sum128(v.x + v.y + v.z + v.w, ws);
    float mean = s * (1.0f / DM);
    float dx = v.x - mean, dy = v.y - mean, dz = v.z - mean, dw = v.w - mean;
    float sq = block_sum128(dx*dx + dy*dy + dz*dz + dw*dw, ws);
    float rstd = rsqrtf(sq * (1.0f / DM) + 1e-5f);
    float4 gg = ((const float4*)g)[tid];
    float4 bb = ((const float4*)bta)[tid];
    float4 o;
    o.x = dx * rstd * gg.x + bb.x;
    o.y = dy * rstd * gg.y + bb.y;
    o.z = dz * rstd * gg.z + bb.z;
    o.w = dw * rstd * gg.w + bb.w;
    ((float4*)(out + (size_t)row * DM))[tid] = o;
}

// ===========================================================================
// head stage 2
// ===========================================================================
__global__ __launch_bounds__(256)
void head2_kernel(const float* __restrict__ tmp, const float* __restrict__ p2_w,
                  const float* __restrict__ p2_b, float* __restrict__ out)
{
    int wid = threadIdx.x >> 5;
    int lane = threadIdx.x & 31;
    int row = blockIdx.x * 8 + wid;
    const float* tr = tmp + (size_t)row * 256;
    float acc = 0.f;
    #pragma unroll
    for (int j = lane; j < 256; j += 32) acc = fmaf(tr[j], p2_w[j], acc);
    #pragma unroll
    for (int o = 16; o > 0; o >>= 1) acc += __shfl_xor_sync(0xffffffffu, acc, o);
    if (lane == 0) out[row] = acc + p2_b[0];
}

// ===========================================================================
// Launcher
// ===========================================================================
extern "C" void kernel_launch(void* const* d_in, const int* in_sizes, int n_in,
                              void* d_out, int out_size)
{
    const float* x     = (const float*)d_in[0];
    const float* in_w  = (const float*)d_in[1];
    const float* in_b  = (const float*)d_in[2];
    const float* Wq    = (const float*)d_in[3];
    const float* Wk    = (const float*)d_in[4];
    const float* Wv    = (const float*)d_in[5];
    const float* Wo    = (const float*)d_in[6];
    const float* bo    = (const float*)d_in[7];
    const float* relE  = (const float*)d_in[8];
    const float* w1    = (const float*)d_in[9];
    const float* b1    = (const float*)d_in[10];
    const float* w2    = (const float*)d_in[11];
    const float* b2    = (const float*)d_in[12];
    const float* ln1_g = (const float*)d_in[13];
    const float* ln1_b = (const float*)d_in[14];
    const float* ln2_g = (const float*)d_in[15];
    const float* ln2_b = (const float*)d_in[16];
    const float* on_g  = (const float*)d_in[17];
    const float* on_b  = (const float*)d_in[18];
    const float* p1_w  = (const float*)d_in[19];
    const float* p1_b  = (const float*)d_in[20];
    const float* p2_w  = (const float*)d_in[21];
    const float* p2_b  = (const float*)d_in[22];
    float* out = (float*)d_out;

    float *h, *q, *k, *v, *ctx, *tmp, *qr, *wr;
    cudaGetSymbolAddress((void**)&h,   g_h);
    cudaGetSymbolAddress((void**)&q,   g_q);
    cudaGetSymbolAddress((void**)&k,   g_k);
    cudaGetSymbolAddress((void**)&v,   g_v);
    cudaGetSymbolAddress((void**)&ctx, g_ctx);
    cudaGetSymbolAddress((void**)&tmp, g_tmp);
    cudaGetSymbolAddress((void**)&qr,  g_qr);
    cudaGetSymbolAddress((void**)&wr,  g_wr);

    static bool attr_set = false;
    if (!attr_set) {
        cudaFuncSetAttribute(qrel_mma,   cudaFuncAttributeMaxDynamicSharedMemorySize, QRELM_SMEM);
        cudaFuncSetAttribute(attn_fused, cudaFuncAttributeMaxDynamicSharedMemorySize, AF_SMEM);
        cudaFuncSetAttribute(tgemm<false, false, false, true, true>, cudaFuncAttributeMaxDynamicSharedMemorySize, TG_SMEM);
        cudaFuncSetAttribute(tgemm<true, false, true, false, false>, cudaFuncAttributeMaxDynamicSharedMemorySize, TG_SMEM);
        cudaFuncSetAttribute(tgemm<true, true, false, true, true>,   cudaFuncAttributeMaxDynamicSharedMemorySize, TG_SMEM);
        cudaFuncSetAttribute(tgemm<true, true, false, true, false>,  cudaFuncAttributeMaxDynamicSharedMemorySize, TG_SMEM);
        cudaFuncSetAttribute(tgemm_qkv,  cudaFuncAttributeMaxDynamicSharedMemorySize, TG_SMEM);
        attr_set = true;
    }

    // Pre-round weights (tf32 RNA) into g_wr
    auto rc = [&](const float* s, float* d, int n) {
        int n4 = n >> 2;
        round_copy<<<(n4 + 255) / 256, 256>>>(s, d, n4);
    };
    rc(Wq,   wr + OFF_WQ,  NLAYER * DM * DM);
    rc(Wk,   wr + OFF_WK,  NLAYER * DM * DM);
    rc(Wv,   wr + OFF_WV,  NLAYER * DM * DM);
    rc(Wo,   wr + OFF_WO,  NLAYER * DM * DM);
    rc(w1,   wr + OFF_W1,  NLAYER * DM * FFD);
    rc(w2,   wr + OFF_W2,  NLAYER * FFD * DM);
    rc(p1_w, wr + OFF_P1,  DM * 256);
    rc(relE, wr + OFF_REL, NLAYER * NREL * HD);

    embed_kernel<<<(MROWS * DM) / 256, 256>>>(x, in_w, in_b, h);

    dim3 gD(DM / 128, MROWS / 128);
    dim3 gQKV(DM / 128, MROWS / 128, 3);
    dim3 gF(FFD / 128, MROWS / 128);
    dim3 gP(256 / 128, MROWS / 128);
    dim3 gQR(MROWS / 128, 2, NH);
    dim3 gAF(SEQ / 128, BATCH * NH);

    for (int l = 0; l < NLAYER; l++) {
        const float* wq  = wr + OFF_WQ + (size_t)l * DM * DM;
        const float* wk  = wr + OFF_WK + (size_t)l * DM * DM;
        const float* wv  = wr + OFF_WV + (size_t)l * DM * DM;
        const float* wo  = wr + OFF_WO + (size_t)l * DM * DM;
        const float* bol = bo + (size_t)l * DM;
        const float* rl  = wr + OFF_REL + (size_t)l * NREL * HD;
        const float* w1l = wr + OFF_W1 + (size_t)l * DM * FFD;
        const float* b1l = b1 + (size_t)l * FFD;
        const float* w2l = wr + OFF_W2 + (size_t)l * FFD * DM;
        const float* b2l = b2 + (size_t)l * DM;

        // q,k,v rounded at epilogue (OUTROUND)
        tgemm_qkv<<<gQKV, 128, TG_SMEM>>>(h, wq, wk, wv, q, k, v);

        qrel_mma<<<gQR, 256, QRELM_SMEM>>>(q, rl, qr);
        attn_fused<<<gAF, 256, AF_SMEM>>>(q, k, v, qr, ctx);

        // q = ctx@Wo + bo + h (ctx pre-rounded: ACVT=false), then h = LN(q)
        tgemm<true, false, true, false, false><<<gD, 128, TG_SMEM>>>(ctx, wo, bol, h, q, DM, DM);
        ln_kernel<<<MROWS, 128>>>(q, ln1_g + (size_t)l * DM, ln1_b + (size_t)l * DM, h);

        // tmp = relu(h@w1+b1) rounded at epilogue
        tgemm<true, true, false, true, true><<<gF, 128, TG_SMEM>>>(h, w1l, b1l, nullptr, tmp, FFD, DM);
        // q = tmp@W2 + b2 + h (tmp pre-rounded: ACVT=false), then h = LN(q)
        tgemm<true, false, true, false, false><<<gD, 128, TG_SMEM>>>(tmp, w2l, b2l, h, q, DM, FFD);
        ln_kernel<<<MROWS, 128>>>(q, ln2_g + (size_t)l * DM, ln2_b + (size_t)l * DM, h);
    }

    ln_kernel<<<MROWS, 128>>>(h, on_g, on_b, q);
    tgemm<true, true, false, true, false><<<gP, 128, TG_SMEM>>>(q, wr + OFF_P1, p1_b, nullptr, tmp, 256, DM);
    head2_kernel<<<MROWS / 8, 256>>>(tmp, p2_w, p2_b, out);
}